// round 1
// baseline (speedup 1.0000x reference)
#include <cuda_runtime.h>
#include <math.h>

#define DD 512
#define HH 20
#define VV 32000
#define TT 1024

// Scratch (allocation-free rule: __device__ globals)
__device__ float g_X [TT*DD];
__device__ float g_Z0[TT*DD];
__device__ float g_Z1[TT*DD];
__device__ float g_Y [TT*DD];
__device__ float g_MX[TT*DD];
__device__ float g_rowloss[TT];

// ---------------------------------------------------------------------------
// 1) X = embed[tokens]
// ---------------------------------------------------------------------------
__global__ void k_gather(const int* __restrict__ tokens,
                         const float* __restrict__ embed) {
    int idx = blockIdx.x * blockDim.x + threadIdx.x;
    if (idx < TT * DD) {
        int t = idx >> 9, d = idx & 511;
        g_X[idx] = embed[(size_t)tokens[t] * DD + d];
    }
}

// ---------------------------------------------------------------------------
// 2) Z0 = X @ wa, Z1 = X @ wb  (fused: share the X tile)
//    64x64 tiles, 256 threads, 4x4 micro-tile per thread per output matrix
// ---------------------------------------------------------------------------
__global__ void __launch_bounds__(256) k_zgemm(const float* __restrict__ wa,
                                               const float* __restrict__ wb) {
    __shared__ float Xs [16][64];
    __shared__ float Was[16][64];
    __shared__ float Wbs[16][64];
    int tid = threadIdx.x;
    int n0 = blockIdx.x * 64;   // output column tile
    int m0 = blockIdx.y * 64;   // token tile
    int ty = tid >> 4, tx = tid & 15;
    float a0[4][4] = {}, a1[4][4] = {};

    for (int k0 = 0; k0 < DD; k0 += 16) {
        {   // X tile, transposed into Xs[k][m]
            int m  = tid >> 2;
            int kq = (tid & 3) * 4;
            float4 v = *(const float4*)&g_X[(size_t)(m0 + m) * DD + k0 + kq];
            Xs[kq+0][m] = v.x; Xs[kq+1][m] = v.y; Xs[kq+2][m] = v.z; Xs[kq+3][m] = v.w;
        }
        {   // W tiles
            int k  = tid >> 4;
            int nq = (tid & 15) * 4;
            *(float4*)&Was[k][nq] = *(const float4*)&wa[(size_t)(k0 + k) * DD + n0 + nq];
            *(float4*)&Wbs[k][nq] = *(const float4*)&wb[(size_t)(k0 + k) * DD + n0 + nq];
        }
        __syncthreads();
        #pragma unroll
        for (int k = 0; k < 16; k++) {
            float xr[4], war[4], wbr[4];
            #pragma unroll
            for (int i = 0; i < 4; i++) xr[i] = Xs[k][ty*4 + i];
            #pragma unroll
            for (int j = 0; j < 4; j++) { war[j] = Was[k][tx*4 + j]; wbr[j] = Wbs[k][tx*4 + j]; }
            #pragma unroll
            for (int i = 0; i < 4; i++)
                #pragma unroll
                for (int j = 0; j < 4; j++) {
                    a0[i][j] = fmaf(xr[i], war[j], a0[i][j]);
                    a1[i][j] = fmaf(xr[i], wbr[j], a1[i][j]);
                }
        }
        __syncthreads();
    }
    #pragma unroll
    for (int i = 0; i < 4; i++) {
        int row = m0 + ty*4 + i;
        #pragma unroll
        for (int j = 0; j < 4; j++) {
            int col = n0 + tx*4 + j;
            g_Z0[(size_t)row * DD + col] = a0[i][j];
            g_Z1[(size_t)row * DD + col] = a1[i][j];
        }
    }
}

// ---------------------------------------------------------------------------
// 3) Sequential scan. One warp owns column j; lane l owns rows i = l + 32k.
//    fw[i][j] lives in registers across all 1024 steps; no inter-CTA sync.
//    tanh(v) = 1 - 2/(exp(2v)+1)   (2 MUFU: EX2 + RCP, abs err ~1e-7)
// ---------------------------------------------------------------------------
__global__ void k_scan(const float* __restrict__ fw_init,
                       const float* __restrict__ eta_p) {
    int j = blockIdx.x;          // 0..511
    int lane = threadIdx.x;      // 0..31
    float eta = *eta_p;
    float fw[16];
    #pragma unroll
    for (int k = 0; k < 16; k++)
        fw[k] = fw_init[(size_t)(lane + 32*k) * DD + j];

    for (int t = 0; t < TT; t++) {
        float z1v = __ldg(&g_Z1[(size_t)t * DD + j]);
        float p = eta * z1v;
        float yacc = 0.f;
        #pragma unroll
        for (int k = 0; k < 16; k++) {
            int i = lane + 32*k;
            float z0v = g_Z0[(size_t)t * DD + i];
            float xv  = g_X [(size_t)t * DD + i];
            float v  = fmaf(z0v, p, fw[k]);
            float e  = __expf(v + v);
            float th = 1.f - __fdividef(2.f, e + 1.f);   // handles ±inf correctly
            fw[k] = th;
            yacc = fmaf(xv, th, yacc);
        }
        #pragma unroll
        for (int off = 16; off; off >>= 1)
            yacc += __shfl_xor_sync(0xffffffffu, yacc, off);
        if (lane == 0) g_Y[(size_t)t * DD + j] = yacc;
    }
}

// ---------------------------------------------------------------------------
// 4) MLP + mix: mixed = 0.5*(selu(Y@aw+ab)@bw+bb) + 0.5*X
// ---------------------------------------------------------------------------
__global__ void k_mlp(const float* __restrict__ aw, const float* __restrict__ ab,
                      const float* __restrict__ bw, const float* __restrict__ bb) {
    __shared__ float ys[DD];
    __shared__ float hs[HH];
    int t = blockIdx.x, tid = threadIdx.x;
    for (int d = tid; d < DD; d += 256) ys[d] = g_Y[(size_t)t * DD + d];
    __syncthreads();
    int w = tid >> 5, lane = tid & 31;
    for (int u = w; u < HH; u += 8) {
        float acc = 0.f;
        #pragma unroll
        for (int k = 0; k < 16; k++) {
            int d = lane + 32*k;
            acc = fmaf(ys[d], aw[(size_t)d * HH + u], acc);
        }
        #pragma unroll
        for (int off = 16; off; off >>= 1)
            acc += __shfl_xor_sync(0xffffffffu, acc, off);
        if (lane == 0) {
            float hv = acc + ab[u];
            const float SC = 1.0507009873554805f, AL = 1.6732632423543772f;
            hs[u] = hv > 0.f ? SC * hv : SC * AL * expm1f(hv);
        }
    }
    __syncthreads();
    for (int j = tid; j < DD; j += 256) {
        float o = bb[j];
        #pragma unroll
        for (int k = 0; k < HH; k++)
            o = fmaf(hs[k], bw[(size_t)k * DD + j], o);
        g_MX[(size_t)t * DD + j] = 0.5f * o + 0.5f * g_X[(size_t)t * DD + j];
    }
}

// ---------------------------------------------------------------------------
// 5) Head GEMM: logits[1024,32000] = MX[1024,512] @ head_w[512,32000] + b
//    128x128 tiles, 256 threads, 8x8 micro-tile. Dims divide exactly.
// ---------------------------------------------------------------------------
__global__ void __launch_bounds__(256) k_head(const float* __restrict__ B,
                                              const float* __restrict__ bias,
                                              float* __restrict__ out) {
    __shared__ float As[16][128];
    __shared__ float Bs[16][128];
    int tid = threadIdx.x;
    int n0 = blockIdx.x * 128;
    int m0 = blockIdx.y * 128;
    int ty = tid >> 4, tx = tid & 15;
    float acc[8][8] = {};

    for (int k0 = 0; k0 < DD; k0 += 16) {
        #pragma unroll
        for (int q = 0; q < 2; q++) {        // A tile (transposed store)
            int f = tid + 256 * q;
            int m = f >> 2; int kq = (f & 3) * 4;
            float4 v = *(const float4*)&g_MX[(size_t)(m0 + m) * DD + k0 + kq];
            As[kq+0][m] = v.x; As[kq+1][m] = v.y; As[kq+2][m] = v.z; As[kq+3][m] = v.w;
        }
        #pragma unroll
        for (int q = 0; q < 2; q++) {        // B tile (direct)
            int f = tid + 256 * q;
            int kk = f >> 5; int nq = (f & 31) * 4;
            *(float4*)&Bs[kk][nq] = *(const float4*)&B[(size_t)(k0 + kk) * VV + n0 + nq];
        }
        __syncthreads();
        #pragma unroll
        for (int k = 0; k < 16; k++) {
            float4 a0 = *(float4*)&As[k][ty*8];
            float4 a1 = *(float4*)&As[k][ty*8 + 4];
            float4 b0 = *(float4*)&Bs[k][tx*8];
            float4 b1 = *(float4*)&Bs[k][tx*8 + 4];
            float ar[8] = {a0.x,a0.y,a0.z,a0.w,a1.x,a1.y,a1.z,a1.w};
            float br[8] = {b0.x,b0.y,b0.z,b0.w,b1.x,b1.y,b1.z,b1.w};
            #pragma unroll
            for (int i = 0; i < 8; i++)
                #pragma unroll
                for (int j = 0; j < 8; j++)
                    acc[i][j] = fmaf(ar[i], br[j], acc[i][j]);
        }
        __syncthreads();
    }
    #pragma unroll
    for (int i = 0; i < 8; i++) {
        int row = m0 + ty*8 + i;
        #pragma unroll
        for (int jv = 0; jv < 2; jv++) {
            int col = n0 + tx*8 + jv*4;
            float4 bv = *(const float4*)&bias[col];
            float4 o;
            o.x = acc[i][jv*4+0] + bv.x;
            o.y = acc[i][jv*4+1] + bv.y;
            o.z = acc[i][jv*4+2] + bv.z;
            o.w = acc[i][jv*4+3] + bv.w;
            *(float4*)&out[(size_t)row * VV + col] = o;
        }
    }
}

// ---------------------------------------------------------------------------
// 6) log-softmax row stats -> per-row loss term; 7) final mean
// ---------------------------------------------------------------------------
__global__ void k_softmax(const float* __restrict__ logits,
                          const int* __restrict__ targets) {
    __shared__ float red[256];
    int t = blockIdx.x, tid = threadIdx.x;
    const float* row = logits + (size_t)t * VV;
    float m = -INFINITY;
    for (int c = tid; c < VV; c += 256) m = fmaxf(m, row[c]);
    red[tid] = m; __syncthreads();
    for (int s = 128; s; s >>= 1) { if (tid < s) red[tid] = fmaxf(red[tid], red[tid+s]); __syncthreads(); }
    m = red[0]; __syncthreads();
    float s = 0.f;
    for (int c = tid; c < VV; c += 256) s += __expf(row[c] - m);
    red[tid] = s; __syncthreads();
    for (int st = 128; st; st >>= 1) { if (tid < st) red[tid] += red[tid+st]; __syncthreads(); }
    if (tid == 0)
        g_rowloss[t] = row[targets[t]] - m - logf(red[0]);
}

__global__ void k_loss(float* __restrict__ out) {
    __shared__ float red[256];
    int tid = threadIdx.x;
    float s = 0.f;
    for (int t = tid; t < TT; t += 256) s += g_rowloss[t];
    red[tid] = s; __syncthreads();
    for (int st = 128; st; st >>= 1) { if (tid < st) red[tid] += red[tid+st]; __syncthreads(); }
    if (tid == 0) out[0] = -red[0] / (float)TT;
}

// ---------------------------------------------------------------------------
extern "C" void kernel_launch(void* const* d_in, const int* in_sizes, int n_in,
                              void* d_out, int out_size) {
    const int*   tokens  = (const int*)  d_in[0];
    const int*   targets = (const int*)  d_in[1];
    const float* embed   = (const float*)d_in[2];
    const float* fw_init = (const float*)d_in[3];
    const float* eta     = (const float*)d_in[4];
    const float* wa      = (const float*)d_in[5];
    const float* wb      = (const float*)d_in[6];
    const float* mlp_aw  = (const float*)d_in[7];
    const float* mlp_ab  = (const float*)d_in[8];
    const float* mlp_bw  = (const float*)d_in[9];
    const float* mlp_bb  = (const float*)d_in[10];
    const float* head_w  = (const float*)d_in[11];
    const float* head_b  = (const float*)d_in[12];
    float* out = (float*)d_out;

    k_gather<<<(TT*DD + 255) / 256, 256>>>(tokens, embed);
    k_zgemm<<<dim3(DD/64, TT/64), 256>>>(wa, wb);
    k_scan<<<DD, 32>>>(fw_init, eta);
    k_mlp<<<TT, 256>>>(mlp_aw, mlp_ab, mlp_bw, mlp_bb);
    k_head<<<dim3(VV/128, TT/128), 256>>>(head_w, head_b, out);
    k_softmax<<<TT, 256>>>(out, targets);
    if (out_size >= TT*VV + 1)
        k_loss<<<1, 256>>>(out + (size_t)TT*VV);
}

// round 2
// speedup vs baseline: 1.0804x; 1.0804x over previous
#include <cuda_runtime.h>
#include <cuda_bf16.h>
#include <math.h>

#define DD 512
#define HH 20
#define VV 32000
#define TT 1024

// Scratch (allocation-free rule: __device__ globals)
__device__ float g_X [TT*DD];
__device__ float g_Z0[TT*DD];
__device__ float g_Z1[TT*DD];
__device__ float g_Y [TT*DD];
__device__ float g_rowloss[TT];
// bf16 hi/lo operands for tensor-core head GEMM
__device__ __nv_bfloat16 g_Ahi[TT*DD];          // mixed activations [m][k]
__device__ __nv_bfloat16 g_Alo[TT*DD];
__device__ __nv_bfloat16 g_Bhi[(size_t)VV*DD];  // head_w transposed [n][k]
__device__ __nv_bfloat16 g_Blo[(size_t)VV*DD];

// ---------------------------------------------------------------------------
// 1) X = embed[tokens]
// ---------------------------------------------------------------------------
__global__ void k_gather(const int* __restrict__ tokens,
                         const float* __restrict__ embed) {
    int idx = blockIdx.x * blockDim.x + threadIdx.x;
    if (idx < TT * DD) {
        int t = idx >> 9, d = idx & 511;
        g_X[idx] = embed[(size_t)tokens[t] * DD + d];
    }
}

// ---------------------------------------------------------------------------
// 1b) head_w [512][32000] -> g_Bhi/g_Blo [32000][512] (transpose + hi/lo split)
// ---------------------------------------------------------------------------
__global__ void __launch_bounds__(256) k_convB(const float* __restrict__ W) {
    __shared__ float tile[32][33];
    int n0 = blockIdx.x * 32, k0 = blockIdx.y * 32;
    int tx = threadIdx.x & 31, ty = threadIdx.x >> 5;   // 32 x 8
    #pragma unroll
    for (int r = 0; r < 4; r++)
        tile[ty + 8*r][tx] = W[(size_t)(k0 + ty + 8*r) * VV + n0 + tx];
    __syncthreads();
    #pragma unroll
    for (int r = 0; r < 4; r++) {
        int row = ty + 8*r;                 // local n
        float v = tile[tx][row];            // conflict-free (stride 33)
        __nv_bfloat16 hi = __float2bfloat16_rn(v);
        __nv_bfloat16 lo = __float2bfloat16_rn(v - __bfloat162float(hi));
        size_t o = (size_t)(n0 + row) * DD + k0 + tx;
        g_Bhi[o] = hi;
        g_Blo[o] = lo;
    }
}

// ---------------------------------------------------------------------------
// 2) Z0 = X @ wa, Z1 = X @ wb  (fused: share the X tile)
// ---------------------------------------------------------------------------
__global__ void __launch_bounds__(256) k_zgemm(const float* __restrict__ wa,
                                               const float* __restrict__ wb) {
    __shared__ float Xs [16][64];
    __shared__ float Was[16][64];
    __shared__ float Wbs[16][64];
    int tid = threadIdx.x;
    int n0 = blockIdx.x * 64;
    int m0 = blockIdx.y * 64;
    int ty = tid >> 4, tx = tid & 15;
    float a0[4][4] = {}, a1[4][4] = {};

    for (int k0 = 0; k0 < DD; k0 += 16) {
        {
            int m  = tid >> 2;
            int kq = (tid & 3) * 4;
            float4 v = *(const float4*)&g_X[(size_t)(m0 + m) * DD + k0 + kq];
            Xs[kq+0][m] = v.x; Xs[kq+1][m] = v.y; Xs[kq+2][m] = v.z; Xs[kq+3][m] = v.w;
        }
        {
            int k  = tid >> 4;
            int nq = (tid & 15) * 4;
            *(float4*)&Was[k][nq] = *(const float4*)&wa[(size_t)(k0 + k) * DD + n0 + nq];
            *(float4*)&Wbs[k][nq] = *(const float4*)&wb[(size_t)(k0 + k) * DD + n0 + nq];
        }
        __syncthreads();
        #pragma unroll
        for (int k = 0; k < 16; k++) {
            float xr[4], war[4], wbr[4];
            #pragma unroll
            for (int i = 0; i < 4; i++) xr[i] = Xs[k][ty*4 + i];
            #pragma unroll
            for (int j = 0; j < 4; j++) { war[j] = Was[k][tx*4 + j]; wbr[j] = Wbs[k][tx*4 + j]; }
            #pragma unroll
            for (int i = 0; i < 4; i++)
                #pragma unroll
                for (int j = 0; j < 4; j++) {
                    a0[i][j] = fmaf(xr[i], war[j], a0[i][j]);
                    a1[i][j] = fmaf(xr[i], wbr[j], a1[i][j]);
                }
        }
        __syncthreads();
    }
    #pragma unroll
    for (int i = 0; i < 4; i++) {
        int row = m0 + ty*4 + i;
        #pragma unroll
        for (int j = 0; j < 4; j++) {
            int col = n0 + tx*4 + j;
            g_Z0[(size_t)row * DD + col] = a0[i][j];
            g_Z1[(size_t)row * DD + col] = a1[i][j];
        }
    }
}

// ---------------------------------------------------------------------------
// 3) Sequential scan. One warp owns column j; lane l owns rows i = l + 32k.
// ---------------------------------------------------------------------------
__global__ void k_scan(const float* __restrict__ fw_init,
                       const float* __restrict__ eta_p) {
    int j = blockIdx.x;
    int lane = threadIdx.x;
    float eta = *eta_p;
    float fw[16];
    #pragma unroll
    for (int k = 0; k < 16; k++)
        fw[k] = fw_init[(size_t)(lane + 32*k) * DD + j];

    for (int t = 0; t < TT; t++) {
        float z1v = __ldg(&g_Z1[(size_t)t * DD + j]);
        float p = eta * z1v;
        float yacc = 0.f;
        #pragma unroll
        for (int k = 0; k < 16; k++) {
            int i = lane + 32*k;
            float z0v = g_Z0[(size_t)t * DD + i];
            float xv  = g_X [(size_t)t * DD + i];
            float v  = fmaf(z0v, p, fw[k]);
            float e  = __expf(v + v);
            float th = 1.f - __fdividef(2.f, e + 1.f);
            fw[k] = th;
            yacc = fmaf(xv, th, yacc);
        }
        #pragma unroll
        for (int off = 16; off; off >>= 1)
            yacc += __shfl_xor_sync(0xffffffffu, yacc, off);
        if (lane == 0) g_Y[(size_t)t * DD + j] = yacc;
    }
}

// ---------------------------------------------------------------------------
// 4) MLP + mix; epilogue also emits bf16 hi/lo of "mixed" for the head GEMM
// ---------------------------------------------------------------------------
__global__ void k_mlp(const float* __restrict__ aw, const float* __restrict__ ab,
                      const float* __restrict__ bw, const float* __restrict__ bb) {
    __shared__ float ys[DD];
    __shared__ float hs[HH];
    int t = blockIdx.x, tid = threadIdx.x;
    for (int d = tid; d < DD; d += 256) ys[d] = g_Y[(size_t)t * DD + d];
    __syncthreads();
    int w = tid >> 5, lane = tid & 31;
    for (int u = w; u < HH; u += 8) {
        float acc = 0.f;
        #pragma unroll
        for (int k = 0; k < 16; k++) {
            int d = lane + 32*k;
            acc = fmaf(ys[d], aw[(size_t)d * HH + u], acc);
        }
        #pragma unroll
        for (int off = 16; off; off >>= 1)
            acc += __shfl_xor_sync(0xffffffffu, acc, off);
        if (lane == 0) {
            float hv = acc + ab[u];
            const float SC = 1.0507009873554805f, AL = 1.6732632423543772f;
            hs[u] = hv > 0.f ? SC * hv : SC * AL * expm1f(hv);
        }
    }
    __syncthreads();
    for (int j = tid; j < DD; j += 256) {
        float o = bb[j];
        #pragma unroll
        for (int k = 0; k < HH; k++)
            o = fmaf(hs[k], bw[(size_t)k * DD + j], o);
        float mx = 0.5f * o + 0.5f * g_X[(size_t)t * DD + j];
        __nv_bfloat16 hi = __float2bfloat16_rn(mx);
        __nv_bfloat16 lo = __float2bfloat16_rn(mx - __bfloat162float(hi));
        size_t idx = (size_t)t * DD + j;
        g_Ahi[idx] = hi;
        g_Alo[idx] = lo;
    }
}

// ---------------------------------------------------------------------------
// 5) Head GEMM on tensor cores: logits = A @ B^T + bias
//    A = mixed [1024][512] (hi/lo bf16), B = head_w^T [32000][512] (hi/lo bf16)
//    split-bf16: acc = Ahi*Bhi + Ahi*Blo + Alo*Bhi
//    Block 128x128, 8 warps (2M x 4N), warp 64x32, mma.sync m16n8k16.
// ---------------------------------------------------------------------------
__device__ __forceinline__ void mma16816(float c[4], const unsigned a[4], const unsigned b[2]) {
    asm volatile(
        "mma.sync.aligned.m16n8k16.row.col.f32.bf16.bf16.f32 "
        "{%0,%1,%2,%3}, {%4,%5,%6,%7}, {%8,%9}, {%0,%1,%2,%3};\n"
        : "+f"(c[0]), "+f"(c[1]), "+f"(c[2]), "+f"(c[3])
        : "r"(a[0]), "r"(a[1]), "r"(a[2]), "r"(a[3]), "r"(b[0]), "r"(b[1]));
}

#define SROW 40   // smem row stride in bf16 (80 B) -> conflict-free fragment LDS

__global__ void __launch_bounds__(256) k_head(const float* __restrict__ bias,
                                              float* __restrict__ out) {
    __shared__ __align__(16) __nv_bfloat16 sAh[128][SROW];
    __shared__ __align__(16) __nv_bfloat16 sAl[128][SROW];
    __shared__ __align__(16) __nv_bfloat16 sBh[128][SROW];
    __shared__ __align__(16) __nv_bfloat16 sBl[128][SROW];

    int tid  = threadIdx.x;
    int wid  = tid >> 5;
    int lane = tid & 31;
    int grp  = lane >> 2;        // 0..7
    int t4   = lane & 3;         // 0..3
    int n0 = blockIdx.x * 128;
    int m0 = blockIdx.y * 128;
    int wm = wid & 1;            // 2 M-subtiles of 64
    int wn = wid >> 1;           // 4 N-subtiles of 32

    float acc[4][4][4] = {};     // [mi][ni][frag]

    for (int k0 = 0; k0 < DD; k0 += 32) {
        // load tiles: 128 rows x 32 k bf16 each = 512 uint4 per tile
        #pragma unroll
        for (int q = 0; q < 2; q++) {
            int f   = tid + 256 * q;
            int row = f >> 2;
            int kq  = (f & 3) * 8;
            *(uint4*)&sAh[row][kq] = *(const uint4*)&g_Ahi[(size_t)(m0 + row) * DD + k0 + kq];
            *(uint4*)&sAl[row][kq] = *(const uint4*)&g_Alo[(size_t)(m0 + row) * DD + k0 + kq];
            *(uint4*)&sBh[row][kq] = *(const uint4*)&g_Bhi[(size_t)(n0 + row) * DD + k0 + kq];
            *(uint4*)&sBl[row][kq] = *(const uint4*)&g_Blo[(size_t)(n0 + row) * DD + k0 + kq];
        }
        __syncthreads();

        #pragma unroll
        for (int ks = 0; ks < 2; ks++) {
            int kk = ks * 16;
            unsigned ah[4][4], al[4][4], bh[4][2], bl[4][2];
            #pragma unroll
            for (int mi = 0; mi < 4; mi++) {
                int r = wm * 64 + mi * 16 + grp;
                int c = kk + t4 * 2;
                ah[mi][0] = *(const unsigned*)&sAh[r    ][c    ];
                ah[mi][1] = *(const unsigned*)&sAh[r + 8][c    ];
                ah[mi][2] = *(const unsigned*)&sAh[r    ][c + 8];
                ah[mi][3] = *(const unsigned*)&sAh[r + 8][c + 8];
                al[mi][0] = *(const unsigned*)&sAl[r    ][c    ];
                al[mi][1] = *(const unsigned*)&sAl[r + 8][c    ];
                al[mi][2] = *(const unsigned*)&sAl[r    ][c + 8];
                al[mi][3] = *(const unsigned*)&sAl[r + 8][c + 8];
            }
            #pragma unroll
            for (int ni = 0; ni < 4; ni++) {
                int r = wn * 32 + ni * 8 + grp;
                int c = kk + t4 * 2;
                bh[ni][0] = *(const unsigned*)&sBh[r][c    ];
                bh[ni][1] = *(const unsigned*)&sBh[r][c + 8];
                bl[ni][0] = *(const unsigned*)&sBl[r][c    ];
                bl[ni][1] = *(const unsigned*)&sBl[r][c + 8];
            }
            #pragma unroll
            for (int mi = 0; mi < 4; mi++)
                #pragma unroll
                for (int ni = 0; ni < 4; ni++) {
                    mma16816(acc[mi][ni], ah[mi], bh[ni]);
                    mma16816(acc[mi][ni], ah[mi], bl[ni]);
                    mma16816(acc[mi][ni], al[mi], bh[ni]);
                }
        }
        __syncthreads();
    }

    // epilogue: add bias, write fp32 logits
    #pragma unroll
    for (int mi = 0; mi < 4; mi++) {
        int r0 = m0 + wm * 64 + mi * 16 + grp;
        #pragma unroll
        for (int ni = 0; ni < 4; ni++) {
            int col = n0 + wn * 32 + ni * 8 + t4 * 2;
            float2 bv = *(const float2*)&bias[col];
            float2 v0 = { acc[mi][ni][0] + bv.x, acc[mi][ni][1] + bv.y };
            float2 v1 = { acc[mi][ni][2] + bv.x, acc[mi][ni][3] + bv.y };
            *(float2*)&out[(size_t)r0       * VV + col] = v0;
            *(float2*)&out[(size_t)(r0 + 8) * VV + col] = v1;
        }
    }
}

// ---------------------------------------------------------------------------
// 6) log-softmax row stats -> per-row loss; 7) final mean
// ---------------------------------------------------------------------------
__global__ void k_softmax(const float* __restrict__ logits,
                          const int* __restrict__ targets) {
    __shared__ float red[256];
    int t = blockIdx.x, tid = threadIdx.x;
    const float* row = logits + (size_t)t * VV;
    float m = -INFINITY;
    for (int c = tid; c < VV; c += 256) m = fmaxf(m, row[c]);
    red[tid] = m; __syncthreads();
    for (int s = 128; s; s >>= 1) { if (tid < s) red[tid] = fmaxf(red[tid], red[tid+s]); __syncthreads(); }
    m = red[0]; __syncthreads();
    float s = 0.f;
    for (int c = tid; c < VV; c += 256) s += __expf(row[c] - m);
    red[tid] = s; __syncthreads();
    for (int st = 128; st; st >>= 1) { if (tid < st) red[tid] += red[tid+st]; __syncthreads(); }
    if (tid == 0)
        g_rowloss[t] = row[targets[t]] - m - logf(red[0]);
}

__global__ void k_loss(float* __restrict__ out) {
    __shared__ float red[256];
    int tid = threadIdx.x;
    float s = 0.f;
    for (int t = tid; t < TT; t += 256) s += g_rowloss[t];
    red[tid] = s; __syncthreads();
    for (int st = 128; st; st >>= 1) { if (tid < st) red[tid] += red[tid+st]; __syncthreads(); }
    if (tid == 0) out[0] = -red[0] / (float)TT;
}

// ---------------------------------------------------------------------------
extern "C" void kernel_launch(void* const* d_in, const int* in_sizes, int n_in,
                              void* d_out, int out_size) {
    const int*   tokens  = (const int*)  d_in[0];
    const int*   targets = (const int*)  d_in[1];
    const float* embed   = (const float*)d_in[2];
    const float* fw_init = (const float*)d_in[3];
    const float* eta     = (const float*)d_in[4];
    const float* wa      = (const float*)d_in[5];
    const float* wb      = (const float*)d_in[6];
    const float* mlp_aw  = (const float*)d_in[7];
    const float* mlp_ab  = (const float*)d_in[8];
    const float* mlp_bw  = (const float*)d_in[9];
    const float* mlp_bb  = (const float*)d_in[10];
    const float* head_w  = (const float*)d_in[11];
    const float* head_b  = (const float*)d_in[12];
    float* out = (float*)d_out;

    k_gather<<<(TT*DD + 255) / 256, 256>>>(tokens, embed);
    k_convB<<<dim3(VV/32, DD/32), 256>>>(head_w);
    k_zgemm<<<dim3(DD/64, TT/64), 256>>>(wa, wb);
    k_scan<<<DD, 32>>>(fw_init, eta);
    k_mlp<<<TT, 256>>>(mlp_aw, mlp_ab, mlp_bw, mlp_bb);
    k_head<<<dim3(VV/128, TT/128), 256>>>(head_b, out);
    k_softmax<<<TT, 256>>>(out, targets);
    if (out_size >= TT*VV + 1)
        k_loss<<<1, 256>>>(out + (size_t)TT*VV);
}

// round 6
// speedup vs baseline: 1.4881x; 1.3773x over previous
#include <cuda_runtime.h>
#include <cuda_bf16.h>
#include <math.h>
#include <stdint.h>

#define DD 512
#define HH 20
#define VV 32000
#define TT 1024

// Scratch (allocation-free rule: __device__ globals)
__device__ float g_X [TT*DD];
__device__ float g_Z0[TT*DD];
__device__ float g_Z1[TT*DD];
__device__ float g_Y [TT*DD];
__device__ float g_rowloss[TT];
// Chunk-major, pre-swizzled bf16 hi/lo operands for the head GEMM.
// Element (row, k) lives at byte offset  g = ((kc*ROWS + row)*64 + kk)*2,
// stored at g ^ ((g>>3)&0x70)  (SW128 swizzle, kc = k/64, kk = k%64).
__device__ __nv_bfloat16 g_Ahic[TT*DD];
__device__ __nv_bfloat16 g_Aloc[TT*DD];
__device__ __nv_bfloat16 g_Bhic[(size_t)VV*DD];
__device__ __nv_bfloat16 g_Bloc[(size_t)VV*DD];

// ---------------------------------------------------------------------------
// PTX helpers (all Hopper-era features; compile on plain sm_103 target)
// ---------------------------------------------------------------------------
__device__ __forceinline__ uint32_t smem_u32(const void* p) {
    uint32_t a;
    asm("{ .reg .u64 t; cvta.to.shared.u64 t, %1; cvt.u32.u64 %0, t; }" : "=r"(a) : "l"(p));
    return a;
}
#define MBAR_INIT(a, c) asm volatile("mbarrier.init.shared.b64 [%0], %1;" :: "r"(a), "r"(c) : "memory")
#define MBAR_EXPECT_TX(a, b) \
    asm volatile("mbarrier.arrive.expect_tx.shared.b64 _, [%0], %1;" :: "r"(a), "r"(b) : "memory")
__device__ __forceinline__ void mbar_wait(uint32_t mbar, uint32_t parity) {
    uint32_t done;
    asm volatile("{ .reg .pred p; mbarrier.try_wait.parity.acquire.cta.shared::cta.b64 p, [%1], %2; selp.b32 %0,1,0,p; }"
                 : "=r"(done) : "r"(mbar), "r"(parity) : "memory");
    if (!done) {
        asm volatile("{ .reg .pred P1;\nWL_%=:\n"
                     "mbarrier.try_wait.parity.acquire.cta.shared::cta.b64 P1, [%0], %1, 0x989680;\n"
                     "@P1 bra.uni WD_%=;\n bra.uni WL_%=;\nWD_%=:\n}"
                     :: "r"(mbar), "r"(parity) : "memory");
    }
}
__device__ __forceinline__ void bulk_cp(uint32_t dst, const void* gsrc,
                                        uint32_t bytes, uint32_t mbar) {
    asm volatile("cp.async.bulk.shared::cluster.global.mbarrier::complete_tx::bytes [%0], [%1], %2, [%3];"
                 :: "r"(dst), "l"(__cvta_generic_to_global(gsrc)), "r"(bytes), "r"(mbar) : "memory");
}
// bf16 mma.sync m16n8k16, fp32 accumulate
__device__ __forceinline__ void mma16816(float c[4], const unsigned a[4], const unsigned b[2]) {
    asm volatile(
        "mma.sync.aligned.m16n8k16.row.col.f32.bf16.bf16.f32 "
        "{%0,%1,%2,%3}, {%4,%5,%6,%7}, {%8,%9}, {%0,%1,%2,%3};\n"
        : "+f"(c[0]), "+f"(c[1]), "+f"(c[2]), "+f"(c[3])
        : "r"(a[0]), "r"(a[1]), "r"(a[2]), "r"(a[3]), "r"(b[0]), "r"(b[1]));
}

// ---------------------------------------------------------------------------
// 1) X = embed[tokens]
// ---------------------------------------------------------------------------
__global__ void k_gather(const int* __restrict__ tokens,
                         const float* __restrict__ embed) {
    int idx = blockIdx.x * blockDim.x + threadIdx.x;
    if (idx < TT * DD) {
        int t = idx >> 9, d = idx & 511;
        g_X[idx] = embed[(size_t)tokens[t] * DD + d];
    }
}

// ---------------------------------------------------------------------------
// 1b) head_w [512][32000] -> chunk-major swizzled bf16 hi/lo [kc][n][64]
//     Tile: 64 k x 64 n per block, transpose through smem.
// ---------------------------------------------------------------------------
__global__ void __launch_bounds__(256) k_convB(const float* __restrict__ W) {
    __shared__ float tile[64][65];
    int n0 = blockIdx.x * 64;
    int k0 = blockIdx.y * 64;      // == kc*64
    int tid = threadIdx.x;
    #pragma unroll
    for (int i = 0; i < 16; i++) {
        int f = tid + 256 * i;
        int k = f >> 6, n = f & 63;
        tile[k][n] = W[(size_t)(k0 + k) * VV + n0 + n];
    }
    __syncthreads();
    size_t kc = (size_t)(k0 >> 6);
    char* bh = (char*)g_Bhic;
    char* bl = (char*)g_Bloc;
    #pragma unroll
    for (int i = 0; i < 16; i++) {
        int f = tid + 256 * i;
        int n = f >> 6, kk = f & 63;
        float v = tile[kk][n];
        __nv_bfloat16 hi = __float2bfloat16_rn(v);
        __nv_bfloat16 lo = __float2bfloat16_rn(v - __bfloat162float(hi));
        size_t g = ((kc * VV + (n0 + n)) * 64 + kk) * 2;
        size_t sw = g ^ ((g >> 3) & 0x70);
        *(__nv_bfloat16*)(bh + sw) = hi;
        *(__nv_bfloat16*)(bl + sw) = lo;
    }
}

// ---------------------------------------------------------------------------
// 2) Z0 = X @ wa, Z1 = X @ wb
// ---------------------------------------------------------------------------
__global__ void __launch_bounds__(256) k_zgemm(const float* __restrict__ wa,
                                               const float* __restrict__ wb) {
    __shared__ float Xs [16][64];
    __shared__ float Was[16][64];
    __shared__ float Wbs[16][64];
    int tid = threadIdx.x;
    int n0 = blockIdx.x * 64;
    int m0 = blockIdx.y * 64;
    int ty = tid >> 4, tx = tid & 15;
    float a0[4][4] = {}, a1[4][4] = {};

    for (int k0 = 0; k0 < DD; k0 += 16) {
        {
            int m  = tid >> 2;
            int kq = (tid & 3) * 4;
            float4 v = *(const float4*)&g_X[(size_t)(m0 + m) * DD + k0 + kq];
            Xs[kq+0][m] = v.x; Xs[kq+1][m] = v.y; Xs[kq+2][m] = v.z; Xs[kq+3][m] = v.w;
        }
        {
            int k  = tid >> 4;
            int nq = (tid & 15) * 4;
            *(float4*)&Was[k][nq] = *(const float4*)&wa[(size_t)(k0 + k) * DD + n0 + nq];
            *(float4*)&Wbs[k][nq] = *(const float4*)&wb[(size_t)(k0 + k) * DD + n0 + nq];
        }
        __syncthreads();
        #pragma unroll
        for (int k = 0; k < 16; k++) {
            float xr[4], war[4], wbr[4];
            #pragma unroll
            for (int i = 0; i < 4; i++) xr[i] = Xs[k][ty*4 + i];
            #pragma unroll
            for (int j = 0; j < 4; j++) { war[j] = Was[k][tx*4 + j]; wbr[j] = Wbs[k][tx*4 + j]; }
            #pragma unroll
            for (int i = 0; i < 4; i++)
                #pragma unroll
                for (int j = 0; j < 4; j++) {
                    a0[i][j] = fmaf(xr[i], war[j], a0[i][j]);
                    a1[i][j] = fmaf(xr[i], wbr[j], a1[i][j]);
                }
        }
        __syncthreads();
    }
    #pragma unroll
    for (int i = 0; i < 4; i++) {
        int row = m0 + ty*4 + i;
        #pragma unroll
        for (int j = 0; j < 4; j++) {
            int col = n0 + tx*4 + j;
            g_Z0[(size_t)row * DD + col] = a0[i][j];
            g_Z1[(size_t)row * DD + col] = a1[i][j];
        }
    }
}

// ---------------------------------------------------------------------------
// 3) Scan: 4 warps/CTA (one column each) -> warps spread over all 4 SMSPs.
// ---------------------------------------------------------------------------
__global__ void __launch_bounds__(128) k_scan(const float* __restrict__ fw_init,
                                              const float* __restrict__ eta_p) {
    int wid  = threadIdx.x >> 5;
    int lane = threadIdx.x & 31;
    int j = blockIdx.x * 4 + wid;
    float eta = *eta_p;
    float fw[16];
    #pragma unroll
    for (int k = 0; k < 16; k++)
        fw[k] = fw_init[(size_t)(lane + 32*k) * DD + j];

    for (int t = 0; t < TT; t++) {
        float z1v = __ldg(&g_Z1[(size_t)t * DD + j]);
        float p = eta * z1v;
        float yacc = 0.f;
        #pragma unroll
        for (int k = 0; k < 16; k++) {
            int i = lane + 32*k;
            float z0v = g_Z0[(size_t)t * DD + i];
            float xv  = g_X [(size_t)t * DD + i];
            float v  = fmaf(z0v, p, fw[k]);
            float e  = __expf(v + v);
            float th = 1.f - __fdividef(2.f, e + 1.f);
            fw[k] = th;
            yacc = fmaf(xv, th, yacc);
        }
        #pragma unroll
        for (int off = 16; off; off >>= 1)
            yacc += __shfl_xor_sync(0xffffffffu, yacc, off);
        if (lane == 0) g_Y[(size_t)t * DD + j] = yacc;
    }
}

// ---------------------------------------------------------------------------
// 4) MLP + mix; epilogue emits chunk-major swizzled bf16 hi/lo of "mixed"
// ---------------------------------------------------------------------------
__global__ void k_mlp(const float* __restrict__ aw, const float* __restrict__ ab,
                      const float* __restrict__ bw, const float* __restrict__ bb) {
    __shared__ float ys[DD];
    __shared__ float hs[HH];
    int t = blockIdx.x, tid = threadIdx.x;
    for (int d = tid; d < DD; d += 256) ys[d] = g_Y[(size_t)t * DD + d];
    __syncthreads();
    int w = tid >> 5, lane = tid & 31;
    for (int u = w; u < HH; u += 8) {
        float acc = 0.f;
        #pragma unroll
        for (int k = 0; k < 16; k++) {
            int d = lane + 32*k;
            acc = fmaf(ys[d], aw[(size_t)d * HH + u], acc);
        }
        #pragma unroll
        for (int off = 16; off; off >>= 1)
            acc += __shfl_xor_sync(0xffffffffu, acc, off);
        if (lane == 0) {
            float hv = acc + ab[u];
            const float SC = 1.0507009873554805f, AL = 1.6732632423543772f;
            hs[u] = hv > 0.f ? SC * hv : SC * AL * expm1f(hv);
        }
    }
    __syncthreads();
    char* ah = (char*)g_Ahic;
    char* al = (char*)g_Aloc;
    for (int j = tid; j < DD; j += 256) {
        float o = bb[j];
        #pragma unroll
        for (int k = 0; k < HH; k++)
            o = fmaf(hs[k], bw[(size_t)k * DD + j], o);
        float mx = 0.5f * o + 0.5f * g_X[(size_t)t * DD + j];
        __nv_bfloat16 hi = __float2bfloat16_rn(mx);
        __nv_bfloat16 lo = __float2bfloat16_rn(mx - __bfloat162float(hi));
        size_t g = (((size_t)(j >> 6) * TT + t) * 64 + (j & 63)) * 2;
        size_t sw = g ^ ((g >> 3) & 0x70);
        *(__nv_bfloat16*)(ah + sw) = hi;
        *(__nv_bfloat16*)(al + sw) = lo;
    }
}

// ---------------------------------------------------------------------------
// 5) Head GEMM: logits[1024,32000] = mixed @ head_w^T + bias  (mma.sync bf16,
//    split-bf16 3-term).  CTA tile 128x128, K in 8 chunks of 64.
//    Each chunk = 4 x 16KB contiguous pre-swizzled tiles fetched with
//    cp.async.bulk (one instruction each), double-buffered on mbarriers.
// ---------------------------------------------------------------------------
#define TILE_B   16384           // 128 rows x 128 bytes
#define CH_B     (4*TILE_B)      // Ahi, Alo, Bhi, Blo
#define HEAD_SMEM (1024 + 2*CH_B)

__global__ void __launch_bounds__(256, 1) k_head(const float* __restrict__ bias,
                                                 float* __restrict__ out) {
    extern __shared__ __align__(1024) char smem[];
    uint32_t sb = smem_u32(smem);
    int tid  = threadIdx.x;
    int wid  = tid >> 5;
    int lane = tid & 31;
    int grp  = lane >> 2;        // 0..7
    int t4   = lane & 3;         // 0..3
    int m0 = blockIdx.x * 128;   // m fastest -> B tiles reused across wave
    int n0 = blockIdx.y * 128;
    int wm = wid & 1;            // 2 M-subtiles of 64
    int wn = wid >> 1;           // 4 N-subtiles of 32

    if (tid == 0) { MBAR_INIT(sb, 1); MBAR_INIT(sb + 8, 1); }
    __syncthreads();

    const char* gAh = (const char*)g_Ahic;
    const char* gAl = (const char*)g_Aloc;
    const char* gBh = (const char*)g_Bhic;
    const char* gBl = (const char*)g_Bloc;

    auto issue = [&](int c) {
        int buf = c & 1;
        uint32_t mb  = sb + buf * 8;
        uint32_t dst = sb + 1024 + buf * CH_B;
        MBAR_EXPECT_TX(mb, CH_B);
        size_t aoff = ((size_t)c * TT + m0) * 128;   // 16KB tile, 16KB aligned
        size_t boff = ((size_t)c * VV + n0) * 128;
        bulk_cp(dst,            gAh + aoff, TILE_B, mb);
        bulk_cp(dst +   TILE_B, gAl + aoff, TILE_B, mb);
        bulk_cp(dst + 2*TILE_B, gBh + boff, TILE_B, mb);
        bulk_cp(dst + 3*TILE_B, gBl + boff, TILE_B, mb);
    };
    if (tid == 0) { issue(0); issue(1); }

    float acc[4][4][4] = {};
    unsigned xorv = (unsigned)(grp << 4);   // swizzle xor, same for every frag row

    for (int c = 0; c < 8; c++) {
        mbar_wait(sb + (c & 1) * 8, (c >> 1) & 1);
        const char* base = smem + 1024 + (c & 1) * CH_B;
        const char* pAh = base;
        const char* pAl = base + TILE_B;
        const char* pBh = base + 2*TILE_B;
        const char* pBl = base + 3*TILE_B;

        #pragma unroll
        for (int ks = 0; ks < 4; ks++) {
            unsigned c0 = ((unsigned)(ks*32 + t4*4)      ) ^ xorv;   // k = ks*16 + t4*2
            unsigned c1 = ((unsigned)(ks*32 + t4*4 + 16) ) ^ xorv;   // k + 8
            unsigned ah[4][4], al[4][4], bh[4][2], bl[4][2];
            #pragma unroll
            for (int mi = 0; mi < 4; mi++) {
                unsigned r0 = (unsigned)(wm*64 + mi*16 + grp) * 128;
                unsigned r1 = r0 + 8*128;
                ah[mi][0] = *(const unsigned*)(pAh + r0 + c0);
                ah[mi][1] = *(const unsigned*)(pAh + r1 + c0);
                ah[mi][2] = *(const unsigned*)(pAh + r0 + c1);
                ah[mi][3] = *(const unsigned*)(pAh + r1 + c1);
                al[mi][0] = *(const unsigned*)(pAl + r0 + c0);
                al[mi][1] = *(const unsigned*)(pAl + r1 + c0);
                al[mi][2] = *(const unsigned*)(pAl + r0 + c1);
                al[mi][3] = *(const unsigned*)(pAl + r1 + c1);
            }
            #pragma unroll
            for (int ni = 0; ni < 4; ni++) {
                unsigned r = (unsigned)(wn*32 + ni*8 + grp) * 128;
                bh[ni][0] = *(const unsigned*)(pBh + r + c0);
                bh[ni][1] = *(const unsigned*)(pBh + r + c1);
                bl[ni][0] = *(const unsigned*)(pBl + r + c0);
                bl[ni][1] = *(const unsigned*)(pBl + r + c1);
            }
            #pragma unroll
            for (int mi = 0; mi < 4; mi++)
                #pragma unroll
                for (int ni = 0; ni < 4; ni++) {
                    mma16816(acc[mi][ni], ah[mi], bh[ni]);
                    mma16816(acc[mi][ni], ah[mi], bl[ni]);
                    mma16816(acc[mi][ni], al[mi], bh[ni]);
                }
        }
        __syncthreads();                    // all warps done reading this buffer
        if (tid == 0 && c + 2 < 8) issue(c + 2);
    }

    // epilogue: add bias, write fp32 logits
    #pragma unroll
    for (int mi = 0; mi < 4; mi++) {
        int r0 = m0 + wm * 64 + mi * 16 + grp;
        #pragma unroll
        for (int ni = 0; ni < 4; ni++) {
            int col = n0 + wn * 32 + ni * 8 + t4 * 2;
            float2 bv = *(const float2*)&bias[col];
            float2 v0 = { acc[mi][ni][0] + bv.x, acc[mi][ni][1] + bv.y };
            float2 v1 = { acc[mi][ni][2] + bv.x, acc[mi][ni][3] + bv.y };
            *(float2*)&out[(size_t)r0       * VV + col] = v0;
            *(float2*)&out[(size_t)(r0 + 8) * VV + col] = v1;
        }
    }
}

// ---------------------------------------------------------------------------
// 6) online log-softmax -> per-row loss; 7) final mean
// ---------------------------------------------------------------------------
__global__ void k_softmax(const float* __restrict__ logits,
                          const int* __restrict__ targets) {
    __shared__ float sm[256], ss[256];
    int t = blockIdx.x, tid = threadIdx.x;
    const float* row = logits + (size_t)t * VV;
    float m = -INFINITY, s = 0.f;
    for (int c = tid * 4; c < VV; c += 1024) {
        float4 v = *(const float4*)&row[c];
        float vm = fmaxf(fmaxf(v.x, v.y), fmaxf(v.z, v.w));
        float nm = fmaxf(m, vm);
        s = s * __expf(m - nm) + __expf(v.x - nm) + __expf(v.y - nm)
          + __expf(v.z - nm) + __expf(v.w - nm);
        m = nm;
    }
    sm[tid] = m; ss[tid] = s; __syncthreads();
    for (int st = 128; st; st >>= 1) {
        if (tid < st) {
            float m2 = fmaxf(sm[tid], sm[tid + st]);
            ss[tid] = ss[tid] * __expf(sm[tid] - m2) + ss[tid + st] * __expf(sm[tid + st] - m2);
            sm[tid] = m2;
        }
        __syncthreads();
    }
    if (tid == 0)
        g_rowloss[t] = row[targets[t]] - sm[0] - logf(ss[0]);
}

__global__ void k_loss(float* __restrict__ out) {
    __shared__ float red[256];
    int tid = threadIdx.x;
    float s = 0.f;
    for (int t = tid; t < TT; t += 256) s += g_rowloss[t];
    red[tid] = s; __syncthreads();
    for (int st = 128; st; st >>= 1) { if (tid < st) red[tid] += red[tid+st]; __syncthreads(); }
    if (tid == 0) out[0] = -red[0] / (float)TT;
}

// ---------------------------------------------------------------------------
extern "C" void kernel_launch(void* const* d_in, const int* in_sizes, int n_in,
                              void* d_out, int out_size) {
    const int*   tokens  = (const int*)  d_in[0];
    const int*   targets = (const int*)  d_in[1];
    const float* embed   = (const float*)d_in[2];
    const float* fw_init = (const float*)d_in[3];
    const float* eta     = (const float*)d_in[4];
    const float* wa      = (const float*)d_in[5];
    const float* wb      = (const float*)d_in[6];
    const float* mlp_aw  = (const float*)d_in[7];
    const float* mlp_ab  = (const float*)d_in[8];
    const float* mlp_bw  = (const float*)d_in[9];
    const float* mlp_bb  = (const float*)d_in[10];
    const float* head_w  = (const float*)d_in[11];
    const float* head_b  = (const float*)d_in[12];
    float* out = (float*)d_out;

    static int smem_set = 0;
    if (!smem_set) {
        cudaFuncSetAttribute(k_head, cudaFuncAttributeMaxDynamicSharedMemorySize, HEAD_SMEM);
        smem_set = 1;
    }

    k_gather<<<(TT*DD + 255) / 256, 256>>>(tokens, embed);
    k_convB<<<dim3(VV/64, DD/64), 256>>>(head_w);
    k_zgemm<<<dim3(DD/64, TT/64), 256>>>(wa, wb);
    k_scan<<<DD/4, 128>>>(fw_init, eta);
    k_mlp<<<TT, 256>>>(mlp_aw, mlp_ab, mlp_bw, mlp_bb);
    k_head<<<dim3(TT/128, VV/128), 256, HEAD_SMEM>>>(head_b, out);
    k_softmax<<<TT, 256>>>(out, targets);
    if (out_size >= TT*VV + 1)
        k_loss<<<1, 256>>>(out + (size_t)TT*VV);
}

// round 7
// speedup vs baseline: 1.5239x; 1.0241x over previous
#include <cuda_runtime.h>
#include <cuda_bf16.h>
#include <math.h>
#include <stdint.h>

#define DD 512
#define HH 20
#define VV 32000
#define TT 1024

// Scratch (allocation-free rule: __device__ globals)
__device__ float g_X [TT*DD];
__device__ float g_Z0[TT*DD];
__device__ float g_Z1[TT*DD];
__device__ float g_Y [TT*DD];
__device__ float g_rowloss[TT];
__device__ unsigned g_bar;        // grid barrier counter (monotonic, mod-128)
// Chunk-major, pre-swizzled bf16 hi/lo operands for the head GEMM.
// Element (row, k): g = ((kc*ROWS + row)*64 + kk)*2, stored at g ^ ((g>>3)&0x70).
__device__ __nv_bfloat16 g_Ahic[TT*DD];
__device__ __nv_bfloat16 g_Aloc[TT*DD];
__device__ __nv_bfloat16 g_Bhic[(size_t)VV*DD];
__device__ __nv_bfloat16 g_Bloc[(size_t)VV*DD];

// ---------------------------------------------------------------------------
// PTX helpers
// ---------------------------------------------------------------------------
__device__ __forceinline__ uint32_t smem_u32(const void* p) {
    uint32_t a;
    asm("{ .reg .u64 t; cvta.to.shared.u64 t, %1; cvt.u32.u64 %0, t; }" : "=r"(a) : "l"(p));
    return a;
}
#define MBAR_INIT(a, c) asm volatile("mbarrier.init.shared.b64 [%0], %1;" :: "r"(a), "r"(c) : "memory")
#define MBAR_EXPECT_TX(a, b) \
    asm volatile("mbarrier.arrive.expect_tx.shared.b64 _, [%0], %1;" :: "r"(a), "r"(b) : "memory")
__device__ __forceinline__ void mbar_wait(uint32_t mbar, uint32_t parity) {
    uint32_t done;
    asm volatile("{ .reg .pred p; mbarrier.try_wait.parity.acquire.cta.shared::cta.b64 p, [%1], %2; selp.b32 %0,1,0,p; }"
                 : "=r"(done) : "r"(mbar), "r"(parity) : "memory");
    if (!done) {
        asm volatile("{ .reg .pred P1;\nWL_%=:\n"
                     "mbarrier.try_wait.parity.acquire.cta.shared::cta.b64 P1, [%0], %1, 0x989680;\n"
                     "@P1 bra.uni WD_%=;\n bra.uni WL_%=;\nWD_%=:\n}"
                     :: "r"(mbar), "r"(parity) : "memory");
    }
}
__device__ __forceinline__ void bulk_cp(uint32_t dst, const void* gsrc,
                                        uint32_t bytes, uint32_t mbar) {
    asm volatile("cp.async.bulk.shared::cluster.global.mbarrier::complete_tx::bytes [%0], [%1], %2, [%3];"
                 :: "r"(dst), "l"(__cvta_generic_to_global(gsrc)), "r"(bytes), "r"(mbar) : "memory");
}
__device__ __forceinline__ void ldsm4(unsigned r[4], uint32_t addr) {
    asm volatile("ldmatrix.sync.aligned.m8n8.x4.shared.b16 {%0,%1,%2,%3}, [%4];"
                 : "=r"(r[0]), "=r"(r[1]), "=r"(r[2]), "=r"(r[3]) : "r"(addr));
}
__device__ __forceinline__ void mma16816(float c[4], const unsigned a[4], const unsigned b[2]) {
    asm volatile(
        "mma.sync.aligned.m16n8k16.row.col.f32.bf16.bf16.f32 "
        "{%0,%1,%2,%3}, {%4,%5,%6,%7}, {%8,%9}, {%0,%1,%2,%3};\n"
        : "+f"(c[0]), "+f"(c[1]), "+f"(c[2]), "+f"(c[3])
        : "r"(a[0]), "r"(a[1]), "r"(a[2]), "r"(a[3]), "r"(b[0]), "r"(b[1]));
}

// ---------------------------------------------------------------------------
// 1) k_prep: blocks [0,4000): convB transpose+split; [4000,6048): gather X
// ---------------------------------------------------------------------------
__global__ void __launch_bounds__(256) k_prep(const int* __restrict__ tokens,
                                              const float* __restrict__ embed,
                                              const float* __restrict__ W) {
    __shared__ float tile[64][65];
    int bid = blockIdx.x;
    int tid = threadIdx.x;
    if (bid < 4000) {
        int n0 = (bid % 500) * 64;
        int k0 = (bid / 500) * 64;
        #pragma unroll
        for (int i = 0; i < 16; i++) {
            int f = tid + 256 * i;
            int k = f >> 6, n = f & 63;
            tile[k][n] = W[(size_t)(k0 + k) * VV + n0 + n];
        }
        __syncthreads();
        size_t kc = (size_t)(k0 >> 6);
        char* bh = (char*)g_Bhic;
        char* bl = (char*)g_Bloc;
        #pragma unroll
        for (int i = 0; i < 16; i++) {
            int f = tid + 256 * i;
            int n = f >> 6, kk = f & 63;
            float v = tile[kk][n];
            __nv_bfloat16 hi = __float2bfloat16_rn(v);
            __nv_bfloat16 lo = __float2bfloat16_rn(v - __bfloat162float(hi));
            size_t g = ((kc * VV + (n0 + n)) * 64 + kk) * 2;
            size_t sw = g ^ ((g >> 3) & 0x70);
            *(__nv_bfloat16*)(bh + sw) = hi;
            *(__nv_bfloat16*)(bl + sw) = lo;
        }
    } else {
        int idx = (bid - 4000) * 256 + tid;
        if (idx < TT * DD) {
            int t = idx >> 9, d = idx & 511;
            g_X[idx] = embed[(size_t)tokens[t] * DD + d];
        }
    }
}

// ---------------------------------------------------------------------------
// 2) Z0 = X @ wa, Z1 = X @ wb
// ---------------------------------------------------------------------------
__global__ void __launch_bounds__(256) k_zgemm(const float* __restrict__ wa,
                                               const float* __restrict__ wb) {
    __shared__ float Xs [16][64];
    __shared__ float Was[16][64];
    __shared__ float Wbs[16][64];
    int tid = threadIdx.x;
    int n0 = blockIdx.x * 64;
    int m0 = blockIdx.y * 64;
    int ty = tid >> 4, tx = tid & 15;
    float a0[4][4] = {}, a1[4][4] = {};

    for (int k0 = 0; k0 < DD; k0 += 16) {
        {
            int m  = tid >> 2;
            int kq = (tid & 3) * 4;
            float4 v = *(const float4*)&g_X[(size_t)(m0 + m) * DD + k0 + kq];
            Xs[kq+0][m] = v.x; Xs[kq+1][m] = v.y; Xs[kq+2][m] = v.z; Xs[kq+3][m] = v.w;
        }
        {
            int k  = tid >> 4;
            int nq = (tid & 15) * 4;
            *(float4*)&Was[k][nq] = *(const float4*)&wa[(size_t)(k0 + k) * DD + n0 + nq];
            *(float4*)&Wbs[k][nq] = *(const float4*)&wb[(size_t)(k0 + k) * DD + n0 + nq];
        }
        __syncthreads();
        #pragma unroll
        for (int k = 0; k < 16; k++) {
            float xr[4], war[4], wbr[4];
            #pragma unroll
            for (int i = 0; i < 4; i++) xr[i] = Xs[k][ty*4 + i];
            #pragma unroll
            for (int j = 0; j < 4; j++) { war[j] = Was[k][tx*4 + j]; wbr[j] = Wbs[k][tx*4 + j]; }
            #pragma unroll
            for (int i = 0; i < 4; i++)
                #pragma unroll
                for (int j = 0; j < 4; j++) {
                    a0[i][j] = fmaf(xr[i], war[j], a0[i][j]);
                    a1[i][j] = fmaf(xr[i], wbr[j], a1[i][j]);
                }
        }
        __syncthreads();
    }
    #pragma unroll
    for (int i = 0; i < 4; i++) {
        int row = m0 + ty*4 + i;
        #pragma unroll
        for (int j = 0; j < 4; j++) {
            int col = n0 + tx*4 + j;
            g_Z0[(size_t)row * DD + col] = a0[i][j];
            g_Z1[(size_t)row * DD + col] = a1[i][j];
        }
    }
}

// ---------------------------------------------------------------------------
// 3) Persistent scan + grid barrier + MLP.  128 CTAs x 128 threads.
//    Phase A: scan (warp w owns column j = bid*4 + w).
//    Barrier: monotonic atomic counter, mod-128 (graph-replay safe).
//    Phase B: MLP+mix for tokens [bid*8, bid*8+8), emits swizzled bf16 hi/lo.
// ---------------------------------------------------------------------------
__global__ void __launch_bounds__(128) k_scanmlp(
        const float* __restrict__ fw_init, const float* __restrict__ eta_p,
        const float* __restrict__ aw, const float* __restrict__ ab,
        const float* __restrict__ bw, const float* __restrict__ bb) {
    __shared__ float ys[DD];
    __shared__ float hs[HH];
    int tid  = threadIdx.x;
    int wid  = tid >> 5;
    int lane = tid & 31;
    int bid  = blockIdx.x;

    // ---- Phase A: scan ----
    {
        int j = bid * 4 + wid;
        float eta = *eta_p;
        float fw[16];
        #pragma unroll
        for (int k = 0; k < 16; k++)
            fw[k] = fw_init[(size_t)(lane + 32*k) * DD + j];

        for (int t = 0; t < TT; t++) {
            float z1v = __ldg(&g_Z1[(size_t)t * DD + j]);
            float p = eta * z1v;
            float yacc = 0.f;
            #pragma unroll
            for (int k = 0; k < 16; k++) {
                int i = lane + 32*k;
                float z0v = g_Z0[(size_t)t * DD + i];
                float xv  = g_X [(size_t)t * DD + i];
                float v  = fmaf(z0v, p, fw[k]);
                float e  = __expf(v + v);
                float th = 1.f - __fdividef(2.f, e + 1.f);
                fw[k] = th;
                yacc = fmaf(xv, th, yacc);
            }
            #pragma unroll
            for (int off = 16; off; off >>= 1)
                yacc += __shfl_xor_sync(0xffffffffu, yacc, off);
            if (lane == 0) g_Y[(size_t)t * DD + j] = yacc;
        }
    }

    // ---- Grid barrier (all 128 CTAs resident; counter stays monotonic) ----
    __threadfence();
    __syncthreads();
    if (tid == 0) {
        atomicAdd(&g_bar, 1u);
        volatile unsigned* vb = &g_bar;
        while (*vb & 127u) { }
    }
    __syncthreads();
    __threadfence();

    // ---- Phase B: MLP + mix for 8 tokens ----
    char* ahp = (char*)g_Ahic;
    char* alp = (char*)g_Aloc;
    for (int it = 0; it < 8; it++) {
        int t = bid * 8 + it;
        for (int d = tid; d < DD; d += 128) ys[d] = g_Y[(size_t)t * DD + d];
        __syncthreads();
        for (int u = wid; u < HH; u += 4) {
            float acc = 0.f;
            #pragma unroll
            for (int k = 0; k < 16; k++) {
                int d = lane + 32*k;
                acc = fmaf(ys[d], aw[(size_t)d * HH + u], acc);
            }
            #pragma unroll
            for (int off = 16; off; off >>= 1)
                acc += __shfl_xor_sync(0xffffffffu, acc, off);
            if (lane == 0) {
                float hv = acc + ab[u];
                const float SC = 1.0507009873554805f, AL = 1.6732632423543772f;
                hs[u] = hv > 0.f ? SC * hv : SC * AL * expm1f(hv);
            }
        }
        __syncthreads();
        for (int j = tid; j < DD; j += 128) {
            float o = bb[j];
            #pragma unroll
            for (int k = 0; k < HH; k++)
                o = fmaf(hs[k], bw[(size_t)k * DD + j], o);
            float mx = 0.5f * o + 0.5f * g_X[(size_t)t * DD + j];
            __nv_bfloat16 hi = __float2bfloat16_rn(mx);
            __nv_bfloat16 lo = __float2bfloat16_rn(mx - __bfloat162float(hi));
            size_t g = (((size_t)(j >> 6) * TT + t) * 64 + (j & 63)) * 2;
            size_t sw = g ^ ((g >> 3) & 0x70);
            *(__nv_bfloat16*)(ahp + sw) = hi;
            *(__nv_bfloat16*)(alp + sw) = lo;
        }
        __syncthreads();
    }
}

// ---------------------------------------------------------------------------
// 4) Head GEMM: logits = mixed @ head_w^T + bias (mma.sync bf16, 3-term split)
//    CTA 128x128 tile, 512 threads (16 warps, warp tile 32x32), K = 8 x 64,
//    bulk-TMA double buffer, ldmatrix fragment loads.
// ---------------------------------------------------------------------------
#define TILE_B   16384           // 128 rows x 128 bytes
#define CH_B     (4*TILE_B)      // Ahi, Alo, Bhi, Blo
#define HEAD_SMEM (1024 + 2*CH_B)

__global__ void __launch_bounds__(512, 1) k_head(const float* __restrict__ bias,
                                                 float* __restrict__ out) {
    extern __shared__ __align__(1024) char smem[];
    uint32_t sb = smem_u32(smem);
    int tid  = threadIdx.x;
    int wid  = tid >> 5;
    int lane = tid & 31;
    int grp  = lane >> 2;
    int t4   = lane & 3;
    int m0 = blockIdx.x * 128;   // m fastest -> B tiles L2-shared across wave
    int n0 = blockIdx.y * 128;
    int wm = wid & 3;            // 4 M-subtiles of 32
    int wn = wid >> 2;           // 4 N-subtiles of 32

    if (tid == 0) { MBAR_INIT(sb, 1); MBAR_INIT(sb + 8, 1); }
    __syncthreads();

    const char* gAh = (const char*)g_Ahic;
    const char* gAl = (const char*)g_Aloc;
    const char* gBh = (const char*)g_Bhic;
    const char* gBl = (const char*)g_Bloc;

    auto issue = [&](int c) {
        int buf = c & 1;
        uint32_t mb  = sb + buf * 8;
        uint32_t dst = sb + 1024 + buf * CH_B;
        MBAR_EXPECT_TX(mb, CH_B);
        size_t aoff = ((size_t)c * TT + m0) * 128;
        size_t boff = ((size_t)c * VV + n0) * 128;
        bulk_cp(dst,            gAh + aoff, TILE_B, mb);
        bulk_cp(dst +   TILE_B, gAl + aoff, TILE_B, mb);
        bulk_cp(dst + 2*TILE_B, gBh + boff, TILE_B, mb);
        bulk_cp(dst + 3*TILE_B, gBl + boff, TILE_B, mb);
    };
    if (tid == 0) { issue(0); issue(1); }

    float acc[2][4][4] = {};     // [mi][ni][frag]

    // ldmatrix lane address components (constant per lane)
    uint32_t aRow  = (uint32_t)(wm*32 + (lane & 15));     // + mi*16
    uint32_t aByte = aRow * 128;
    uint32_t aXor  = (aRow & 7) << 4;
    uint32_t aKb   = (uint32_t)((lane >> 4) * 16);        // + ks*32
    uint32_t bRow  = (uint32_t)(wn*32 + (lane & 7) + ((lane >> 4) & 1) * 8);  // + p*16
    uint32_t bByte = bRow * 128;
    uint32_t bXor  = (bRow & 7) << 4;
    uint32_t bKb   = (uint32_t)(((lane >> 3) & 1) * 16);  // + ks*32

    for (int c = 0; c < 8; c++) {
        mbar_wait(sb + (c & 1) * 8, (c >> 1) & 1);
        uint32_t base = sb + 1024 + (c & 1) * CH_B;
        uint32_t pAh = base;
        uint32_t pAl = base + TILE_B;
        uint32_t pBh = base + 2*TILE_B;
        uint32_t pBl = base + 3*TILE_B;

        #pragma unroll
        for (int ks = 0; ks < 4; ks++) {
            uint32_t ka = ((uint32_t)(ks*32) + aKb) ^ aXor;
            uint32_t kb = ((uint32_t)(ks*32) + bKb) ^ bXor;
            unsigned ah[2][4], al[2][4], bh[4][2], bl[4][2];
            #pragma unroll
            for (int mi = 0; mi < 2; mi++) {
                ldsm4(ah[mi], pAh + aByte + mi*2048 + ka);
                ldsm4(al[mi], pAl + aByte + mi*2048 + ka);
            }
            #pragma unroll
            for (int p = 0; p < 2; p++) {
                unsigned tmp[4];
                ldsm4(tmp, pBh + bByte + p*2048 + kb);
                bh[p*2][0] = tmp[0]; bh[p*2][1] = tmp[1];
                bh[p*2+1][0] = tmp[2]; bh[p*2+1][1] = tmp[3];
                ldsm4(tmp, pBl + bByte + p*2048 + kb);
                bl[p*2][0] = tmp[0]; bl[p*2][1] = tmp[1];
                bl[p*2+1][0] = tmp[2]; bl[p*2+1][1] = tmp[3];
            }
            #pragma unroll
            for (int mi = 0; mi < 2; mi++)
                #pragma unroll
                for (int ni = 0; ni < 4; ni++) {
                    mma16816(acc[mi][ni], ah[mi], bh[ni]);
                    mma16816(acc[mi][ni], ah[mi], bl[ni]);
                    mma16816(acc[mi][ni], al[mi], bh[ni]);
                }
        }
        __syncthreads();
        if (tid == 0 && c + 2 < 8) issue(c + 2);
    }

    // epilogue: add bias, write fp32 logits
    #pragma unroll
    for (int mi = 0; mi < 2; mi++) {
        int r0 = m0 + wm * 32 + mi * 16 + grp;
        #pragma unroll
        for (int ni = 0; ni < 4; ni++) {
            int col = n0 + wn * 32 + ni * 8 + t4 * 2;
            float2 bv = *(const float2*)&bias[col];
            float2 v0 = { acc[mi][ni][0] + bv.x, acc[mi][ni][1] + bv.y };
            float2 v1 = { acc[mi][ni][2] + bv.x, acc[mi][ni][3] + bv.y };
            *(float2*)&out[(size_t)r0       * VV + col] = v0;
            *(float2*)&out[(size_t)(r0 + 8) * VV + col] = v1;
        }
    }
}

// ---------------------------------------------------------------------------
// 5) online log-softmax -> per-row loss; 6) final mean
// ---------------------------------------------------------------------------
__global__ void k_softmax(const float* __restrict__ logits,
                          const int* __restrict__ targets) {
    __shared__ float sm[256], ss[256];
    int t = blockIdx.x, tid = threadIdx.x;
    const float* row = logits + (size_t)t * VV;
    float m = -INFINITY, s = 0.f;
    for (int c = tid * 4; c < VV; c += 1024) {
        float4 v = *(const float4*)&row[c];
        float vm = fmaxf(fmaxf(v.x, v.y), fmaxf(v.z, v.w));
        float nm = fmaxf(m, vm);
        s = s * __expf(m - nm) + __expf(v.x - nm) + __expf(v.y - nm)
          + __expf(v.z - nm) + __expf(v.w - nm);
        m = nm;
    }
    sm[tid] = m; ss[tid] = s; __syncthreads();
    for (int st = 128; st; st >>= 1) {
        if (tid < st) {
            float m2 = fmaxf(sm[tid], sm[tid + st]);
            ss[tid] = ss[tid] * __expf(sm[tid] - m2) + ss[tid + st] * __expf(sm[tid + st] - m2);
            sm[tid] = m2;
        }
        __syncthreads();
    }
    if (tid == 0)
        g_rowloss[t] = row[targets[t]] - sm[0] - logf(ss[0]);
}

__global__ void k_loss(float* __restrict__ out) {
    __shared__ float red[256];
    int tid = threadIdx.x;
    float s = 0.f;
    for (int t = tid; t < TT; t += 256) s += g_rowloss[t];
    red[tid] = s; __syncthreads();
    for (int st = 128; st; st >>= 1) { if (tid < st) red[tid] += red[tid+st]; __syncthreads(); }
    if (tid == 0) out[0] = -red[0] / (float)TT;
}

// ---------------------------------------------------------------------------
extern "C" void kernel_launch(void* const* d_in, const int* in_sizes, int n_in,
                              void* d_out, int out_size) {
    const int*   tokens  = (const int*)  d_in[0];
    const int*   targets = (const int*)  d_in[1];
    const float* embed   = (const float*)d_in[2];
    const float* fw_init = (const float*)d_in[3];
    const float* eta     = (const float*)d_in[4];
    const float* wa      = (const float*)d_in[5];
    const float* wb      = (const float*)d_in[6];
    const float* mlp_aw  = (const float*)d_in[7];
    const float* mlp_ab  = (const float*)d_in[8];
    const float* mlp_bw  = (const float*)d_in[9];
    const float* mlp_bb  = (const float*)d_in[10];
    const float* head_w  = (const float*)d_in[11];
    const float* head_b  = (const float*)d_in[12];
    float* out = (float*)d_out;

    static int smem_set = 0;
    if (!smem_set) {
        cudaFuncSetAttribute(k_head, cudaFuncAttributeMaxDynamicSharedMemorySize, HEAD_SMEM);
        smem_set = 1;
    }

    k_prep<<<4000 + (TT*DD + 255) / 256, 256>>>(tokens, embed, head_w);
    k_zgemm<<<dim3(DD/64, TT/64), 256>>>(wa, wb);
    k_scanmlp<<<DD/4, 128>>>(fw_init, eta, mlp_aw, mlp_ab, mlp_bw, mlp_bb);
    k_head<<<dim3(TT/128, VV/128), 512, HEAD_SMEM>>>(head_b, out);   // captured by ncu (slot 4)
    k_softmax<<<TT, 256>>>(out, targets);
    if (out_size >= TT*VV + 1)
        k_loss<<<1, 256>>>(out + (size_t)TT*VV);
}

// round 8
// speedup vs baseline: 3.4073x; 2.2359x over previous
#include <cuda_runtime.h>
#include <cuda_bf16.h>
#include <math.h>
#include <stdint.h>

#define DD 512
#define HH 20
#define VV 32000
#define TT 1024

// Scratch (allocation-free rule: __device__ globals)
__device__ float g_X [TT*DD];
__device__ float g_Z0[TT*DD];
__device__ float g_Z1[TT*DD];
__device__ float g_Y [TT*DD];
__device__ float g_rowloss[TT];
// Chunk-major, pre-swizzled bf16 hi/lo operands for the head GEMM.
// Element (row, k): g = ((kc*ROWS + row)*64 + kk)*2, stored at g ^ ((g>>3)&0x70).
__device__ __nv_bfloat16 g_Ahic[TT*DD];
__device__ __nv_bfloat16 g_Aloc[TT*DD];
__device__ __nv_bfloat16 g_Bhic[(size_t)VV*DD];
__device__ __nv_bfloat16 g_Bloc[(size_t)VV*DD];

// ---------------------------------------------------------------------------
// PTX helpers
// ---------------------------------------------------------------------------
__device__ __forceinline__ uint32_t smem_u32(const void* p) {
    uint32_t a;
    asm("{ .reg .u64 t; cvta.to.shared.u64 t, %1; cvt.u32.u64 %0, t; }" : "=r"(a) : "l"(p));
    return a;
}
#define MBAR_INIT(a, c) asm volatile("mbarrier.init.shared.b64 [%0], %1;" :: "r"(a), "r"(c) : "memory")
#define MBAR_EXPECT_TX(a, b) \
    asm volatile("mbarrier.arrive.expect_tx.shared.b64 _, [%0], %1;" :: "r"(a), "r"(b) : "memory")
__device__ __forceinline__ void mbar_wait(uint32_t mbar, uint32_t parity) {
    uint32_t done;
    asm volatile("{ .reg .pred p; mbarrier.try_wait.parity.acquire.cta.shared::cta.b64 p, [%1], %2; selp.b32 %0,1,0,p; }"
                 : "=r"(done) : "r"(mbar), "r"(parity) : "memory");
    if (!done) {
        asm volatile("{ .reg .pred P1;\nWL_%=:\n"
                     "mbarrier.try_wait.parity.acquire.cta.shared::cta.b64 P1, [%0], %1, 0x989680;\n"
                     "@P1 bra.uni WD_%=;\n bra.uni WL_%=;\nWD_%=:\n}"
                     :: "r"(mbar), "r"(parity) : "memory");
    }
}
__device__ __forceinline__ void bulk_cp(uint32_t dst, const void* gsrc,
                                        uint32_t bytes, uint32_t mbar) {
    asm volatile("cp.async.bulk.shared::cluster.global.mbarrier::complete_tx::bytes [%0], [%1], %2, [%3];"
                 :: "r"(dst), "l"(__cvta_generic_to_global(gsrc)), "r"(bytes), "r"(mbar) : "memory");
}
__device__ __forceinline__ void ldsm4(unsigned r[4], uint32_t addr) {
    asm volatile("ldmatrix.sync.aligned.m8n8.x4.shared.b16 {%0,%1,%2,%3}, [%4];"
                 : "=r"(r[0]), "=r"(r[1]), "=r"(r[2]), "=r"(r[3]) : "r"(addr));
}
__device__ __forceinline__ void mma16816(float c[4], const unsigned a[4], const unsigned b[2]) {
    asm volatile(
        "mma.sync.aligned.m16n8k16.row.col.f32.bf16.bf16.f32 "
        "{%0,%1,%2,%3}, {%4,%5,%6,%7}, {%8,%9}, {%0,%1,%2,%3};\n"
        : "+f"(c[0]), "+f"(c[1]), "+f"(c[2]), "+f"(c[3])
        : "r"(a[0]), "r"(a[1]), "r"(a[2]), "r"(a[3]), "r"(b[0]), "r"(b[1]));
}

// ---------------------------------------------------------------------------
// 1) X = embed[tokens]
// ---------------------------------------------------------------------------
__global__ void k_gather(const int* __restrict__ tokens,
                         const float* __restrict__ embed) {
    int idx = blockIdx.x * blockDim.x + threadIdx.x;
    if (idx < TT * DD) {
        int t = idx >> 9, d = idx & 511;
        g_X[idx] = embed[(size_t)tokens[t] * DD + d];
    }
}

// ---------------------------------------------------------------------------
// 2) head_w -> chunk-major swizzled bf16 hi/lo [kc][n][64]
// ---------------------------------------------------------------------------
__global__ void __launch_bounds__(256) k_convB(const float* __restrict__ W) {
    __shared__ float tile[64][65];
    int n0 = blockIdx.x * 64;
    int k0 = blockIdx.y * 64;
    int tid = threadIdx.x;
    #pragma unroll
    for (int i = 0; i < 16; i++) {
        int f = tid + 256 * i;
        int k = f >> 6, n = f & 63;
        tile[k][n] = W[(size_t)(k0 + k) * VV + n0 + n];
    }
    __syncthreads();
    size_t kc = (size_t)(k0 >> 6);
    char* bh = (char*)g_Bhic;
    char* bl = (char*)g_Bloc;
    #pragma unroll
    for (int i = 0; i < 16; i++) {
        int f = tid + 256 * i;
        int n = f >> 6, kk = f & 63;
        float v = tile[kk][n];
        __nv_bfloat16 hi = __float2bfloat16_rn(v);
        __nv_bfloat16 lo = __float2bfloat16_rn(v - __bfloat162float(hi));
        size_t g = ((kc * VV + (n0 + n)) * 64 + kk) * 2;
        size_t sw = g ^ ((g >> 3) & 0x70);
        *(__nv_bfloat16*)(bh + sw) = hi;
        *(__nv_bfloat16*)(bl + sw) = lo;
    }
}

// ---------------------------------------------------------------------------
// 3) Z0 = X @ wa, Z1 = X @ wb
// ---------------------------------------------------------------------------
__global__ void __launch_bounds__(256) k_zgemm(const float* __restrict__ wa,
                                               const float* __restrict__ wb) {
    __shared__ float Xs [16][64];
    __shared__ float Was[16][64];
    __shared__ float Wbs[16][64];
    int tid = threadIdx.x;
    int n0 = blockIdx.x * 64;
    int m0 = blockIdx.y * 64;
    int ty = tid >> 4, tx = tid & 15;
    float a0[4][4] = {}, a1[4][4] = {};

    for (int k0 = 0; k0 < DD; k0 += 16) {
        {
            int m  = tid >> 2;
            int kq = (tid & 3) * 4;
            float4 v = *(const float4*)&g_X[(size_t)(m0 + m) * DD + k0 + kq];
            Xs[kq+0][m] = v.x; Xs[kq+1][m] = v.y; Xs[kq+2][m] = v.z; Xs[kq+3][m] = v.w;
        }
        {
            int k  = tid >> 4;
            int nq = (tid & 15) * 4;
            *(float4*)&Was[k][nq] = *(const float4*)&wa[(size_t)(k0 + k) * DD + n0 + nq];
            *(float4*)&Wbs[k][nq] = *(const float4*)&wb[(size_t)(k0 + k) * DD + n0 + nq];
        }
        __syncthreads();
        #pragma unroll
        for (int k = 0; k < 16; k++) {
            float xr[4], war[4], wbr[4];
            #pragma unroll
            for (int i = 0; i < 4; i++) xr[i] = Xs[k][ty*4 + i];
            #pragma unroll
            for (int j = 0; j < 4; j++) { war[j] = Was[k][tx*4 + j]; wbr[j] = Wbs[k][tx*4 + j]; }
            #pragma unroll
            for (int i = 0; i < 4; i++)
                #pragma unroll
                for (int j = 0; j < 4; j++) {
                    a0[i][j] = fmaf(xr[i], war[j], a0[i][j]);
                    a1[i][j] = fmaf(xr[i], wbr[j], a1[i][j]);
                }
        }
        __syncthreads();
    }
    #pragma unroll
    for (int i = 0; i < 4; i++) {
        int row = m0 + ty*4 + i;
        #pragma unroll
        for (int j = 0; j < 4; j++) {
            int col = n0 + tx*4 + j;
            g_Z0[(size_t)row * DD + col] = a0[i][j];
            g_Z1[(size_t)row * DD + col] = a1[i][j];
        }
    }
}

// ---------------------------------------------------------------------------
// 4) Scan, re-parallelized: 4 warps per column (2048 warps total).
//    CTA = 256 threads = 8 warps = 2 columns. Warp part p owns rows
//    lane + 32*(4p+g), g=0..3 (fw in 4 regs). Partial y via shfl + smem,
//    one __syncthreads per step, double-buffered partial slots,
//    next-step z0/x/z1 prefetched into registers.
// ---------------------------------------------------------------------------
__global__ void __launch_bounds__(256) k_scan(const float* __restrict__ fw_init,
                                              const float* __restrict__ eta_p) {
    __shared__ float part[2][2][4];   // [t&1][colLocal][part]
    int tid  = threadIdx.x;
    int wid  = tid >> 5;
    int lane = tid & 31;
    int cl   = wid >> 2;              // 0..1 column within CTA
    int pr   = wid & 3;               // 0..3 row-part
    int j    = blockIdx.x * 2 + cl;
    float eta = *eta_p;

    float fw[4];
    #pragma unroll
    for (int g = 0; g < 4; g++)
        fw[g] = fw_init[(size_t)(lane + 32*(pr*4 + g)) * DD + j];

    // prefetch step 0
    float z0p[4], xp[4], z1p;
    #pragma unroll
    for (int g = 0; g < 4; g++) {
        int i = lane + 32*(pr*4 + g);
        z0p[g] = g_Z0[i];
        xp[g]  = g_X [i];
    }
    z1p = g_Z1[j];

    for (int t = 0; t < TT; t++) {
        float z0c[4], xc[4];
        #pragma unroll
        for (int g = 0; g < 4; g++) { z0c[g] = z0p[g]; xc[g] = xp[g]; }
        float p = eta * z1p;

        // prefetch step t+1 (clamped)
        int tn = (t + 1 < TT) ? (t + 1) : t;
        #pragma unroll
        for (int g = 0; g < 4; g++) {
            int i = lane + 32*(pr*4 + g);
            z0p[g] = g_Z0[(size_t)tn * DD + i];
            xp[g]  = g_X [(size_t)tn * DD + i];
        }
        z1p = g_Z1[(size_t)tn * DD + j];

        float yacc = 0.f;
        #pragma unroll
        for (int g = 0; g < 4; g++) {
            float v  = fmaf(z0c[g], p, fw[g]);
            float e  = __expf(v + v);
            float th = 1.f - __fdividef(2.f, e + 1.f);
            fw[g] = th;
            yacc = fmaf(xc[g], th, yacc);
        }
        #pragma unroll
        for (int off = 16; off; off >>= 1)
            yacc += __shfl_xor_sync(0xffffffffu, yacc, off);
        if (lane == 0) part[t & 1][cl][pr] = yacc;
        __syncthreads();
        if (pr == 0 && lane == 0) {
            float y = part[t & 1][cl][0] + part[t & 1][cl][1]
                    + part[t & 1][cl][2] + part[t & 1][cl][3];
            g_Y[(size_t)t * DD + j] = y;
        }
    }
}

// ---------------------------------------------------------------------------
// 5) MLP + mix; epilogue emits chunk-major swizzled bf16 hi/lo of "mixed"
// ---------------------------------------------------------------------------
__global__ void k_mlp(const float* __restrict__ aw, const float* __restrict__ ab,
                      const float* __restrict__ bw, const float* __restrict__ bb) {
    __shared__ float ys[DD];
    __shared__ float hs[HH];
    int t = blockIdx.x, tid = threadIdx.x;
    for (int d = tid; d < DD; d += 256) ys[d] = g_Y[(size_t)t * DD + d];
    __syncthreads();
    int w = tid >> 5, lane = tid & 31;
    for (int u = w; u < HH; u += 8) {
        float acc = 0.f;
        #pragma unroll
        for (int k = 0; k < 16; k++) {
            int d = lane + 32*k;
            acc = fmaf(ys[d], aw[(size_t)d * HH + u], acc);
        }
        #pragma unroll
        for (int off = 16; off; off >>= 1)
            acc += __shfl_xor_sync(0xffffffffu, acc, off);
        if (lane == 0) {
            float hv = acc + ab[u];
            const float SC = 1.0507009873554805f, AL = 1.6732632423543772f;
            hs[u] = hv > 0.f ? SC * hv : SC * AL * expm1f(hv);
        }
    }
    __syncthreads();
    char* ah = (char*)g_Ahic;
    char* al = (char*)g_Aloc;
    for (int j = tid; j < DD; j += 256) {
        float o = bb[j];
        #pragma unroll
        for (int k = 0; k < HH; k++)
            o = fmaf(hs[k], bw[(size_t)k * DD + j], o);
        float mx = 0.5f * o + 0.5f * g_X[(size_t)t * DD + j];
        __nv_bfloat16 hi = __float2bfloat16_rn(mx);
        __nv_bfloat16 lo = __float2bfloat16_rn(mx - __bfloat162float(hi));
        size_t g = (((size_t)(j >> 6) * TT + t) * 64 + (j & 63)) * 2;
        size_t sw = g ^ ((g >> 3) & 0x70);
        *(__nv_bfloat16*)(ah + sw) = hi;
        *(__nv_bfloat16*)(al + sw) = lo;
    }
}

// ---------------------------------------------------------------------------
// 6) Head GEMM (unchanged from R7: 259us, tensor 64%)
// ---------------------------------------------------------------------------
#define TILE_B   16384           // 128 rows x 128 bytes
#define CH_B     (4*TILE_B)      // Ahi, Alo, Bhi, Blo
#define HEAD_SMEM (1024 + 2*CH_B)

__global__ void __launch_bounds__(512, 1) k_head(const float* __restrict__ bias,
                                                 float* __restrict__ out) {
    extern __shared__ __align__(1024) char smem[];
    uint32_t sb = smem_u32(smem);
    int tid  = threadIdx.x;
    int wid  = tid >> 5;
    int lane = tid & 31;
    int grp  = lane >> 2;
    int t4   = lane & 3;
    int m0 = blockIdx.x * 128;
    int n0 = blockIdx.y * 128;
    int wm = wid & 3;
    int wn = wid >> 2;

    if (tid == 0) { MBAR_INIT(sb, 1); MBAR_INIT(sb + 8, 1); }
    __syncthreads();

    const char* gAh = (const char*)g_Ahic;
    const char* gAl = (const char*)g_Aloc;
    const char* gBh = (const char*)g_Bhic;
    const char* gBl = (const char*)g_Bloc;

    auto issue = [&](int c) {
        int buf = c & 1;
        uint32_t mb  = sb + buf * 8;
        uint32_t dst = sb + 1024 + buf * CH_B;
        MBAR_EXPECT_TX(mb, CH_B);
        size_t aoff = ((size_t)c * TT + m0) * 128;
        size_t boff = ((size_t)c * VV + n0) * 128;
        bulk_cp(dst,            gAh + aoff, TILE_B, mb);
        bulk_cp(dst +   TILE_B, gAl + aoff, TILE_B, mb);
        bulk_cp(dst + 2*TILE_B, gBh + boff, TILE_B, mb);
        bulk_cp(dst + 3*TILE_B, gBl + boff, TILE_B, mb);
    };
    if (tid == 0) { issue(0); issue(1); }

    float acc[2][4][4] = {};

    uint32_t aRow  = (uint32_t)(wm*32 + (lane & 15));
    uint32_t aByte = aRow * 128;
    uint32_t aXor  = (aRow & 7) << 4;
    uint32_t aKb   = (uint32_t)((lane >> 4) * 16);
    uint32_t bRow  = (uint32_t)(wn*32 + (lane & 7) + ((lane >> 4) & 1) * 8);
    uint32_t bByte = bRow * 128;
    uint32_t bXor  = (bRow & 7) << 4;
    uint32_t bKb   = (uint32_t)(((lane >> 3) & 1) * 16);

    for (int c = 0; c < 8; c++) {
        mbar_wait(sb + (c & 1) * 8, (c >> 1) & 1);
        uint32_t base = sb + 1024 + (c & 1) * CH_B;
        uint32_t pAh = base;
        uint32_t pAl = base + TILE_B;
        uint32_t pBh = base + 2*TILE_B;
        uint32_t pBl = base + 3*TILE_B;

        #pragma unroll
        for (int ks = 0; ks < 4; ks++) {
            uint32_t ka = ((uint32_t)(ks*32) + aKb) ^ aXor;
            uint32_t kb = ((uint32_t)(ks*32) + bKb) ^ bXor;
            unsigned ah[2][4], al[2][4], bh[4][2], bl[4][2];
            #pragma unroll
            for (int mi = 0; mi < 2; mi++) {
                ldsm4(ah[mi], pAh + aByte + mi*2048 + ka);
                ldsm4(al[mi], pAl + aByte + mi*2048 + ka);
            }
            #pragma unroll
            for (int p = 0; p < 2; p++) {
                unsigned tmp[4];
                ldsm4(tmp, pBh + bByte + p*2048 + kb);
                bh[p*2][0] = tmp[0]; bh[p*2][1] = tmp[1];
                bh[p*2+1][0] = tmp[2]; bh[p*2+1][1] = tmp[3];
                ldsm4(tmp, pBl + bByte + p*2048 + kb);
                bl[p*2][0] = tmp[0]; bl[p*2][1] = tmp[1];
                bl[p*2+1][0] = tmp[2]; bl[p*2+1][1] = tmp[3];
            }
            #pragma unroll
            for (int mi = 0; mi < 2; mi++)
                #pragma unroll
                for (int ni = 0; ni < 4; ni++) {
                    mma16816(acc[mi][ni], ah[mi], bh[ni]);
                    mma16816(acc[mi][ni], ah[mi], bl[ni]);
                    mma16816(acc[mi][ni], al[mi], bh[ni]);
                }
        }
        __syncthreads();
        if (tid == 0 && c + 2 < 8) issue(c + 2);
    }

    #pragma unroll
    for (int mi = 0; mi < 2; mi++) {
        int r0 = m0 + wm * 32 + mi * 16 + grp;
        #pragma unroll
        for (int ni = 0; ni < 4; ni++) {
            int col = n0 + wn * 32 + ni * 8 + t4 * 2;
            float2 bv = *(const float2*)&bias[col];
            float2 v0 = { acc[mi][ni][0] + bv.x, acc[mi][ni][1] + bv.y };
            float2 v1 = { acc[mi][ni][2] + bv.x, acc[mi][ni][3] + bv.y };
            *(float2*)&out[(size_t)r0       * VV + col] = v0;
            *(float2*)&out[(size_t)(r0 + 8) * VV + col] = v1;
        }
    }
}

// ---------------------------------------------------------------------------
// 7) online log-softmax -> per-row loss; 8) final mean
// ---------------------------------------------------------------------------
__global__ void k_softmax(const float* __restrict__ logits,
                          const int* __restrict__ targets) {
    __shared__ float sm[256], ss[256];
    int t = blockIdx.x, tid = threadIdx.x;
    const float* row = logits + (size_t)t * VV;
    float m = -INFINITY, s = 0.f;
    for (int c = tid * 4; c < VV; c += 1024) {
        float4 v = *(const float4*)&row[c];
        float vm = fmaxf(fmaxf(v.x, v.y), fmaxf(v.z, v.w));
        float nm = fmaxf(m, vm);
        s = s * __expf(m - nm) + __expf(v.x - nm) + __expf(v.y - nm)
          + __expf(v.z - nm) + __expf(v.w - nm);
        m = nm;
    }
    sm[tid] = m; ss[tid] = s; __syncthreads();
    for (int st = 128; st; st >>= 1) {
        if (tid < st) {
            float m2 = fmaxf(sm[tid], sm[tid + st]);
            ss[tid] = ss[tid] * __expf(sm[tid] - m2) + ss[tid + st] * __expf(sm[tid + st] - m2);
            sm[tid] = m2;
        }
        __syncthreads();
    }
    if (tid == 0)
        g_rowloss[t] = row[targets[t]] - sm[0] - logf(ss[0]);
}

__global__ void k_loss(float* __restrict__ out) {
    __shared__ float red[256];
    int tid = threadIdx.x;
    float s = 0.f;
    for (int t = tid; t < TT; t += 256) s += g_rowloss[t];
    red[tid] = s; __syncthreads();
    for (int st = 128; st; st >>= 1) { if (tid < st) red[tid] += red[tid+st]; __syncthreads(); }
    if (tid == 0) out[0] = -red[0] / (float)TT;
}

// ---------------------------------------------------------------------------
extern "C" void kernel_launch(void* const* d_in, const int* in_sizes, int n_in,
                              void* d_out, int out_size) {
    const int*   tokens  = (const int*)  d_in[0];
    const int*   targets = (const int*)  d_in[1];
    const float* embed   = (const float*)d_in[2];
    const float* fw_init = (const float*)d_in[3];
    const float* eta     = (const float*)d_in[4];
    const float* wa      = (const float*)d_in[5];
    const float* wb      = (const float*)d_in[6];
    const float* mlp_aw  = (const float*)d_in[7];
    const float* mlp_ab  = (const float*)d_in[8];
    const float* mlp_bw  = (const float*)d_in[9];
    const float* mlp_bb  = (const float*)d_in[10];
    const float* head_w  = (const float*)d_in[11];
    const float* head_b  = (const float*)d_in[12];
    float* out = (float*)d_out;

    static int smem_set = 0;
    if (!smem_set) {
        cudaFuncSetAttribute(k_head, cudaFuncAttributeMaxDynamicSharedMemorySize, HEAD_SMEM);
        smem_set = 1;
    }

    k_gather<<<(TT*DD + 255) / 256, 256>>>(tokens, embed);
    k_convB<<<dim3(VV/64, DD/64), 256>>>(head_w);
    k_zgemm<<<dim3(DD/64, TT/64), 256>>>(wa, wb);
    k_scan<<<DD/2, 256>>>(fw_init, eta);            // ncu slot 4
    k_mlp<<<TT, 256>>>(mlp_aw, mlp_ab, mlp_bw, mlp_bb);
    k_head<<<dim3(TT/128, VV/128), 512, HEAD_SMEM>>>(head_b, out);
    k_softmax<<<TT, 256>>>(out, targets);
    if (out_size >= TT*VV + 1)
        k_loss<<<1, 256>>>(out + (size_t)TT*VV);
}

// round 9
// speedup vs baseline: 3.6663x; 1.0760x over previous
#include <cuda_runtime.h>
#include <cuda_bf16.h>
#include <math.h>
#include <stdint.h>

#define DD 512
#define HH 20
#define VV 32000
#define TT 1024

// Scratch (allocation-free rule: __device__ globals)
__device__ float g_X [TT*DD];
__device__ float g_Z0[TT*DD];
__device__ float g_Z1[TT*DD];
__device__ float g_Y [TT*DD];
__device__ float g_rowloss[TT];
// Chunk-major, pre-swizzled bf16 hi/lo operands for the head GEMM.
// Element (row, k): g = ((kc*ROWS + row)*64 + kk)*2, stored at g ^ ((g>>3)&0x70).
__device__ __nv_bfloat16 g_Ahic[TT*DD];
__device__ __nv_bfloat16 g_Aloc[TT*DD];
__device__ __nv_bfloat16 g_Bhic[(size_t)VV*DD];
__device__ __nv_bfloat16 g_Bloc[(size_t)VV*DD];

// ---------------------------------------------------------------------------
// PTX helpers
// ---------------------------------------------------------------------------
__device__ __forceinline__ uint32_t smem_u32(const void* p) {
    uint32_t a;
    asm("{ .reg .u64 t; cvta.to.shared.u64 t, %1; cvt.u32.u64 %0, t; }" : "=r"(a) : "l"(p));
    return a;
}
#define MBAR_INIT(a, c) asm volatile("mbarrier.init.shared.b64 [%0], %1;" :: "r"(a), "r"(c) : "memory")
#define MBAR_EXPECT_TX(a, b) \
    asm volatile("mbarrier.arrive.expect_tx.shared.b64 _, [%0], %1;" :: "r"(a), "r"(b) : "memory")
__device__ __forceinline__ void mbar_wait(uint32_t mbar, uint32_t parity) {
    uint32_t done;
    asm volatile("{ .reg .pred p; mbarrier.try_wait.parity.acquire.cta.shared::cta.b64 p, [%1], %2; selp.b32 %0,1,0,p; }"
                 : "=r"(done) : "r"(mbar), "r"(parity) : "memory");
    if (!done) {
        asm volatile("{ .reg .pred P1;\nWL_%=:\n"
                     "mbarrier.try_wait.parity.acquire.cta.shared::cta.b64 P1, [%0], %1, 0x989680;\n"
                     "@P1 bra.uni WD_%=;\n bra.uni WL_%=;\nWD_%=:\n}"
                     :: "r"(mbar), "r"(parity) : "memory");
    }
}
__device__ __forceinline__ void bulk_cp(uint32_t dst, const void* gsrc,
                                        uint32_t bytes, uint32_t mbar) {
    asm volatile("cp.async.bulk.shared::cluster.global.mbarrier::complete_tx::bytes [%0], [%1], %2, [%3];"
                 :: "r"(dst), "l"(__cvta_generic_to_global(gsrc)), "r"(bytes), "r"(mbar) : "memory");
}
__device__ __forceinline__ void ldsm4(unsigned r[4], uint32_t addr) {
    asm volatile("ldmatrix.sync.aligned.m8n8.x4.shared.b16 {%0,%1,%2,%3}, [%4];"
                 : "=r"(r[0]), "=r"(r[1]), "=r"(r[2]), "=r"(r[3]) : "r"(addr));
}
__device__ __forceinline__ void mma16816(float c[4], const unsigned a[4], const unsigned b[2]) {
    asm volatile(
        "mma.sync.aligned.m16n8k16.row.col.f32.bf16.bf16.f32 "
        "{%0,%1,%2,%3}, {%4,%5,%6,%7}, {%8,%9}, {%0,%1,%2,%3};\n"
        : "+f"(c[0]), "+f"(c[1]), "+f"(c[2]), "+f"(c[3])
        : "r"(a[0]), "r"(a[1]), "r"(a[2]), "r"(a[3]), "r"(b[0]), "r"(b[1]));
}
__device__ __forceinline__ float tanh_fast(float v) {
    float r;
    asm("tanh.approx.f32 %0, %1;" : "=f"(r) : "f"(v));
    return r;
}

// ---------------------------------------------------------------------------
// 1) X = embed[tokens]
// ---------------------------------------------------------------------------
__global__ void k_gather(const int* __restrict__ tokens,
                         const float* __restrict__ embed) {
    int idx = blockIdx.x * blockDim.x + threadIdx.x;
    if (idx < TT * DD) {
        int t = idx >> 9, d = idx & 511;
        g_X[idx] = embed[(size_t)tokens[t] * DD + d];
    }
}

// ---------------------------------------------------------------------------
// 2) head_w -> chunk-major swizzled bf16 hi/lo [kc][n][64]
// ---------------------------------------------------------------------------
__global__ void __launch_bounds__(256) k_convB(const float* __restrict__ W) {
    __shared__ float tile[64][65];
    int n0 = blockIdx.x * 64;
    int k0 = blockIdx.y * 64;
    int tid = threadIdx.x;
    #pragma unroll
    for (int i = 0; i < 16; i++) {
        int f = tid + 256 * i;
        int k = f >> 6, n = f & 63;
        tile[k][n] = W[(size_t)(k0 + k) * VV + n0 + n];
    }
    __syncthreads();
    size_t kc = (size_t)(k0 >> 6);
    char* bh = (char*)g_Bhic;
    char* bl = (char*)g_Bloc;
    #pragma unroll
    for (int i = 0; i < 16; i++) {
        int f = tid + 256 * i;
        int n = f >> 6, kk = f & 63;
        float v = tile[kk][n];
        __nv_bfloat16 hi = __float2bfloat16_rn(v);
        __nv_bfloat16 lo = __float2bfloat16_rn(v - __bfloat162float(hi));
        size_t g = ((kc * VV + (n0 + n)) * 64 + kk) * 2;
        size_t sw = g ^ ((g >> 3) & 0x70);
        *(__nv_bfloat16*)(bh + sw) = hi;
        *(__nv_bfloat16*)(bl + sw) = lo;
    }
}

// ---------------------------------------------------------------------------
// 3) Z0 = X @ wa, Z1 = X @ wb
// ---------------------------------------------------------------------------
__global__ void __launch_bounds__(256) k_zgemm(const float* __restrict__ wa,
                                               const float* __restrict__ wb) {
    __shared__ float Xs [16][64];
    __shared__ float Was[16][64];
    __shared__ float Wbs[16][64];
    int tid = threadIdx.x;
    int n0 = blockIdx.x * 64;
    int m0 = blockIdx.y * 64;
    int ty = tid >> 4, tx = tid & 15;
    float a0[4][4] = {}, a1[4][4] = {};

    for (int k0 = 0; k0 < DD; k0 += 16) {
        {
            int m  = tid >> 2;
            int kq = (tid & 3) * 4;
            float4 v = *(const float4*)&g_X[(size_t)(m0 + m) * DD + k0 + kq];
            Xs[kq+0][m] = v.x; Xs[kq+1][m] = v.y; Xs[kq+2][m] = v.z; Xs[kq+3][m] = v.w;
        }
        {
            int k  = tid >> 4;
            int nq = (tid & 15) * 4;
            *(float4*)&Was[k][nq] = *(const float4*)&wa[(size_t)(k0 + k) * DD + n0 + nq];
            *(float4*)&Wbs[k][nq] = *(const float4*)&wb[(size_t)(k0 + k) * DD + n0 + nq];
        }
        __syncthreads();
        #pragma unroll
        for (int k = 0; k < 16; k++) {
            float xr[4], war[4], wbr[4];
            #pragma unroll
            for (int i = 0; i < 4; i++) xr[i] = Xs[k][ty*4 + i];
            #pragma unroll
            for (int j = 0; j < 4; j++) { war[j] = Was[k][tx*4 + j]; wbr[j] = Wbs[k][tx*4 + j]; }
            #pragma unroll
            for (int i = 0; i < 4; i++)
                #pragma unroll
                for (int j = 0; j < 4; j++) {
                    a0[i][j] = fmaf(xr[i], war[j], a0[i][j]);
                    a1[i][j] = fmaf(xr[i], wbr[j], a1[i][j]);
                }
        }
        __syncthreads();
    }
    #pragma unroll
    for (int i = 0; i < 4; i++) {
        int row = m0 + ty*4 + i;
        #pragma unroll
        for (int j = 0; j < 4; j++) {
            int col = n0 + tx*4 + j;
            g_Z0[(size_t)row * DD + col] = a0[i][j];
            g_Z1[(size_t)row * DD + col] = a1[i][j];
        }
    }
}

// ---------------------------------------------------------------------------
// 4) Scan v3: 128 CTAs x 512 threads. CTA owns 4 columns, 4 warps/column.
//    tanh via MUFU.TANH (1 op). Reduction batched 8 steps deep:
//    8 independent shfl chains, one __syncthreads per 8 steps,
//    double-buffered partial slots, 32 threads do final sums.
// ---------------------------------------------------------------------------
__global__ void __launch_bounds__(512) k_scan(const float* __restrict__ fw_init,
                                              const float* __restrict__ eta_p) {
    __shared__ float part[2][8][4][4];   // [phase][step][colLocal][part]
    int tid  = threadIdx.x;
    int wid  = tid >> 5;
    int lane = tid & 31;
    int cl   = wid >> 2;              // 0..3 column within CTA
    int pr   = wid & 3;               // 0..3 row-part
    int j0   = blockIdx.x * 4;
    int j    = j0 + cl;
    float eta = *eta_p;

    int i0 = lane + 32 * (pr * 4);    // base row index for this warp
    float fw[4];
    #pragma unroll
    for (int g = 0; g < 4; g++)
        fw[g] = fw_init[(size_t)(i0 + 32*g) * DD + j];

    for (int tb = 0; tb < TT; tb += 8) {
        float yb[8];
        #pragma unroll
        for (int s = 0; s < 8; s++) {
            int t = tb + s;
            const float* z0r = &g_Z0[(size_t)t * DD];
            const float* xr  = &g_X [(size_t)t * DD];
            float p = eta * __ldg(&g_Z1[(size_t)t * DD + j]);
            float y = 0.f;
            #pragma unroll
            for (int g = 0; g < 4; g++) {
                int i = i0 + 32*g;
                float v  = fmaf(z0r[i], p, fw[g]);
                float th = tanh_fast(v);
                fw[g] = th;
                y = fmaf(xr[i], th, y);
            }
            yb[s] = y;
        }
        // 8 independent butterfly reductions (latency-pipelined)
        #pragma unroll
        for (int off = 16; off; off >>= 1)
            #pragma unroll
            for (int s = 0; s < 8; s++)
                yb[s] += __shfl_xor_sync(0xffffffffu, yb[s], off);
        int ph = (tb >> 3) & 1;
        if (lane == 0) {
            #pragma unroll
            for (int s = 0; s < 8; s++)
                part[ph][s][cl][pr] = yb[s];
        }
        __syncthreads();
        if (tid < 32) {
            int s = tid >> 2, c = tid & 3;
            float y = part[ph][s][c][0] + part[ph][s][c][1]
                    + part[ph][s][c][2] + part[ph][s][c][3];
            g_Y[(size_t)(tb + s) * DD + j0 + c] = y;
        }
    }
}

// ---------------------------------------------------------------------------
// 5) MLP + mix; epilogue emits chunk-major swizzled bf16 hi/lo of "mixed"
// ---------------------------------------------------------------------------
__global__ void k_mlp(const float* __restrict__ aw, const float* __restrict__ ab,
                      const float* __restrict__ bw, const float* __restrict__ bb) {
    __shared__ float ys[DD];
    __shared__ float hs[HH];
    int t = blockIdx.x, tid = threadIdx.x;
    for (int d = tid; d < DD; d += 256) ys[d] = g_Y[(size_t)t * DD + d];
    __syncthreads();
    int w = tid >> 5, lane = tid & 31;
    for (int u = w; u < HH; u += 8) {
        float acc = 0.f;
        #pragma unroll
        for (int k = 0; k < 16; k++) {
            int d = lane + 32*k;
            acc = fmaf(ys[d], aw[(size_t)d * HH + u], acc);
        }
        #pragma unroll
        for (int off = 16; off; off >>= 1)
            acc += __shfl_xor_sync(0xffffffffu, acc, off);
        if (lane == 0) {
            float hv = acc + ab[u];
            const float SC = 1.0507009873554805f, AL = 1.6732632423543772f;
            hs[u] = hv > 0.f ? SC * hv : SC * AL * expm1f(hv);
        }
    }
    __syncthreads();
    char* ah = (char*)g_Ahic;
    char* al = (char*)g_Aloc;
    for (int j = tid; j < DD; j += 256) {
        float o = bb[j];
        #pragma unroll
        for (int k = 0; k < HH; k++)
            o = fmaf(hs[k], bw[(size_t)k * DD + j], o);
        float mx = 0.5f * o + 0.5f * g_X[(size_t)t * DD + j];
        __nv_bfloat16 hi = __float2bfloat16_rn(mx);
        __nv_bfloat16 lo = __float2bfloat16_rn(mx - __bfloat162float(hi));
        size_t g = (((size_t)(j >> 6) * TT + t) * 64 + (j & 63)) * 2;
        size_t sw = g ^ ((g >> 3) & 0x70);
        *(__nv_bfloat16*)(ah + sw) = hi;
        *(__nv_bfloat16*)(al + sw) = lo;
    }
}

// ---------------------------------------------------------------------------
// 6) Head GEMM (R7 design: 259us under ncu, tensor 64%)
// ---------------------------------------------------------------------------
#define TILE_B   16384           // 128 rows x 128 bytes
#define CH_B     (4*TILE_B)      // Ahi, Alo, Bhi, Blo
#define HEAD_SMEM (1024 + 2*CH_B)

__global__ void __launch_bounds__(512, 1) k_head(const float* __restrict__ bias,
                                                 float* __restrict__ out) {
    extern __shared__ __align__(1024) char smem[];
    uint32_t sb = smem_u32(smem);
    int tid  = threadIdx.x;
    int wid  = tid >> 5;
    int lane = tid & 31;
    int grp  = lane >> 2;
    int t4   = lane & 3;
    int m0 = blockIdx.x * 128;
    int n0 = blockIdx.y * 128;
    int wm = wid & 3;
    int wn = wid >> 2;

    if (tid == 0) { MBAR_INIT(sb, 1); MBAR_INIT(sb + 8, 1); }
    __syncthreads();

    const char* gAh = (const char*)g_Ahic;
    const char* gAl = (const char*)g_Aloc;
    const char* gBh = (const char*)g_Bhic;
    const char* gBl = (const char*)g_Bloc;

    auto issue = [&](int c) {
        int buf = c & 1;
        uint32_t mb  = sb + buf * 8;
        uint32_t dst = sb + 1024 + buf * CH_B;
        MBAR_EXPECT_TX(mb, CH_B);
        size_t aoff = ((size_t)c * TT + m0) * 128;
        size_t boff = ((size_t)c * VV + n0) * 128;
        bulk_cp(dst,            gAh + aoff, TILE_B, mb);
        bulk_cp(dst +   TILE_B, gAl + aoff, TILE_B, mb);
        bulk_cp(dst + 2*TILE_B, gBh + boff, TILE_B, mb);
        bulk_cp(dst + 3*TILE_B, gBl + boff, TILE_B, mb);
    };
    if (tid == 0) { issue(0); issue(1); }

    float acc[2][4][4] = {};

    uint32_t aRow  = (uint32_t)(wm*32 + (lane & 15));
    uint32_t aByte = aRow * 128;
    uint32_t aXor  = (aRow & 7) << 4;
    uint32_t aKb   = (uint32_t)((lane >> 4) * 16);
    uint32_t bRow  = (uint32_t)(wn*32 + (lane & 7) + ((lane >> 4) & 1) * 8);
    uint32_t bByte = bRow * 128;
    uint32_t bXor  = (bRow & 7) << 4;
    uint32_t bKb   = (uint32_t)(((lane >> 3) & 1) * 16);

    for (int c = 0; c < 8; c++) {
        mbar_wait(sb + (c & 1) * 8, (c >> 1) & 1);
        uint32_t base = sb + 1024 + (c & 1) * CH_B;
        uint32_t pAh = base;
        uint32_t pAl = base + TILE_B;
        uint32_t pBh = base + 2*TILE_B;
        uint32_t pBl = base + 3*TILE_B;

        #pragma unroll
        for (int ks = 0; ks < 4; ks++) {
            uint32_t ka = ((uint32_t)(ks*32) + aKb) ^ aXor;
            uint32_t kb = ((uint32_t)(ks*32) + bKb) ^ bXor;
            unsigned ah[2][4], al[2][4], bh[4][2], bl[4][2];
            #pragma unroll
            for (int mi = 0; mi < 2; mi++) {
                ldsm4(ah[mi], pAh + aByte + mi*2048 + ka);
                ldsm4(al[mi], pAl + aByte + mi*2048 + ka);
            }
            #pragma unroll
            for (int p = 0; p < 2; p++) {
                unsigned tmp[4];
                ldsm4(tmp, pBh + bByte + p*2048 + kb);
                bh[p*2][0] = tmp[0]; bh[p*2][1] = tmp[1];
                bh[p*2+1][0] = tmp[2]; bh[p*2+1][1] = tmp[3];
                ldsm4(tmp, pBl + bByte + p*2048 + kb);
                bl[p*2][0] = tmp[0]; bl[p*2][1] = tmp[1];
                bl[p*2+1][0] = tmp[2]; bl[p*2+1][1] = tmp[3];
            }
            #pragma unroll
            for (int mi = 0; mi < 2; mi++)
                #pragma unroll
                for (int ni = 0; ni < 4; ni++) {
                    mma16816(acc[mi][ni], ah[mi], bh[ni]);
                    mma16816(acc[mi][ni], ah[mi], bl[ni]);
                    mma16816(acc[mi][ni], al[mi], bh[ni]);
                }
        }
        __syncthreads();
        if (tid == 0 && c + 2 < 8) issue(c + 2);
    }

    #pragma unroll
    for (int mi = 0; mi < 2; mi++) {
        int r0 = m0 + wm * 32 + mi * 16 + grp;
        #pragma unroll
        for (int ni = 0; ni < 4; ni++) {
            int col = n0 + wn * 32 + ni * 8 + t4 * 2;
            float2 bv = *(const float2*)&bias[col];
            float2 v0 = { acc[mi][ni][0] + bv.x, acc[mi][ni][1] + bv.y };
            float2 v1 = { acc[mi][ni][2] + bv.x, acc[mi][ni][3] + bv.y };
            *(float2*)&out[(size_t)r0       * VV + col] = v0;
            *(float2*)&out[(size_t)(r0 + 8) * VV + col] = v1;
        }
    }
}

// ---------------------------------------------------------------------------
// 7) online log-softmax -> per-row loss; 8) final mean
// ---------------------------------------------------------------------------
__global__ void k_softmax(const float* __restrict__ logits,
                          const int* __restrict__ targets) {
    __shared__ float sm[256], ss[256];
    int t = blockIdx.x, tid = threadIdx.x;
    const float* row = logits + (size_t)t * VV;
    float m = -INFINITY, s = 0.f;
    for (int c = tid * 4; c < VV; c += 1024) {
        float4 v = *(const float4*)&row[c];
        float vm = fmaxf(fmaxf(v.x, v.y), fmaxf(v.z, v.w));
        float nm = fmaxf(m, vm);
        s = s * __expf(m - nm) + __expf(v.x - nm) + __expf(v.y - nm)
          + __expf(v.z - nm) + __expf(v.w - nm);
        m = nm;
    }
    sm[tid] = m; ss[tid] = s; __syncthreads();
    for (int st = 128; st; st >>= 1) {
        if (tid < st) {
            float m2 = fmaxf(sm[tid], sm[tid + st]);
            ss[tid] = ss[tid] * __expf(sm[tid] - m2) + ss[tid + st] * __expf(sm[tid + st] - m2);
            sm[tid] = m2;
        }
        __syncthreads();
    }
    if (tid == 0)
        g_rowloss[t] = row[targets[t]] - sm[0] - logf(ss[0]);
}

__global__ void k_loss(float* __restrict__ out) {
    __shared__ float red[256];
    int tid = threadIdx.x;
    float s = 0.f;
    for (int t = tid; t < TT; t += 256) s += g_rowloss[t];
    red[tid] = s; __syncthreads();
    for (int st = 128; st; st >>= 1) { if (tid < st) red[tid] += red[tid+st]; __syncthreads(); }
    if (tid == 0) out[0] = -red[0] / (float)TT;
}

// ---------------------------------------------------------------------------
extern "C" void kernel_launch(void* const* d_in, const int* in_sizes, int n_in,
                              void* d_out, int out_size) {
    const int*   tokens  = (const int*)  d_in[0];
    const int*   targets = (const int*)  d_in[1];
    const float* embed   = (const float*)d_in[2];
    const float* fw_init = (const float*)d_in[3];
    const float* eta     = (const float*)d_in[4];
    const float* wa      = (const float*)d_in[5];
    const float* wb      = (const float*)d_in[6];
    const float* mlp_aw  = (const float*)d_in[7];
    const float* mlp_ab  = (const float*)d_in[8];
    const float* mlp_bw  = (const float*)d_in[9];
    const float* mlp_bb  = (const float*)d_in[10];
    const float* head_w  = (const float*)d_in[11];
    const float* head_b  = (const float*)d_in[12];
    float* out = (float*)d_out;

    static int smem_set = 0;
    if (!smem_set) {
        cudaFuncSetAttribute(k_head, cudaFuncAttributeMaxDynamicSharedMemorySize, HEAD_SMEM);
        smem_set = 1;
    }

    k_gather<<<(TT*DD + 255) / 256, 256>>>(tokens, embed);
    k_convB<<<dim3(VV/64, DD/64), 256>>>(head_w);
    k_zgemm<<<dim3(DD/64, TT/64), 256>>>(wa, wb);
    k_scan<<<DD/4, 512>>>(fw_init, eta);            // ncu slot 4
    k_mlp<<<TT, 256>>>(mlp_aw, mlp_ab, mlp_bw, mlp_bb);
    k_head<<<dim3(TT/128, VV/128), 512, HEAD_SMEM>>>(head_b, out);
    k_softmax<<<TT, 256>>>(out, targets);
    if (out_size >= TT*VV + 1)
        k_loss<<<1, 256>>>(out + (size_t)TT*VV);
}

// round 11
// speedup vs baseline: 4.9548x; 1.3514x over previous
#include <cuda_runtime.h>
#include <cuda_bf16.h>
#include <math.h>
#include <stdint.h>

#define DD 512
#define HH 20
#define VV 32000
#define TT 1024

// Scratch (allocation-free rule: __device__ globals)
__device__ float g_X [TT*DD];
__device__ float g_Z0[TT*DD];
__device__ float g_Z1[TT*DD];
__device__ float g_Y [TT*DD];
__device__ float g_rowloss[TT];
// Chunk-major, pre-swizzled bf16 hi/lo operands for the head GEMM.
// Element (row, k): g = ((kc*ROWS + row)*64 + kk)*2, stored at g ^ ((g>>3)&0x70).
__device__ __nv_bfloat16 g_Ahic[TT*DD];
__device__ __nv_bfloat16 g_Aloc[TT*DD];
__device__ __nv_bfloat16 g_Bhic[(size_t)VV*DD];
__device__ __nv_bfloat16 g_Bloc[(size_t)VV*DD];

// ---------------------------------------------------------------------------
// PTX helpers
// ---------------------------------------------------------------------------
__device__ __forceinline__ uint32_t smem_u32(const void* p) {
    uint32_t a;
    asm("{ .reg .u64 t; cvta.to.shared.u64 t, %1; cvt.u32.u64 %0, t; }" : "=r"(a) : "l"(p));
    return a;
}
#define MBAR_INIT(a, c) asm volatile("mbarrier.init.shared.b64 [%0], %1;" :: "r"(a), "r"(c) : "memory")
#define MBAR_EXPECT_TX(a, b) \
    asm volatile("mbarrier.arrive.expect_tx.shared.b64 _, [%0], %1;" :: "r"(a), "r"(b) : "memory")
__device__ __forceinline__ void mbar_wait(uint32_t mbar, uint32_t parity) {
    uint32_t done;
    asm volatile("{ .reg .pred p; mbarrier.try_wait.parity.acquire.cta.shared::cta.b64 p, [%1], %2; selp.b32 %0,1,0,p; }"
                 : "=r"(done) : "r"(mbar), "r"(parity) : "memory");
    if (!done) {
        asm volatile("{ .reg .pred P1;\nWL_%=:\n"
                     "mbarrier.try_wait.parity.acquire.cta.shared::cta.b64 P1, [%0], %1, 0x989680;\n"
                     "@P1 bra.uni WD_%=;\n bra.uni WL_%=;\nWD_%=:\n}"
                     :: "r"(mbar), "r"(parity) : "memory");
    }
}
__device__ __forceinline__ void bulk_cp(uint32_t dst, const void* gsrc,
                                        uint32_t bytes, uint32_t mbar) {
    asm volatile("cp.async.bulk.shared::cluster.global.mbarrier::complete_tx::bytes [%0], [%1], %2, [%3];"
                 :: "r"(dst), "l"(__cvta_generic_to_global(gsrc)), "r"(bytes), "r"(mbar) : "memory");
}
__device__ __forceinline__ void ldsm4(unsigned r[4], uint32_t addr) {
    asm volatile("ldmatrix.sync.aligned.m8n8.x4.shared.b16 {%0,%1,%2,%3}, [%4];"
                 : "=r"(r[0]), "=r"(r[1]), "=r"(r[2]), "=r"(r[3]) : "r"(addr));
}
__device__ __forceinline__ void mma16816(float c[4], const unsigned a[4], const unsigned b[2]) {
    asm volatile(
        "mma.sync.aligned.m16n8k16.row.col.f32.bf16.bf16.f32 "
        "{%0,%1,%2,%3}, {%4,%5,%6,%7}, {%8,%9}, {%0,%1,%2,%3};\n"
        : "+f"(c[0]), "+f"(c[1]), "+f"(c[2]), "+f"(c[3])
        : "r"(a[0]), "r"(a[1]), "r"(a[2]), "r"(a[3]), "r"(b[0]), "r"(b[1]));
}
__device__ __forceinline__ float tanh_fast(float v) {
    float r;
    asm("tanh.approx.f32 %0, %1;" : "=f"(r) : "f"(v));
    return r;
}

// ---------------------------------------------------------------------------
// 1) X = embed[tokens]
// ---------------------------------------------------------------------------
__global__ void k_gather(const int* __restrict__ tokens,
                         const float* __restrict__ embed) {
    int idx = blockIdx.x * blockDim.x + threadIdx.x;
    if (idx < TT * DD) {
        int t = idx >> 9, d = idx & 511;
        g_X[idx] = embed[(size_t)tokens[t] * DD + d];
    }
}

// ---------------------------------------------------------------------------
// 2) head_w -> chunk-major swizzled bf16 hi/lo [kc][n][64]
// ---------------------------------------------------------------------------
__global__ void __launch_bounds__(256) k_convB(const float* __restrict__ W) {
    __shared__ float tile[64][65];
    int n0 = blockIdx.x * 64;
    int k0 = blockIdx.y * 64;
    int tid = threadIdx.x;
    #pragma unroll
    for (int i = 0; i < 16; i++) {
        int f = tid + 256 * i;
        int k = f >> 6, n = f & 63;
        tile[k][n] = W[(size_t)(k0 + k) * VV + n0 + n];
    }
    __syncthreads();
    size_t kc = (size_t)(k0 >> 6);
    char* bh = (char*)g_Bhic;
    char* bl = (char*)g_Bloc;
    #pragma unroll
    for (int i = 0; i < 16; i++) {
        int f = tid + 256 * i;
        int n = f >> 6, kk = f & 63;
        float v = tile[kk][n];
        __nv_bfloat16 hi = __float2bfloat16_rn(v);
        __nv_bfloat16 lo = __float2bfloat16_rn(v - __bfloat162float(hi));
        size_t g = ((kc * VV + (n0 + n)) * 64 + kk) * 2;
        size_t sw = g ^ ((g >> 3) & 0x70);
        *(__nv_bfloat16*)(bh + sw) = hi;
        *(__nv_bfloat16*)(bl + sw) = lo;
    }
}

// ---------------------------------------------------------------------------
// 3) Z0 = X @ wa, Z1 = X @ wb
// ---------------------------------------------------------------------------
__global__ void __launch_bounds__(256) k_zgemm(const float* __restrict__ wa,
                                               const float* __restrict__ wb) {
    __shared__ float Xs [16][64];
    __shared__ float Was[16][64];
    __shared__ float Wbs[16][64];
    int tid = threadIdx.x;
    int n0 = blockIdx.x * 64;
    int m0 = blockIdx.y * 64;
    int ty = tid >> 4, tx = tid & 15;
    float a0[4][4] = {}, a1[4][4] = {};

    for (int k0 = 0; k0 < DD; k0 += 16) {
        {
            int m  = tid >> 2;
            int kq = (tid & 3) * 4;
            float4 v = *(const float4*)&g_X[(size_t)(m0 + m) * DD + k0 + kq];
            Xs[kq+0][m] = v.x; Xs[kq+1][m] = v.y; Xs[kq+2][m] = v.z; Xs[kq+3][m] = v.w;
        }
        {
            int k  = tid >> 4;
            int nq = (tid & 15) * 4;
            *(float4*)&Was[k][nq] = *(const float4*)&wa[(size_t)(k0 + k) * DD + n0 + nq];
            *(float4*)&Wbs[k][nq] = *(const float4*)&wb[(size_t)(k0 + k) * DD + n0 + nq];
        }
        __syncthreads();
        #pragma unroll
        for (int k = 0; k < 16; k++) {
            float xr[4], war[4], wbr[4];
            #pragma unroll
            for (int i = 0; i < 4; i++) xr[i] = Xs[k][ty*4 + i];
            #pragma unroll
            for (int j = 0; j < 4; j++) { war[j] = Was[k][tx*4 + j]; wbr[j] = Wbs[k][tx*4 + j]; }
            #pragma unroll
            for (int i = 0; i < 4; i++)
                #pragma unroll
                for (int j = 0; j < 4; j++) {
                    a0[i][j] = fmaf(xr[i], war[j], a0[i][j]);
                    a1[i][j] = fmaf(xr[i], wbr[j], a1[i][j]);
                }
        }
        __syncthreads();
    }
    #pragma unroll
    for (int i = 0; i < 4; i++) {
        int row = m0 + ty*4 + i;
        #pragma unroll
        for (int j = 0; j < 4; j++) {
            int col = n0 + tx*4 + j;
            g_Z0[(size_t)row * DD + col] = a0[i][j];
            g_Z1[(size_t)row * DD + col] = a1[i][j];
        }
    }
}

// ---------------------------------------------------------------------------
// 4) Scan v4b: 128 CTAs x 512 threads, 4 cols/CTA, 4 warps/col.
//    z0/x rows for 8 consecutive steps staged via double-buffered
//    cp.async.bulk; consumers use LDS.128. Header region [0,2048):
//    mbarriers at [0,16), partial slots at [64,1088). Staging at [2048,...)
//    (R10 bug: partials overlapped staging buffer 0 — fixed).
// ---------------------------------------------------------------------------
#define SC_STEPS 8
#define SC_HALF  (SC_STEPS*DD*4)          // 16KB: 8 steps of one array
#define SC_BUF   (2*SC_HALF)              // 32KB: z0 + x
#define SC_STAGE0 2048                    // staging base offset
#define SC_SMEM  (SC_STAGE0 + 2*SC_BUF)   // 2048 + 64KB

__global__ void __launch_bounds__(512) k_scan(const float* __restrict__ fw_init,
                                              const float* __restrict__ eta_p) {
    extern __shared__ __align__(1024) char smem[];
    uint32_t sb = smem_u32(smem);
    float (*part)[8][4][4] = (float (*)[8][4][4])(smem + 64);  // [64,1088)

    int tid  = threadIdx.x;
    int wid  = tid >> 5;
    int lane = tid & 31;
    int cl   = wid >> 2;              // 0..3 column within CTA
    int pr   = wid & 3;               // 0..3 row-part
    int j0   = blockIdx.x * 4;
    int j    = j0 + cl;
    float eta = *eta_p;

    if (tid == 0) { MBAR_INIT(sb, 1); MBAR_INIT(sb + 8, 1); }
    __syncthreads();

    auto issue = [&](int b) {        // stage 8-step block b into buffer b&1
        uint32_t mb  = sb + (b & 1) * 8;
        uint32_t dst = sb + SC_STAGE0 + (b & 1) * SC_BUF;
        MBAR_EXPECT_TX(mb, SC_BUF);
        bulk_cp(dst,           g_Z0 + (size_t)b * SC_STEPS * DD, SC_HALF, mb);
        bulk_cp(dst + SC_HALF, g_X  + (size_t)b * SC_STEPS * DD, SC_HALF, mb);
    };
    if (tid == 0) { issue(0); issue(1); }

    int iL = pr * 128 + lane * 4;     // this lane's 4 consecutive rows
    float fw[4];
    #pragma unroll
    for (int g = 0; g < 4; g++)
        fw[g] = fw_init[(size_t)(iL + g) * DD + j];

    const int NB = TT / SC_STEPS;     // 128 blocks
    for (int b = 0; b < NB; b++) {
        int tb = b * SC_STEPS;
        // prefetch z1 for the whole block (independent scalar LDGs)
        float z1b[SC_STEPS];
        #pragma unroll
        for (int s = 0; s < SC_STEPS; s++)
            z1b[s] = __ldg(&g_Z1[(size_t)(tb + s) * DD + j]);

        mbar_wait(sb + (b & 1) * 8, (b >> 1) & 1);
        uint32_t base = sb + SC_STAGE0 + (b & 1) * SC_BUF;

        float yb[SC_STEPS];
        #pragma unroll
        for (int s = 0; s < SC_STEPS; s++) {
            float4 z0v, xv;
            asm volatile("ld.shared.v4.f32 {%0,%1,%2,%3}, [%4];"
                         : "=f"(z0v.x), "=f"(z0v.y), "=f"(z0v.z), "=f"(z0v.w)
                         : "r"(base + (uint32_t)(s * DD + iL) * 4));
            asm volatile("ld.shared.v4.f32 {%0,%1,%2,%3}, [%4];"
                         : "=f"(xv.x), "=f"(xv.y), "=f"(xv.z), "=f"(xv.w)
                         : "r"(base + SC_HALF + (uint32_t)(s * DD + iL) * 4));
            float p = eta * z1b[s];
            float t0 = tanh_fast(fmaf(z0v.x, p, fw[0]));
            float t1 = tanh_fast(fmaf(z0v.y, p, fw[1]));
            float t2 = tanh_fast(fmaf(z0v.z, p, fw[2]));
            float t3 = tanh_fast(fmaf(z0v.w, p, fw[3]));
            fw[0] = t0; fw[1] = t1; fw[2] = t2; fw[3] = t3;
            yb[s] = fmaf(xv.x, t0, fmaf(xv.y, t1, fmaf(xv.z, t2, xv.w * t3)));
        }
        // 8 independent butterfly reductions (latency-pipelined)
        #pragma unroll
        for (int off = 16; off; off >>= 1)
            #pragma unroll
            for (int s = 0; s < SC_STEPS; s++)
                yb[s] += __shfl_xor_sync(0xffffffffu, yb[s], off);
        int ph = b & 1;
        if (lane == 0) {
            #pragma unroll
            for (int s = 0; s < SC_STEPS; s++)
                part[ph][s][cl][pr] = yb[s];
        }
        __syncthreads();              // partials ready AND buffer b&1 free
        if (tid == 0 && b + 2 < NB) issue(b + 2);
        if (tid < 32) {
            int s = tid >> 2, c = tid & 3;
            float y = part[ph][s][c][0] + part[ph][s][c][1]
                    + part[ph][s][c][2] + part[ph][s][c][3];
            g_Y[(size_t)(tb + s) * DD + j0 + c] = y;
        }
    }
}

// ---------------------------------------------------------------------------
// 5) MLP + mix; epilogue emits chunk-major swizzled bf16 hi/lo of "mixed"
// ---------------------------------------------------------------------------
__global__ void k_mlp(const float* __restrict__ aw, const float* __restrict__ ab,
                      const float* __restrict__ bw, const float* __restrict__ bb) {
    __shared__ float ys[DD];
    __shared__ float hs[HH];
    int t = blockIdx.x, tid = threadIdx.x;
    for (int d = tid; d < DD; d += 256) ys[d] = g_Y[(size_t)t * DD + d];
    __syncthreads();
    int w = tid >> 5, lane = tid & 31;
    for (int u = w; u < HH; u += 8) {
        float acc = 0.f;
        #pragma unroll
        for (int k = 0; k < 16; k++) {
            int d = lane + 32*k;
            acc = fmaf(ys[d], aw[(size_t)d * HH + u], acc);
        }
        #pragma unroll
        for (int off = 16; off; off >>= 1)
            acc += __shfl_xor_sync(0xffffffffu, acc, off);
        if (lane == 0) {
            float hv = acc + ab[u];
            const float SC = 1.0507009873554805f, AL = 1.6732632423543772f;
            hs[u] = hv > 0.f ? SC * hv : SC * AL * expm1f(hv);
        }
    }
    __syncthreads();
    char* ah = (char*)g_Ahic;
    char* al = (char*)g_Aloc;
    for (int j = tid; j < DD; j += 256) {
        float o = bb[j];
        #pragma unroll
        for (int k = 0; k < HH; k++)
            o = fmaf(hs[k], bw[(size_t)k * DD + j], o);
        float mx = 0.5f * o + 0.5f * g_X[(size_t)t * DD + j];
        __nv_bfloat16 hi = __float2bfloat16_rn(mx);
        __nv_bfloat16 lo = __float2bfloat16_rn(mx - __bfloat162float(hi));
        size_t g = (((size_t)(j >> 6) * TT + t) * 64 + (j & 63)) * 2;
        size_t sw = g ^ ((g >> 3) & 0x70);
        *(__nv_bfloat16*)(ah + sw) = hi;
        *(__nv_bfloat16*)(al + sw) = lo;
    }
}

// ---------------------------------------------------------------------------
// 6) Head GEMM (R7 design)
// ---------------------------------------------------------------------------
#define TILE_B   16384           // 128 rows x 128 bytes
#define CH_B     (4*TILE_B)      // Ahi, Alo, Bhi, Blo
#define HEAD_SMEM (1024 + 2*CH_B)

__global__ void __launch_bounds__(512, 1) k_head(const float* __restrict__ bias,
                                                 float* __restrict__ out) {
    extern __shared__ __align__(1024) char smem[];
    uint32_t sb = smem_u32(smem);
    int tid  = threadIdx.x;
    int wid  = tid >> 5;
    int lane = tid & 31;
    int grp  = lane >> 2;
    int t4   = lane & 3;
    int m0 = blockIdx.x * 128;
    int n0 = blockIdx.y * 128;
    int wm = wid & 3;
    int wn = wid >> 2;

    if (tid == 0) { MBAR_INIT(sb, 1); MBAR_INIT(sb + 8, 1); }
    __syncthreads();

    const char* gAh = (const char*)g_Ahic;
    const char* gAl = (const char*)g_Aloc;
    const char* gBh = (const char*)g_Bhic;
    const char* gBl = (const char*)g_Bloc;

    auto issue = [&](int c) {
        int buf = c & 1;
        uint32_t mb  = sb + buf * 8;
        uint32_t dst = sb + 1024 + buf * CH_B;
        MBAR_EXPECT_TX(mb, CH_B);
        size_t aoff = ((size_t)c * TT + m0) * 128;
        size_t boff = ((size_t)c * VV + n0) * 128;
        bulk_cp(dst,            gAh + aoff, TILE_B, mb);
        bulk_cp(dst +   TILE_B, gAl + aoff, TILE_B, mb);
        bulk_cp(dst + 2*TILE_B, gBh + boff, TILE_B, mb);
        bulk_cp(dst + 3*TILE_B, gBl + boff, TILE_B, mb);
    };
    if (tid == 0) { issue(0); issue(1); }

    float acc[2][4][4] = {};

    uint32_t aRow  = (uint32_t)(wm*32 + (lane & 15));
    uint32_t aByte = aRow * 128;
    uint32_t aXor  = (aRow & 7) << 4;
    uint32_t aKb   = (uint32_t)((lane >> 4) * 16);
    uint32_t bRow  = (uint32_t)(wn*32 + (lane & 7) + ((lane >> 4) & 1) * 8);
    uint32_t bByte = bRow * 128;
    uint32_t bXor  = (bRow & 7) << 4;
    uint32_t bKb   = (uint32_t)(((lane >> 3) & 1) * 16);

    for (int c = 0; c < 8; c++) {
        mbar_wait(sb + (c & 1) * 8, (c >> 1) & 1);
        uint32_t base = sb + 1024 + (c & 1) * CH_B;
        uint32_t pAh = base;
        uint32_t pAl = base + TILE_B;
        uint32_t pBh = base + 2*TILE_B;
        uint32_t pBl = base + 3*TILE_B;

        #pragma unroll
        for (int ks = 0; ks < 4; ks++) {
            uint32_t ka = ((uint32_t)(ks*32) + aKb) ^ aXor;
            uint32_t kb = ((uint32_t)(ks*32) + bKb) ^ bXor;
            unsigned ah[2][4], al[2][4], bh[4][2], bl[4][2];
            #pragma unroll
            for (int mi = 0; mi < 2; mi++) {
                ldsm4(ah[mi], pAh + aByte + mi*2048 + ka);
                ldsm4(al[mi], pAl + aByte + mi*2048 + ka);
            }
            #pragma unroll
            for (int p = 0; p < 2; p++) {
                unsigned tmp[4];
                ldsm4(tmp, pBh + bByte + p*2048 + kb);
                bh[p*2][0] = tmp[0]; bh[p*2][1] = tmp[1];
                bh[p*2+1][0] = tmp[2]; bh[p*2+1][1] = tmp[3];
                ldsm4(tmp, pBl + bByte + p*2048 + kb);
                bl[p*2][0] = tmp[0]; bl[p*2][1] = tmp[1];
                bl[p*2+1][0] = tmp[2]; bl[p*2+1][1] = tmp[3];
            }
            #pragma unroll
            for (int mi = 0; mi < 2; mi++)
                #pragma unroll
                for (int ni = 0; ni < 4; ni++) {
                    mma16816(acc[mi][ni], ah[mi], bh[ni]);
                    mma16816(acc[mi][ni], ah[mi], bl[ni]);
                    mma16816(acc[mi][ni], al[mi], bh[ni]);
                }
        }
        __syncthreads();
        if (tid == 0 && c + 2 < 8) issue(c + 2);
    }

    #pragma unroll
    for (int mi = 0; mi < 2; mi++) {
        int r0 = m0 + wm * 32 + mi * 16 + grp;
        #pragma unroll
        for (int ni = 0; ni < 4; ni++) {
            int col = n0 + wn * 32 + ni * 8 + t4 * 2;
            float2 bv = *(const float2*)&bias[col];
            float2 v0 = { acc[mi][ni][0] + bv.x, acc[mi][ni][1] + bv.y };
            float2 v1 = { acc[mi][ni][2] + bv.x, acc[mi][ni][3] + bv.y };
            *(float2*)&out[(size_t)r0       * VV + col] = v0;
            *(float2*)&out[(size_t)(r0 + 8) * VV + col] = v1;
        }
    }
}

// ---------------------------------------------------------------------------
// 7) online log-softmax -> per-row loss; 8) final mean
// ---------------------------------------------------------------------------
__global__ void k_softmax(const float* __restrict__ logits,
                          const int* __restrict__ targets) {
    __shared__ float sm[256], ss[256];
    int t = blockIdx.x, tid = threadIdx.x;
    const float* row = logits + (size_t)t * VV;
    float m = -INFINITY, s = 0.f;
    for (int c = tid * 4; c < VV; c += 1024) {
        float4 v = *(const float4*)&row[c];
        float vm = fmaxf(fmaxf(v.x, v.y), fmaxf(v.z, v.w));
        float nm = fmaxf(m, vm);
        s = s * __expf(m - nm) + __expf(v.x - nm) + __expf(v.y - nm)
          + __expf(v.z - nm) + __expf(v.w - nm);
        m = nm;
    }
    sm[tid] = m; ss[tid] = s; __syncthreads();
    for (int st = 128; st; st >>= 1) {
        if (tid < st) {
            float m2 = fmaxf(sm[tid], sm[tid + st]);
            ss[tid] = ss[tid] * __expf(sm[tid] - m2) + ss[tid + st] * __expf(sm[tid + st] - m2);
            sm[tid] = m2;
        }
        __syncthreads();
    }
    if (tid == 0)
        g_rowloss[t] = row[targets[t]] - sm[0] - logf(ss[0]);
}

__global__ void k_loss(float* __restrict__ out) {
    __shared__ float red[256];
    int tid = threadIdx.x;
    float s = 0.f;
    for (int t = tid; t < TT; t += 256) s += g_rowloss[t];
    red[tid] = s; __syncthreads();
    for (int st = 128; st; st >>= 1) { if (tid < st) red[tid] += red[tid+st]; __syncthreads(); }
    if (tid == 0) out[0] = -red[0] / (float)TT;
}

// ---------------------------------------------------------------------------
extern "C" void kernel_launch(void* const* d_in, const int* in_sizes, int n_in,
                              void* d_out, int out_size) {
    const int*   tokens  = (const int*)  d_in[0];
    const int*   targets = (const int*)  d_in[1];
    const float* embed   = (const float*)d_in[2];
    const float* fw_init = (const float*)d_in[3];
    const float* eta     = (const float*)d_in[4];
    const float* wa      = (const float*)d_in[5];
    const float* wb      = (const float*)d_in[6];
    const float* mlp_aw  = (const float*)d_in[7];
    const float* mlp_ab  = (const float*)d_in[8];
    const float* mlp_bw  = (const float*)d_in[9];
    const float* mlp_bb  = (const float*)d_in[10];
    const float* head_w  = (const float*)d_in[11];
    const float* head_b  = (const float*)d_in[12];
    float* out = (float*)d_out;

    static int smem_set = 0;
    if (!smem_set) {
        cudaFuncSetAttribute(k_head, cudaFuncAttributeMaxDynamicSharedMemorySize, HEAD_SMEM);
        cudaFuncSetAttribute(k_scan, cudaFuncAttributeMaxDynamicSharedMemorySize, SC_SMEM);
        smem_set = 1;
    }

    k_gather<<<(TT*DD + 255) / 256, 256>>>(tokens, embed);
    k_convB<<<dim3(VV/64, DD/64), 256>>>(head_w);
    k_zgemm<<<dim3(DD/64, TT/64), 256>>>(wa, wb);
    k_scan<<<DD/4, 512, SC_SMEM>>>(fw_init, eta);   // ncu slot 4
    k_mlp<<<TT, 256>>>(mlp_aw, mlp_ab, mlp_bw, mlp_bb);
    k_head<<<dim3(TT/128, VV/128), 512, HEAD_SMEM>>>(head_b, out);
    k_softmax<<<TT, 256>>>(out, targets);
    if (out_size >= TT*VV + 1)
        k_loss<<<1, 256>>>(out + (size_t)TT*VV);
}

// round 12
// speedup vs baseline: 5.0249x; 1.0142x over previous
#include <cuda_runtime.h>
#include <cuda_bf16.h>
#include <math.h>
#include <stdint.h>

#define DD 512
#define HH 20
#define VV 32000
#define TT 1024

// Scratch (allocation-free rule: __device__ globals)
__device__ float g_X [TT*DD];
__device__ float g_Z0[TT*DD];
__device__ float g_Z1[TT*DD];
__device__ float g_Y [TT*DD];
__device__ float g_rowloss[TT];
// Chunk-major, pre-swizzled bf16 hi/lo operands for the head GEMM.
// Element (row, k): g = ((kc*ROWS + row)*64 + kk)*2, stored at g ^ ((g>>3)&0x70).
__device__ __nv_bfloat16 g_Ahic[TT*DD];
__device__ __nv_bfloat16 g_Aloc[TT*DD];
__device__ __nv_bfloat16 g_Bhic[(size_t)VV*DD];
__device__ __nv_bfloat16 g_Bloc[(size_t)VV*DD];

// ---------------------------------------------------------------------------
// PTX helpers
// ---------------------------------------------------------------------------
__device__ __forceinline__ uint32_t smem_u32(const void* p) {
    uint32_t a;
    asm("{ .reg .u64 t; cvta.to.shared.u64 t, %1; cvt.u32.u64 %0, t; }" : "=r"(a) : "l"(p));
    return a;
}
#define MBAR_INIT(a, c) asm volatile("mbarrier.init.shared.b64 [%0], %1;" :: "r"(a), "r"(c) : "memory")
#define MBAR_EXPECT_TX(a, b) \
    asm volatile("mbarrier.arrive.expect_tx.shared.b64 _, [%0], %1;" :: "r"(a), "r"(b) : "memory")
__device__ __forceinline__ void mbar_wait(uint32_t mbar, uint32_t parity) {
    uint32_t done;
    asm volatile("{ .reg .pred p; mbarrier.try_wait.parity.acquire.cta.shared::cta.b64 p, [%1], %2; selp.b32 %0,1,0,p; }"
                 : "=r"(done) : "r"(mbar), "r"(parity) : "memory");
    if (!done) {
        asm volatile("{ .reg .pred P1;\nWL_%=:\n"
                     "mbarrier.try_wait.parity.acquire.cta.shared::cta.b64 P1, [%0], %1, 0x989680;\n"
                     "@P1 bra.uni WD_%=;\n bra.uni WL_%=;\nWD_%=:\n}"
                     :: "r"(mbar), "r"(parity) : "memory");
    }
}
__device__ __forceinline__ void bulk_cp(uint32_t dst, const void* gsrc,
                                        uint32_t bytes, uint32_t mbar) {
    asm volatile("cp.async.bulk.shared::cluster.global.mbarrier::complete_tx::bytes [%0], [%1], %2, [%3];"
                 :: "r"(dst), "l"(__cvta_generic_to_global(gsrc)), "r"(bytes), "r"(mbar) : "memory");
}
__device__ __forceinline__ void ldsm4(unsigned r[4], uint32_t addr) {
    asm volatile("ldmatrix.sync.aligned.m8n8.x4.shared.b16 {%0,%1,%2,%3}, [%4];"
                 : "=r"(r[0]), "=r"(r[1]), "=r"(r[2]), "=r"(r[3]) : "r"(addr));
}
__device__ __forceinline__ void mma16816(float c[4], const unsigned a[4], const unsigned b[2]) {
    asm volatile(
        "mma.sync.aligned.m16n8k16.row.col.f32.bf16.bf16.f32 "
        "{%0,%1,%2,%3}, {%4,%5,%6,%7}, {%8,%9}, {%0,%1,%2,%3};\n"
        : "+f"(c[0]), "+f"(c[1]), "+f"(c[2]), "+f"(c[3])
        : "r"(a[0]), "r"(a[1]), "r"(a[2]), "r"(a[3]), "r"(b[0]), "r"(b[1]));
}
__device__ __forceinline__ float tanh_fast(float v) {
    float r;
    asm("tanh.approx.f32 %0, %1;" : "=f"(r) : "f"(v));
    return r;
}

// ---------------------------------------------------------------------------
// 1) X = embed[tokens]
// ---------------------------------------------------------------------------
__global__ void k_gather(const int* __restrict__ tokens,
                         const float* __restrict__ embed) {
    int idx = blockIdx.x * blockDim.x + threadIdx.x;
    if (idx < TT * DD) {
        int t = idx >> 9, d = idx & 511;
        g_X[idx] = embed[(size_t)tokens[t] * DD + d];
    }
}

// ---------------------------------------------------------------------------
// 2) head_w -> chunk-major swizzled bf16 hi/lo [kc][n][64]
// ---------------------------------------------------------------------------
__global__ void __launch_bounds__(256) k_convB(const float* __restrict__ W) {
    __shared__ float tile[64][65];
    int n0 = blockIdx.x * 64;
    int k0 = blockIdx.y * 64;
    int tid = threadIdx.x;
    #pragma unroll
    for (int i = 0; i < 16; i++) {
        int f = tid + 256 * i;
        int k = f >> 6, n = f & 63;
        tile[k][n] = W[(size_t)(k0 + k) * VV + n0 + n];
    }
    __syncthreads();
    size_t kc = (size_t)(k0 >> 6);
    char* bh = (char*)g_Bhic;
    char* bl = (char*)g_Bloc;
    #pragma unroll
    for (int i = 0; i < 16; i++) {
        int f = tid + 256 * i;
        int n = f >> 6, kk = f & 63;
        float v = tile[kk][n];
        __nv_bfloat16 hi = __float2bfloat16_rn(v);
        __nv_bfloat16 lo = __float2bfloat16_rn(v - __bfloat162float(hi));
        size_t g = ((kc * VV + (n0 + n)) * 64 + kk) * 2;
        size_t sw = g ^ ((g >> 3) & 0x70);
        *(__nv_bfloat16*)(bh + sw) = hi;
        *(__nv_bfloat16*)(bl + sw) = lo;
    }
}

// ---------------------------------------------------------------------------
// 3) Z0 = X @ wa, Z1 = X @ wb
// ---------------------------------------------------------------------------
__global__ void __launch_bounds__(256) k_zgemm(const float* __restrict__ wa,
                                               const float* __restrict__ wb) {
    __shared__ float Xs [16][64];
    __shared__ float Was[16][64];
    __shared__ float Wbs[16][64];
    int tid = threadIdx.x;
    int n0 = blockIdx.x * 64;
    int m0 = blockIdx.y * 64;
    int ty = tid >> 4, tx = tid & 15;
    float a0[4][4] = {}, a1[4][4] = {};

    for (int k0 = 0; k0 < DD; k0 += 16) {
        {
            int m  = tid >> 2;
            int kq = (tid & 3) * 4;
            float4 v = *(const float4*)&g_X[(size_t)(m0 + m) * DD + k0 + kq];
            Xs[kq+0][m] = v.x; Xs[kq+1][m] = v.y; Xs[kq+2][m] = v.z; Xs[kq+3][m] = v.w;
        }
        {
            int k  = tid >> 4;
            int nq = (tid & 15) * 4;
            *(float4*)&Was[k][nq] = *(const float4*)&wa[(size_t)(k0 + k) * DD + n0 + nq];
            *(float4*)&Wbs[k][nq] = *(const float4*)&wb[(size_t)(k0 + k) * DD + n0 + nq];
        }
        __syncthreads();
        #pragma unroll
        for (int k = 0; k < 16; k++) {
            float xr[4], war[4], wbr[4];
            #pragma unroll
            for (int i = 0; i < 4; i++) xr[i] = Xs[k][ty*4 + i];
            #pragma unroll
            for (int j = 0; j < 4; j++) { war[j] = Was[k][tx*4 + j]; wbr[j] = Wbs[k][tx*4 + j]; }
            #pragma unroll
            for (int i = 0; i < 4; i++)
                #pragma unroll
                for (int j = 0; j < 4; j++) {
                    a0[i][j] = fmaf(xr[i], war[j], a0[i][j]);
                    a1[i][j] = fmaf(xr[i], wbr[j], a1[i][j]);
                }
        }
        __syncthreads();
    }
    #pragma unroll
    for (int i = 0; i < 4; i++) {
        int row = m0 + ty*4 + i;
        #pragma unroll
        for (int j = 0; j < 4; j++) {
            int col = n0 + tx*4 + j;
            g_Z0[(size_t)row * DD + col] = a0[i][j];
            g_Z1[(size_t)row * DD + col] = a1[i][j];
        }
    }
}

// ---------------------------------------------------------------------------
// 4) Scan v5: 128 CTAs x 512 threads. Warp owns 32 rows x ALL 4 columns:
//    lane = (r4 = lane>>2 row-quad, col = lane&3). Quad lanes share the same
//    z0/x LDS.128 address -> smem broadcast dedups (4KB unique per CTA-step,
//    was 16KB). Reduction: 3-shfl butterfly (xor 16/8/4) leaves every lane
//    holding its column's warp partial; 16 warp-partials summed by tid<32.
//    Partial slots padded (stride 68 floats) -> conflict-free writeback.
// ---------------------------------------------------------------------------
#define SC_STEPS 8
#define SC_HALF  (SC_STEPS*DD*4)          // 16KB: 8 steps of one array
#define SC_BUF   (2*SC_HALF)              // 32KB: z0 + x
#define SC_STAGE0 8192                    // staging base (header below)
#define SC_SMEM  (SC_STAGE0 + 2*SC_BUF)   // 8KB + 64KB
#define PART_IDX(ph, s, w, c)  (((ph)*8 + (s))*68 + (w)*4 + (c))

__global__ void __launch_bounds__(512) k_scan(const float* __restrict__ fw_init,
                                              const float* __restrict__ eta_p) {
    extern __shared__ __align__(1024) char smem[];
    uint32_t sb = smem_u32(smem);
    float* part = (float*)(smem + 64);    // [64, 64+2*8*68*4=4416) < 8192

    int tid  = threadIdx.x;
    int wid  = tid >> 5;                  // 0..15: row group
    int lane = tid & 31;
    int r4   = lane >> 2;                 // 0..7 row-quad
    int col  = lane & 3;                  // 0..3 column
    int j0   = blockIdx.x * 4;
    int j    = j0 + col;
    int row0 = wid * 32 + r4 * 4;         // this lane's 4 consecutive rows
    float eta = *eta_p;

    if (tid == 0) { MBAR_INIT(sb, 1); MBAR_INIT(sb + 8, 1); }
    __syncthreads();

    auto issue = [&](int b) {
        uint32_t mb  = sb + (b & 1) * 8;
        uint32_t dst = sb + SC_STAGE0 + (b & 1) * SC_BUF;
        MBAR_EXPECT_TX(mb, SC_BUF);
        bulk_cp(dst,           g_Z0 + (size_t)b * SC_STEPS * DD, SC_HALF, mb);
        bulk_cp(dst + SC_HALF, g_X  + (size_t)b * SC_STEPS * DD, SC_HALF, mb);
    };
    if (tid == 0) { issue(0); issue(1); }

    float fw[4];
    #pragma unroll
    for (int g = 0; g < 4; g++)
        fw[g] = fw_init[(size_t)(row0 + g) * DD + j];

    const int NB = TT / SC_STEPS;         // 128 blocks
    for (int b = 0; b < NB; b++) {
        int tb = b * SC_STEPS;
        float z1b[SC_STEPS];
        #pragma unroll
        for (int s = 0; s < SC_STEPS; s++)
            z1b[s] = __ldg(&g_Z1[(size_t)(tb + s) * DD + j]);

        mbar_wait(sb + (b & 1) * 8, (b >> 1) & 1);
        uint32_t base = sb + SC_STAGE0 + (b & 1) * SC_BUF;

        float yb[SC_STEPS];
        #pragma unroll
        for (int s = 0; s < SC_STEPS; s++) {
            float4 z0v, xv;
            asm volatile("ld.shared.v4.f32 {%0,%1,%2,%3}, [%4];"
                         : "=f"(z0v.x), "=f"(z0v.y), "=f"(z0v.z), "=f"(z0v.w)
                         : "r"(base + (uint32_t)(s * DD + row0) * 4));
            asm volatile("ld.shared.v4.f32 {%0,%1,%2,%3}, [%4];"
                         : "=f"(xv.x), "=f"(xv.y), "=f"(xv.z), "=f"(xv.w)
                         : "r"(base + SC_HALF + (uint32_t)(s * DD + row0) * 4));
            float p = eta * z1b[s];
            float t0 = tanh_fast(fmaf(z0v.x, p, fw[0]));
            float t1 = tanh_fast(fmaf(z0v.y, p, fw[1]));
            float t2 = tanh_fast(fmaf(z0v.z, p, fw[2]));
            float t3 = tanh_fast(fmaf(z0v.w, p, fw[3]));
            fw[0] = t0; fw[1] = t1; fw[2] = t2; fw[3] = t3;
            yb[s] = fmaf(xv.x, t0, fmaf(xv.y, t1, fmaf(xv.z, t2, xv.w * t3)));
        }
        // reduce over lanes with the same col: xor 16, 8, 4 (pipelined x8)
        #pragma unroll
        for (int off = 16; off >= 4; off >>= 1)
            #pragma unroll
            for (int s = 0; s < SC_STEPS; s++)
                yb[s] += __shfl_xor_sync(0xffffffffu, yb[s], off);
        int ph = b & 1;
        if (lane < 4) {
            #pragma unroll
            for (int s = 0; s < SC_STEPS; s++)
                part[PART_IDX(ph, s, wid, lane)] = yb[s];
        }
        __syncthreads();              // partials ready AND buffer b&1 free
        if (tid == 0 && b + 2 < NB) issue(b + 2);
        if (tid < 32) {
            int s = tid >> 2, c = tid & 3;
            float y = 0.f;
            #pragma unroll
            for (int w = 0; w < 16; w++)
                y += part[PART_IDX(ph, s, w, c)];
            g_Y[(size_t)(tb + s) * DD + j0 + c] = y;
        }
    }
}

// ---------------------------------------------------------------------------
// 5) MLP + mix; epilogue emits chunk-major swizzled bf16 hi/lo of "mixed"
// ---------------------------------------------------------------------------
__global__ void k_mlp(const float* __restrict__ aw, const float* __restrict__ ab,
                      const float* __restrict__ bw, const float* __restrict__ bb) {
    __shared__ float ys[DD];
    __shared__ float hs[HH];
    int t = blockIdx.x, tid = threadIdx.x;
    for (int d = tid; d < DD; d += 256) ys[d] = g_Y[(size_t)t * DD + d];
    __syncthreads();
    int w = tid >> 5, lane = tid & 31;
    for (int u = w; u < HH; u += 8) {
        float acc = 0.f;
        #pragma unroll
        for (int k = 0; k < 16; k++) {
            int d = lane + 32*k;
            acc = fmaf(ys[d], aw[(size_t)d * HH + u], acc);
        }
        #pragma unroll
        for (int off = 16; off; off >>= 1)
            acc += __shfl_xor_sync(0xffffffffu, acc, off);
        if (lane == 0) {
            float hv = acc + ab[u];
            const float SC = 1.0507009873554805f, AL = 1.6732632423543772f;
            hs[u] = hv > 0.f ? SC * hv : SC * AL * expm1f(hv);
        }
    }
    __syncthreads();
    char* ah = (char*)g_Ahic;
    char* al = (char*)g_Aloc;
    for (int j = tid; j < DD; j += 256) {
        float o = bb[j];
        #pragma unroll
        for (int k = 0; k < HH; k++)
            o = fmaf(hs[k], bw[(size_t)k * DD + j], o);
        float mx = 0.5f * o + 0.5f * g_X[(size_t)t * DD + j];
        __nv_bfloat16 hi = __float2bfloat16_rn(mx);
        __nv_bfloat16 lo = __float2bfloat16_rn(mx - __bfloat162float(hi));
        size_t g = (((size_t)(j >> 6) * TT + t) * 64 + (j & 63)) * 2;
        size_t sw = g ^ ((g >> 3) & 0x70);
        *(__nv_bfloat16*)(ah + sw) = hi;
        *(__nv_bfloat16*)(al + sw) = lo;
    }
}

// ---------------------------------------------------------------------------
// 6) Head GEMM: 3-stage chunk pipeline (was 2) to deepen TMA overlap.
// ---------------------------------------------------------------------------
#define TILE_B   16384           // 128 rows x 128 bytes
#define CH_B     (4*TILE_B)      // Ahi, Alo, Bhi, Blo
#define HEAD_SMEM (1024 + 3*CH_B)   // 197632

__global__ void __launch_bounds__(512, 1) k_head(const float* __restrict__ bias,
                                                 float* __restrict__ out) {
    extern __shared__ __align__(1024) char smem[];
    uint32_t sb = smem_u32(smem);
    int tid  = threadIdx.x;
    int wid  = tid >> 5;
    int lane = tid & 31;
    int grp  = lane >> 2;
    int t4   = lane & 3;
    int m0 = blockIdx.x * 128;
    int n0 = blockIdx.y * 128;
    int wm = wid & 3;
    int wn = wid >> 2;

    if (tid == 0) { MBAR_INIT(sb, 1); MBAR_INIT(sb + 8, 1); MBAR_INIT(sb + 16, 1); }
    __syncthreads();

    const char* gAh = (const char*)g_Ahic;
    const char* gAl = (const char*)g_Aloc;
    const char* gBh = (const char*)g_Bhic;
    const char* gBl = (const char*)g_Bloc;

    auto issue = [&](int c) {
        int buf = c % 3;
        uint32_t mb  = sb + buf * 8;
        uint32_t dst = sb + 1024 + buf * CH_B;
        MBAR_EXPECT_TX(mb, CH_B);
        size_t aoff = ((size_t)c * TT + m0) * 128;
        size_t boff = ((size_t)c * VV + n0) * 128;
        bulk_cp(dst,            gAh + aoff, TILE_B, mb);
        bulk_cp(dst +   TILE_B, gAl + aoff, TILE_B, mb);
        bulk_cp(dst + 2*TILE_B, gBh + boff, TILE_B, mb);
        bulk_cp(dst + 3*TILE_B, gBl + boff, TILE_B, mb);
    };
    if (tid == 0) { issue(0); issue(1); issue(2); }

    float acc[2][4][4] = {};

    uint32_t aRow  = (uint32_t)(wm*32 + (lane & 15));
    uint32_t aByte = aRow * 128;
    uint32_t aXor  = (aRow & 7) << 4;
    uint32_t aKb   = (uint32_t)((lane >> 4) * 16);
    uint32_t bRow  = (uint32_t)(wn*32 + (lane & 7) + ((lane >> 4) & 1) * 8);
    uint32_t bByte = bRow * 128;
    uint32_t bXor  = (bRow & 7) << 4;
    uint32_t bKb   = (uint32_t)(((lane >> 3) & 1) * 16);

    for (int c = 0; c < 8; c++) {
        mbar_wait(sb + (c % 3) * 8, (c / 3) & 1);
        uint32_t base = sb + 1024 + (c % 3) * CH_B;
        uint32_t pAh = base;
        uint32_t pAl = base + TILE_B;
        uint32_t pBh = base + 2*TILE_B;
        uint32_t pBl = base + 3*TILE_B;

        #pragma unroll
        for (int ks = 0; ks < 4; ks++) {
            uint32_t ka = ((uint32_t)(ks*32) + aKb) ^ aXor;
            uint32_t kb = ((uint32_t)(ks*32) + bKb) ^ bXor;
            unsigned ah[2][4], al[2][4], bh[4][2], bl[4][2];
            #pragma unroll
            for (int mi = 0; mi < 2; mi++) {
                ldsm4(ah[mi], pAh + aByte + mi*2048 + ka);
                ldsm4(al[mi], pAl + aByte + mi*2048 + ka);
            }
            #pragma unroll
            for (int p = 0; p < 2; p++) {
                unsigned tmp[4];
                ldsm4(tmp, pBh + bByte + p*2048 + kb);
                bh[p*2][0] = tmp[0]; bh[p*2][1] = tmp[1];
                bh[p*2+1][0] = tmp[2]; bh[p*2+1][1] = tmp[3];
                ldsm4(tmp, pBl + bByte + p*2048 + kb);
                bl[p*2][0] = tmp[0]; bl[p*2][1] = tmp[1];
                bl[p*2+1][0] = tmp[2]; bl[p*2+1][1] = tmp[3];
            }
            #pragma unroll
            for (int mi = 0; mi < 2; mi++)
                #pragma unroll
                for (int ni = 0; ni < 4; ni++) {
                    mma16816(acc[mi][ni], ah[mi], bh[ni]);
                    mma16816(acc[mi][ni], ah[mi], bl[ni]);
                    mma16816(acc[mi][ni], al[mi], bh[ni]);
                }
        }
        __syncthreads();
        if (tid == 0 && c + 3 < 8) issue(c + 3);
    }

    #pragma unroll
    for (int mi = 0; mi < 2; mi++) {
        int r0 = m0 + wm * 32 + mi * 16 + grp;
        #pragma unroll
        for (int ni = 0; ni < 4; ni++) {
            int col = n0 + wn * 32 + ni * 8 + t4 * 2;
            float2 bv = *(const float2*)&bias[col];
            float2 v0 = { acc[mi][ni][0] + bv.x, acc[mi][ni][1] + bv.y };
            float2 v1 = { acc[mi][ni][2] + bv.x, acc[mi][ni][3] + bv.y };
            *(float2*)&out[(size_t)r0       * VV + col] = v0;
            *(float2*)&out[(size_t)(r0 + 8) * VV + col] = v1;
        }
    }
}

// ---------------------------------------------------------------------------
// 7) online log-softmax -> per-row loss; 8) final mean
// ---------------------------------------------------------------------------
__global__ void k_softmax(const float* __restrict__ logits,
                          const int* __restrict__ targets) {
    __shared__ float sm[256], ss[256];
    int t = blockIdx.x, tid = threadIdx.x;
    const float* row = logits + (size_t)t * VV;
    float m = -INFINITY, s = 0.f;
    for (int c = tid * 4; c < VV; c += 1024) {
        float4 v = *(const float4*)&row[c];
        float vm = fmaxf(fmaxf(v.x, v.y), fmaxf(v.z, v.w));
        float nm = fmaxf(m, vm);
        s = s * __expf(m - nm) + __expf(v.x - nm) + __expf(v.y - nm)
          + __expf(v.z - nm) + __expf(v.w - nm);
        m = nm;
    }
    sm[tid] = m; ss[tid] = s; __syncthreads();
    for (int st = 128; st; st >>= 1) {
        if (tid < st) {
            float m2 = fmaxf(sm[tid], sm[tid + st]);
            ss[tid] = ss[tid] * __expf(sm[tid] - m2) + ss[tid + st] * __expf(sm[tid + st] - m2);
            sm[tid] = m2;
        }
        __syncthreads();
    }
    if (tid == 0)
        g_rowloss[t] = row[targets[t]] - sm[0] - logf(ss[0]);
}

__global__ void k_loss(float* __restrict__ out) {
    __shared__ float red[256];
    int tid = threadIdx.x;
    float s = 0.f;
    for (int t = tid; t < TT; t += 256) s += g_rowloss[t];
    red[tid] = s; __syncthreads();
    for (int st = 128; st; st >>= 1) { if (tid < st) red[tid] += red[tid+st]; __syncthreads(); }
    if (tid == 0) out[0] = -red[0] / (float)TT;
}

// ---------------------------------------------------------------------------
extern "C" void kernel_launch(void* const* d_in, const int* in_sizes, int n_in,
                              void* d_out, int out_size) {
    const int*   tokens  = (const int*)  d_in[0];
    const int*   targets = (const int*)  d_in[1];
    const float* embed   = (const float*)d_in[2];
    const float* fw_init = (const float*)d_in[3];
    const float* eta     = (const float*)d_in[4];
    const float* wa      = (const float*)d_in[5];
    const float* wb      = (const float*)d_in[6];
    const float* mlp_aw  = (const float*)d_in[7];
    const float* mlp_ab  = (const float*)d_in[8];
    const float* mlp_bw  = (const float*)d_in[9];
    const float* mlp_bb  = (const float*)d_in[10];
    const float* head_w  = (const float*)d_in[11];
    const float* head_b  = (const float*)d_in[12];
    float* out = (float*)d_out;

    static int smem_set = 0;
    if (!smem_set) {
        cudaFuncSetAttribute(k_head, cudaFuncAttributeMaxDynamicSharedMemorySize, HEAD_SMEM);
        cudaFuncSetAttribute(k_scan, cudaFuncAttributeMaxDynamicSharedMemorySize, SC_SMEM);
        smem_set = 1;
    }

    k_gather<<<(TT*DD + 255) / 256, 256>>>(tokens, embed);
    k_convB<<<dim3(VV/64, DD/64), 256>>>(head_w);
    k_zgemm<<<dim3(DD/64, TT/64), 256>>>(wa, wb);
    k_scan<<<DD/4, 512, SC_SMEM>>>(fw_init, eta);   // ncu slot 4
    k_mlp<<<TT, 256>>>(mlp_aw, mlp_ab, mlp_bw, mlp_bb);
    k_head<<<dim3(TT/128, VV/128), 512, HEAD_SMEM>>>(head_b, out);
    k_softmax<<<TT, 256>>>(out, targets);
    if (out_size >= TT*VV + 1)
        k_loss<<<1, 256>>>(out + (size_t)TT*VV);
}

// round 13
// speedup vs baseline: 5.4119x; 1.0770x over previous
#include <cuda_runtime.h>
#include <cuda_bf16.h>
#include <math.h>
#include <stdint.h>

#define DD 512
#define HH 20
#define VV 32000
#define TT 1024

// Scratch (allocation-free rule: __device__ globals)
__device__ float g_X [TT*DD];
__device__ float g_Z0[TT*DD];
__device__ float g_Z1[TT*DD];
__device__ float g_Y [TT*DD];
__device__ float g_rowloss[TT];
// Chunk-major, pre-swizzled bf16 hi/lo operands for the head GEMM.
// Element (row, k): g = ((kc*ROWS + row)*64 + kk)*2, stored at g ^ ((g>>3)&0x70).
__device__ __nv_bfloat16 g_Ahic[TT*DD];
__device__ __nv_bfloat16 g_Aloc[TT*DD];
__device__ __nv_bfloat16 g_Bhic[(size_t)VV*DD];
__device__ __nv_bfloat16 g_Bloc[(size_t)VV*DD];

// ---------------------------------------------------------------------------
// PTX helpers
// ---------------------------------------------------------------------------
__device__ __forceinline__ uint32_t smem_u32(const void* p) {
    uint32_t a;
    asm("{ .reg .u64 t; cvta.to.shared.u64 t, %1; cvt.u32.u64 %0, t; }" : "=r"(a) : "l"(p));
    return a;
}
#define MBAR_INIT(a, c) asm volatile("mbarrier.init.shared.b64 [%0], %1;" :: "r"(a), "r"(c) : "memory")
#define MBAR_EXPECT_TX(a, b) \
    asm volatile("mbarrier.arrive.expect_tx.shared.b64 _, [%0], %1;" :: "r"(a), "r"(b) : "memory")
__device__ __forceinline__ void mbar_wait(uint32_t mbar, uint32_t parity) {
    uint32_t done;
    asm volatile("{ .reg .pred p; mbarrier.try_wait.parity.acquire.cta.shared::cta.b64 p, [%1], %2; selp.b32 %0,1,0,p; }"
                 : "=r"(done) : "r"(mbar), "r"(parity) : "memory");
    if (!done) {
        asm volatile("{ .reg .pred P1;\nWL_%=:\n"
                     "mbarrier.try_wait.parity.acquire.cta.shared::cta.b64 P1, [%0], %1, 0x989680;\n"
                     "@P1 bra.uni WD_%=;\n bra.uni WL_%=;\nWD_%=:\n}"
                     :: "r"(mbar), "r"(parity) : "memory");
    }
}
__device__ __forceinline__ void bulk_cp(uint32_t dst, const void* gsrc,
                                        uint32_t bytes, uint32_t mbar) {
    asm volatile("cp.async.bulk.shared::cluster.global.mbarrier::complete_tx::bytes [%0], [%1], %2, [%3];"
                 :: "r"(dst), "l"(__cvta_generic_to_global(gsrc)), "r"(bytes), "r"(mbar) : "memory");
}
__device__ __forceinline__ void ldsm4(unsigned r[4], uint32_t addr) {
    asm volatile("ldmatrix.sync.aligned.m8n8.x4.shared.b16 {%0,%1,%2,%3}, [%4];"
                 : "=r"(r[0]), "=r"(r[1]), "=r"(r[2]), "=r"(r[3]) : "r"(addr));
}
__device__ __forceinline__ void mma16816(float c[4], const unsigned a[4], const unsigned b[2]) {
    asm volatile(
        "mma.sync.aligned.m16n8k16.row.col.f32.bf16.bf16.f32 "
        "{%0,%1,%2,%3}, {%4,%5,%6,%7}, {%8,%9}, {%0,%1,%2,%3};\n"
        : "+f"(c[0]), "+f"(c[1]), "+f"(c[2]), "+f"(c[3])
        : "r"(a[0]), "r"(a[1]), "r"(a[2]), "r"(a[3]), "r"(b[0]), "r"(b[1]));
}
__device__ __forceinline__ float tanh_fast(float v) {
    float r;
    asm("tanh.approx.f32 %0, %1;" : "=f"(r) : "f"(v));
    return r;
}

// ---------------------------------------------------------------------------
// 1) X = embed[tokens]
// ---------------------------------------------------------------------------
__global__ void k_gather(const int* __restrict__ tokens,
                         const float* __restrict__ embed) {
    int idx = blockIdx.x * blockDim.x + threadIdx.x;
    if (idx < TT * DD) {
        int t = idx >> 9, d = idx & 511;
        g_X[idx] = embed[(size_t)tokens[t] * DD + d];
    }
}

// ---------------------------------------------------------------------------
// 2) head_w -> chunk-major swizzled bf16 hi/lo [kc][n][64]
// ---------------------------------------------------------------------------
__global__ void __launch_bounds__(256) k_convB(const float* __restrict__ W) {
    __shared__ float tile[64][65];
    int n0 = blockIdx.x * 64;
    int k0 = blockIdx.y * 64;
    int tid = threadIdx.x;
    #pragma unroll
    for (int i = 0; i < 16; i++) {
        int f = tid + 256 * i;
        int k = f >> 6, n = f & 63;
        tile[k][n] = W[(size_t)(k0 + k) * VV + n0 + n];
    }
    __syncthreads();
    size_t kc = (size_t)(k0 >> 6);
    char* bh = (char*)g_Bhic;
    char* bl = (char*)g_Bloc;
    #pragma unroll
    for (int i = 0; i < 16; i++) {
        int f = tid + 256 * i;
        int n = f >> 6, kk = f & 63;
        float v = tile[kk][n];
        __nv_bfloat16 hi = __float2bfloat16_rn(v);
        __nv_bfloat16 lo = __float2bfloat16_rn(v - __bfloat162float(hi));
        size_t g = ((kc * VV + (n0 + n)) * 64 + kk) * 2;
        size_t sw = g ^ ((g >> 3) & 0x70);
        *(__nv_bfloat16*)(bh + sw) = hi;
        *(__nv_bfloat16*)(bl + sw) = lo;
    }
}

// ---------------------------------------------------------------------------
// 3) Z0 = X @ wa, Z1 = X @ wb
// ---------------------------------------------------------------------------
__global__ void __launch_bounds__(256) k_zgemm(const float* __restrict__ wa,
                                               const float* __restrict__ wb) {
    __shared__ float Xs [16][64];
    __shared__ float Was[16][64];
    __shared__ float Wbs[16][64];
    int tid = threadIdx.x;
    int n0 = blockIdx.x * 64;
    int m0 = blockIdx.y * 64;
    int ty = tid >> 4, tx = tid & 15;
    float a0[4][4] = {}, a1[4][4] = {};

    for (int k0 = 0; k0 < DD; k0 += 16) {
        {
            int m  = tid >> 2;
            int kq = (tid & 3) * 4;
            float4 v = *(const float4*)&g_X[(size_t)(m0 + m) * DD + k0 + kq];
            Xs[kq+0][m] = v.x; Xs[kq+1][m] = v.y; Xs[kq+2][m] = v.z; Xs[kq+3][m] = v.w;
        }
        {
            int k  = tid >> 4;
            int nq = (tid & 15) * 4;
            *(float4*)&Was[k][nq] = *(const float4*)&wa[(size_t)(k0 + k) * DD + n0 + nq];
            *(float4*)&Wbs[k][nq] = *(const float4*)&wb[(size_t)(k0 + k) * DD + n0 + nq];
        }
        __syncthreads();
        #pragma unroll
        for (int k = 0; k < 16; k++) {
            float xr[4], war[4], wbr[4];
            #pragma unroll
            for (int i = 0; i < 4; i++) xr[i] = Xs[k][ty*4 + i];
            #pragma unroll
            for (int j = 0; j < 4; j++) { war[j] = Was[k][tx*4 + j]; wbr[j] = Wbs[k][tx*4 + j]; }
            #pragma unroll
            for (int i = 0; i < 4; i++)
                #pragma unroll
                for (int j = 0; j < 4; j++) {
                    a0[i][j] = fmaf(xr[i], war[j], a0[i][j]);
                    a1[i][j] = fmaf(xr[i], wbr[j], a1[i][j]);
                }
        }
        __syncthreads();
    }
    #pragma unroll
    for (int i = 0; i < 4; i++) {
        int row = m0 + ty*4 + i;
        #pragma unroll
        for (int j = 0; j < 4; j++) {
            int col = n0 + tx*4 + j;
            g_Z0[(size_t)row * DD + col] = a0[i][j];
            g_Z1[(size_t)row * DD + col] = a1[i][j];
        }
    }
}

// ---------------------------------------------------------------------------
// 4) Scan v6: 128 CTAs x 512 threads, 16-step blocks (64 blocks).
//    Warp owns 32 rows x all 4 columns (quad-broadcast LDS).
//    z1 software-pipelined ONE BLOCK AHEAD (R12 finding: per-block z1 LDG
//    latency was exposed every block). z0/x staged by double-buffered
//    cp.async.bulk, 32KB per array per block.
// ---------------------------------------------------------------------------
#define SC_STEPS 16
#define SC_HALF  (SC_STEPS*DD*4)          // 32KB: 16 steps of one array
#define SC_BUF   (2*SC_HALF)              // 64KB: z0 + x
#define SC_STAGE0 9216                    // staging base (header below)
#define SC_SMEM  (SC_STAGE0 + 2*SC_BUF)   // 9KB + 128KB
#define PART_IDX(ph, s, w, c)  (((ph)*SC_STEPS + (s))*68 + (w)*4 + (c))

__global__ void __launch_bounds__(512) k_scan(const float* __restrict__ fw_init,
                                              const float* __restrict__ eta_p) {
    extern __shared__ __align__(1024) char smem[];
    uint32_t sb = smem_u32(smem);
    float* part = (float*)(smem + 64);    // 2*16*68*4 = 8704 B -> [64, 8768) < 9216

    int tid  = threadIdx.x;
    int wid  = tid >> 5;                  // 0..15: row group
    int lane = tid & 31;
    int r4   = lane >> 2;                 // 0..7 row-quad
    int col  = lane & 3;                  // 0..3 column
    int j0   = blockIdx.x * 4;
    int j    = j0 + col;
    int row0 = wid * 32 + r4 * 4;         // this lane's 4 consecutive rows
    float eta = *eta_p;

    if (tid == 0) { MBAR_INIT(sb, 1); MBAR_INIT(sb + 8, 1); }
    __syncthreads();

    auto issue = [&](int b) {
        uint32_t mb  = sb + (b & 1) * 8;
        uint32_t dst = sb + SC_STAGE0 + (b & 1) * SC_BUF;
        MBAR_EXPECT_TX(mb, SC_BUF);
        bulk_cp(dst,           g_Z0 + (size_t)b * SC_STEPS * DD, SC_HALF, mb);
        bulk_cp(dst + SC_HALF, g_X  + (size_t)b * SC_STEPS * DD, SC_HALF, mb);
    };
    if (tid == 0) { issue(0); issue(1); }

    float fw[4];
    #pragma unroll
    for (int g = 0; g < 4; g++)
        fw[g] = fw_init[(size_t)(row0 + g) * DD + j];

    // z1 pipeline: block 0 loaded up-front
    float z1cur[SC_STEPS];
    #pragma unroll
    for (int s = 0; s < SC_STEPS; s++)
        z1cur[s] = __ldg(&g_Z1[(size_t)s * DD + j]);

    const int NB = TT / SC_STEPS;         // 64 blocks
    for (int b = 0; b < NB; b++) {
        int tb = b * SC_STEPS;
        // issue z1 prefetch for block b+1 FIRST (consumed next iteration)
        float z1nxt[SC_STEPS];
        if (b + 1 < NB) {
            #pragma unroll
            for (int s = 0; s < SC_STEPS; s++)
                z1nxt[s] = __ldg(&g_Z1[(size_t)(tb + SC_STEPS + s) * DD + j]);
        }

        mbar_wait(sb + (b & 1) * 8, (b >> 1) & 1);
        uint32_t base = sb + SC_STAGE0 + (b & 1) * SC_BUF;

        float yb[SC_STEPS];
        #pragma unroll
        for (int s = 0; s < SC_STEPS; s++) {
            float4 z0v, xv;
            asm volatile("ld.shared.v4.f32 {%0,%1,%2,%3}, [%4];"
                         : "=f"(z0v.x), "=f"(z0v.y), "=f"(z0v.z), "=f"(z0v.w)
                         : "r"(base + (uint32_t)(s * DD + row0) * 4));
            asm volatile("ld.shared.v4.f32 {%0,%1,%2,%3}, [%4];"
                         : "=f"(xv.x), "=f"(xv.y), "=f"(xv.z), "=f"(xv.w)
                         : "r"(base + SC_HALF + (uint32_t)(s * DD + row0) * 4));
            float p = eta * z1cur[s];
            float t0 = tanh_fast(fmaf(z0v.x, p, fw[0]));
            float t1 = tanh_fast(fmaf(z0v.y, p, fw[1]));
            float t2 = tanh_fast(fmaf(z0v.z, p, fw[2]));
            float t3 = tanh_fast(fmaf(z0v.w, p, fw[3]));
            fw[0] = t0; fw[1] = t1; fw[2] = t2; fw[3] = t3;
            yb[s] = fmaf(xv.x, t0, fmaf(xv.y, t1, fmaf(xv.z, t2, xv.w * t3)));
        }
        // reduce over lanes with the same col: xor 16, 8, 4 (pipelined x16)
        #pragma unroll
        for (int off = 16; off >= 4; off >>= 1)
            #pragma unroll
            for (int s = 0; s < SC_STEPS; s++)
                yb[s] += __shfl_xor_sync(0xffffffffu, yb[s], off);
        int ph = b & 1;
        if (lane < 4) {
            #pragma unroll
            for (int s = 0; s < SC_STEPS; s++)
                part[PART_IDX(ph, s, wid, lane)] = yb[s];
        }
        __syncthreads();              // partials ready AND buffer b&1 free
        if (tid == 0 && b + 2 < NB) issue(b + 2);
        if (tid < 64) {
            int s = tid >> 2, c = tid & 3;
            float y = 0.f;
            #pragma unroll
            for (int w = 0; w < 16; w++)
                y += part[PART_IDX(ph, s, w, c)];
            g_Y[(size_t)(tb + s) * DD + j0 + c] = y;
        }
        // rotate z1 pipeline
        #pragma unroll
        for (int s = 0; s < SC_STEPS; s++)
            z1cur[s] = z1nxt[s];
    }
}

// ---------------------------------------------------------------------------
// 5) MLP + mix; epilogue emits chunk-major swizzled bf16 hi/lo of "mixed"
// ---------------------------------------------------------------------------
__global__ void k_mlp(const float* __restrict__ aw, const float* __restrict__ ab,
                      const float* __restrict__ bw, const float* __restrict__ bb) {
    __shared__ float ys[DD];
    __shared__ float hs[HH];
    int t = blockIdx.x, tid = threadIdx.x;
    for (int d = tid; d < DD; d += 256) ys[d] = g_Y[(size_t)t * DD + d];
    __syncthreads();
    int w = tid >> 5, lane = tid & 31;
    for (int u = w; u < HH; u += 8) {
        float acc = 0.f;
        #pragma unroll
        for (int k = 0; k < 16; k++) {
            int d = lane + 32*k;
            acc = fmaf(ys[d], aw[(size_t)d * HH + u], acc);
        }
        #pragma unroll
        for (int off = 16; off; off >>= 1)
            acc += __shfl_xor_sync(0xffffffffu, acc, off);
        if (lane == 0) {
            float hv = acc + ab[u];
            const float SC = 1.0507009873554805f, AL = 1.6732632423543772f;
            hs[u] = hv > 0.f ? SC * hv : SC * AL * expm1f(hv);
        }
    }
    __syncthreads();
    char* ah = (char*)g_Ahic;
    char* al = (char*)g_Aloc;
    for (int j = tid; j < DD; j += 256) {
        float o = bb[j];
        #pragma unroll
        for (int k = 0; k < HH; k++)
            o = fmaf(hs[k], bw[(size_t)k * DD + j], o);
        float mx = 0.5f * o + 0.5f * g_X[(size_t)t * DD + j];
        __nv_bfloat16 hi = __float2bfloat16_rn(mx);
        __nv_bfloat16 lo = __float2bfloat16_rn(mx - __bfloat162float(hi));
        size_t g = (((size_t)(j >> 6) * TT + t) * 64 + (j & 63)) * 2;
        size_t sw = g ^ ((g >> 3) & 0x70);
        *(__nv_bfloat16*)(ah + sw) = hi;
        *(__nv_bfloat16*)(al + sw) = lo;
    }
}

// ---------------------------------------------------------------------------
// 6) Head GEMM: 3-stage chunk pipeline
// ---------------------------------------------------------------------------
#define TILE_B   16384           // 128 rows x 128 bytes
#define CH_B     (4*TILE_B)      // Ahi, Alo, Bhi, Blo
#define HEAD_SMEM (1024 + 3*CH_B)   // 197632

__global__ void __launch_bounds__(512, 1) k_head(const float* __restrict__ bias,
                                                 float* __restrict__ out) {
    extern __shared__ __align__(1024) char smem[];
    uint32_t sb = smem_u32(smem);
    int tid  = threadIdx.x;
    int wid  = tid >> 5;
    int lane = tid & 31;
    int grp  = lane >> 2;
    int t4   = lane & 3;
    int m0 = blockIdx.x * 128;
    int n0 = blockIdx.y * 128;
    int wm = wid & 3;
    int wn = wid >> 2;

    if (tid == 0) { MBAR_INIT(sb, 1); MBAR_INIT(sb + 8, 1); MBAR_INIT(sb + 16, 1); }
    __syncthreads();

    const char* gAh = (const char*)g_Ahic;
    const char* gAl = (const char*)g_Aloc;
    const char* gBh = (const char*)g_Bhic;
    const char* gBl = (const char*)g_Bloc;

    auto issue = [&](int c) {
        int buf = c % 3;
        uint32_t mb  = sb + buf * 8;
        uint32_t dst = sb + 1024 + buf * CH_B;
        MBAR_EXPECT_TX(mb, CH_B);
        size_t aoff = ((size_t)c * TT + m0) * 128;
        size_t boff = ((size_t)c * VV + n0) * 128;
        bulk_cp(dst,            gAh + aoff, TILE_B, mb);
        bulk_cp(dst +   TILE_B, gAl + aoff, TILE_B, mb);
        bulk_cp(dst + 2*TILE_B, gBh + boff, TILE_B, mb);
        bulk_cp(dst + 3*TILE_B, gBl + boff, TILE_B, mb);
    };
    if (tid == 0) { issue(0); issue(1); issue(2); }

    float acc[2][4][4] = {};

    uint32_t aRow  = (uint32_t)(wm*32 + (lane & 15));
    uint32_t aByte = aRow * 128;
    uint32_t aXor  = (aRow & 7) << 4;
    uint32_t aKb   = (uint32_t)((lane >> 4) * 16);
    uint32_t bRow  = (uint32_t)(wn*32 + (lane & 7) + ((lane >> 4) & 1) * 8);
    uint32_t bByte = bRow * 128;
    uint32_t bXor  = (bRow & 7) << 4;
    uint32_t bKb   = (uint32_t)(((lane >> 3) & 1) * 16);

    for (int c = 0; c < 8; c++) {
        mbar_wait(sb + (c % 3) * 8, (c / 3) & 1);
        uint32_t base = sb + 1024 + (c % 3) * CH_B;
        uint32_t pAh = base;
        uint32_t pAl = base + TILE_B;
        uint32_t pBh = base + 2*TILE_B;
        uint32_t pBl = base + 3*TILE_B;

        #pragma unroll
        for (int ks = 0; ks < 4; ks++) {
            uint32_t ka = ((uint32_t)(ks*32) + aKb) ^ aXor;
            uint32_t kb = ((uint32_t)(ks*32) + bKb) ^ bXor;
            unsigned ah[2][4], al[2][4], bh[4][2], bl[4][2];
            #pragma unroll
            for (int mi = 0; mi < 2; mi++) {
                ldsm4(ah[mi], pAh + aByte + mi*2048 + ka);
                ldsm4(al[mi], pAl + aByte + mi*2048 + ka);
            }
            #pragma unroll
            for (int p = 0; p < 2; p++) {
                unsigned tmp[4];
                ldsm4(tmp, pBh + bByte + p*2048 + kb);
                bh[p*2][0] = tmp[0]; bh[p*2][1] = tmp[1];
                bh[p*2+1][0] = tmp[2]; bh[p*2+1][1] = tmp[3];
                ldsm4(tmp, pBl + bByte + p*2048 + kb);
                bl[p*2][0] = tmp[0]; bl[p*2][1] = tmp[1];
                bl[p*2+1][0] = tmp[2]; bl[p*2+1][1] = tmp[3];
            }
            #pragma unroll
            for (int mi = 0; mi < 2; mi++)
                #pragma unroll
                for (int ni = 0; ni < 4; ni++) {
                    mma16816(acc[mi][ni], ah[mi], bh[ni]);
                    mma16816(acc[mi][ni], ah[mi], bl[ni]);
                    mma16816(acc[mi][ni], al[mi], bh[ni]);
                }
        }
        __syncthreads();
        if (tid == 0 && c + 3 < 8) issue(c + 3);
    }

    #pragma unroll
    for (int mi = 0; mi < 2; mi++) {
        int r0 = m0 + wm * 32 + mi * 16 + grp;
        #pragma unroll
        for (int ni = 0; ni < 4; ni++) {
            int col = n0 + wn * 32 + ni * 8 + t4 * 2;
            float2 bv = *(const float2*)&bias[col];
            float2 v0 = { acc[mi][ni][0] + bv.x, acc[mi][ni][1] + bv.y };
            float2 v1 = { acc[mi][ni][2] + bv.x, acc[mi][ni][3] + bv.y };
            *(float2*)&out[(size_t)r0       * VV + col] = v0;
            *(float2*)&out[(size_t)(r0 + 8) * VV + col] = v1;
        }
    }
}

// ---------------------------------------------------------------------------
// 7) online log-softmax -> per-row loss; 8) final mean
// ---------------------------------------------------------------------------
__global__ void k_softmax(const float* __restrict__ logits,
                          const int* __restrict__ targets) {
    __shared__ float sm[256], ss[256];
    int t = blockIdx.x, tid = threadIdx.x;
    const float* row = logits + (size_t)t * VV;
    float m = -INFINITY, s = 0.f;
    for (int c = tid * 4; c < VV; c += 1024) {
        float4 v = *(const float4*)&row[c];
        float vm = fmaxf(fmaxf(v.x, v.y), fmaxf(v.z, v.w));
        float nm = fmaxf(m, vm);
        s = s * __expf(m - nm) + __expf(v.x - nm) + __expf(v.y - nm)
          + __expf(v.z - nm) + __expf(v.w - nm);
        m = nm;
    }
    sm[tid] = m; ss[tid] = s; __syncthreads();
    for (int st = 128; st; st >>= 1) {
        if (tid < st) {
            float m2 = fmaxf(sm[tid], sm[tid + st]);
            ss[tid] = ss[tid] * __expf(sm[tid] - m2) + ss[tid + st] * __expf(sm[tid + st] - m2);
            sm[tid] = m2;
        }
        __syncthreads();
    }
    if (tid == 0)
        g_rowloss[t] = row[targets[t]] - sm[0] - logf(ss[0]);
}

__global__ void k_loss(float* __restrict__ out) {
    __shared__ float red[256];
    int tid = threadIdx.x;
    float s = 0.f;
    for (int t = tid; t < TT; t += 256) s += g_rowloss[t];
    red[tid] = s; __syncthreads();
    for (int st = 128; st; st >>= 1) { if (tid < st) red[tid] += red[tid+st]; __syncthreads(); }
    if (tid == 0) out[0] = -red[0] / (float)TT;
}

// ---------------------------------------------------------------------------
extern "C" void kernel_launch(void* const* d_in, const int* in_sizes, int n_in,
                              void* d_out, int out_size) {
    const int*   tokens  = (const int*)  d_in[0];
    const int*   targets = (const int*)  d_in[1];
    const float* embed   = (const float*)d_in[2];
    const float* fw_init = (const float*)d_in[3];
    const float* eta     = (const float*)d_in[4];
    const float* wa      = (const float*)d_in[5];
    const float* wb      = (const float*)d_in[6];
    const float* mlp_aw  = (const float*)d_in[7];
    const float* mlp_ab  = (const float*)d_in[8];
    const float* mlp_bw  = (const float*)d_in[9];
    const float* mlp_bb  = (const float*)d_in[10];
    const float* head_w  = (const float*)d_in[11];
    const float* head_b  = (const float*)d_in[12];
    float* out = (float*)d_out;

    static int smem_set = 0;
    if (!smem_set) {
        cudaFuncSetAttribute(k_head, cudaFuncAttributeMaxDynamicSharedMemorySize, HEAD_SMEM);
        cudaFuncSetAttribute(k_scan, cudaFuncAttributeMaxDynamicSharedMemorySize, SC_SMEM);
        smem_set = 1;
    }

    k_gather<<<(TT*DD + 255) / 256, 256>>>(tokens, embed);
    k_convB<<<dim3(VV/64, DD/64), 256>>>(head_w);
    k_zgemm<<<dim3(DD/64, TT/64), 256>>>(wa, wb);
    k_scan<<<DD/4, 512, SC_SMEM>>>(fw_init, eta);   // ncu slot 4
    k_mlp<<<TT, 256>>>(mlp_aw, mlp_ab, mlp_bw, mlp_bb);
    k_head<<<dim3(TT/128, VV/128), 512, HEAD_SMEM>>>(head_b, out);
    k_softmax<<<TT, 256>>>(out, targets);
    if (out_size >= TT*VV + 1)
        k_loss<<<1, 256>>>(out + (size_t)TT*VV);
}

// round 15
// speedup vs baseline: 5.5683x; 1.0289x over previous
#include <cuda_runtime.h>
#include <cuda_bf16.h>
#include <math.h>
#include <stdint.h>

#define DD 512
#define HH 20
#define VV 32000
#define TT 1024
#define NTILES (VV/128)   // 250 n-tiles in the head grid

// Scratch (allocation-free rule: __device__ globals)
__device__ float g_X [TT*DD];
__device__ float g_Z0[TT*DD];
__device__ float g_Z1[TT*DD];
__device__ float g_Y [TT*DD];
__device__ float g_rowloss[TT];
__device__ float g_pm[TT*NTILES];   // per (row, n-tile) max
__device__ float g_ps[TT*NTILES];   // per (row, n-tile) sum exp(v - max)
// Chunk-major, pre-swizzled bf16 hi/lo operands for the head GEMM.
__device__ __nv_bfloat16 g_Ahic[TT*DD];
__device__ __nv_bfloat16 g_Aloc[TT*DD];
__device__ __nv_bfloat16 g_Bhic[(size_t)VV*DD];
__device__ __nv_bfloat16 g_Bloc[(size_t)VV*DD];

// ---------------------------------------------------------------------------
// PTX helpers
// ---------------------------------------------------------------------------
__device__ __forceinline__ uint32_t smem_u32(const void* p) {
    uint32_t a;
    asm("{ .reg .u64 t; cvta.to.shared.u64 t, %1; cvt.u32.u64 %0, t; }" : "=r"(a) : "l"(p));
    return a;
}
#define MBAR_INIT(a, c) asm volatile("mbarrier.init.shared.b64 [%0], %1;" :: "r"(a), "r"(c) : "memory")
#define MBAR_EXPECT_TX(a, b) \
    asm volatile("mbarrier.arrive.expect_tx.shared.b64 _, [%0], %1;" :: "r"(a), "r"(b) : "memory")
__device__ __forceinline__ void mbar_wait(uint32_t mbar, uint32_t parity) {
    uint32_t done;
    asm volatile("{ .reg .pred p; mbarrier.try_wait.parity.acquire.cta.shared::cta.b64 p, [%1], %2; selp.b32 %0,1,0,p; }"
                 : "=r"(done) : "r"(mbar), "r"(parity) : "memory");
    if (!done) {
        asm volatile("{ .reg .pred P1;\nWL_%=:\n"
                     "mbarrier.try_wait.parity.acquire.cta.shared::cta.b64 P1, [%0], %1, 0x989680;\n"
                     "@P1 bra.uni WD_%=;\n bra.uni WL_%=;\nWD_%=:\n}"
                     :: "r"(mbar), "r"(parity) : "memory");
    }
}
__device__ __forceinline__ void bulk_cp(uint32_t dst, const void* gsrc,
                                        uint32_t bytes, uint32_t mbar) {
    asm volatile("cp.async.bulk.shared::cluster.global.mbarrier::complete_tx::bytes [%0], [%1], %2, [%3];"
                 :: "r"(dst), "l"(__cvta_generic_to_global(gsrc)), "r"(bytes), "r"(mbar) : "memory");
}
__device__ __forceinline__ void ldsm4(unsigned r[4], uint32_t addr) {
    asm volatile("ldmatrix.sync.aligned.m8n8.x4.shared.b16 {%0,%1,%2,%3}, [%4];"
                 : "=r"(r[0]), "=r"(r[1]), "=r"(r[2]), "=r"(r[3]) : "r"(addr));
}
__device__ __forceinline__ void mma16816(float c[4], const unsigned a[4], const unsigned b[2]) {
    asm volatile(
        "mma.sync.aligned.m16n8k16.row.col.f32.bf16.bf16.f32 "
        "{%0,%1,%2,%3}, {%4,%5,%6,%7}, {%8,%9}, {%0,%1,%2,%3};\n"
        : "+f"(c[0]), "+f"(c[1]), "+f"(c[2]), "+f"(c[3])
        : "r"(a[0]), "r"(a[1]), "r"(a[2]), "r"(a[3]), "r"(b[0]), "r"(b[1]));
}
__device__ __forceinline__ float tanh_fast(float v) {
    float r;
    asm("tanh.approx.f32 %0, %1;" : "=f"(r) : "f"(v));
    return r;
}

// ---------------------------------------------------------------------------
// 1) X = embed[tokens]
// ---------------------------------------------------------------------------
__global__ void k_gather(const int* __restrict__ tokens,
                         const float* __restrict__ embed) {
    int idx = blockIdx.x * blockDim.x + threadIdx.x;
    if (idx < TT * DD) {
        int t = idx >> 9, d = idx & 511;
        g_X[idx] = embed[(size_t)tokens[t] * DD + d];
    }
}

// ---------------------------------------------------------------------------
// 2) head_w -> chunk-major swizzled bf16 hi/lo [kc][n][64]
// ---------------------------------------------------------------------------
__global__ void __launch_bounds__(256) k_convB(const float* __restrict__ W) {
    __shared__ float tile[64][65];
    int n0 = blockIdx.x * 64;
    int k0 = blockIdx.y * 64;
    int tid = threadIdx.x;
    #pragma unroll
    for (int i = 0; i < 16; i++) {
        int f = tid + 256 * i;
        int k = f >> 6, n = f & 63;
        tile[k][n] = W[(size_t)(k0 + k) * VV + n0 + n];
    }
    __syncthreads();
    size_t kc = (size_t)(k0 >> 6);
    char* bh = (char*)g_Bhic;
    char* bl = (char*)g_Bloc;
    #pragma unroll
    for (int i = 0; i < 16; i++) {
        int f = tid + 256 * i;
        int n = f >> 6, kk = f & 63;
        float v = tile[kk][n];
        __nv_bfloat16 hi = __float2bfloat16_rn(v);
        __nv_bfloat16 lo = __float2bfloat16_rn(v - __bfloat162float(hi));
        size_t g = ((kc * VV + (n0 + n)) * 64 + kk) * 2;
        size_t sw = g ^ ((g >> 3) & 0x70);
        *(__nv_bfloat16*)(bh + sw) = hi;
        *(__nv_bfloat16*)(bl + sw) = lo;
    }
}

// ---------------------------------------------------------------------------
// 3) Z0 = X @ wa, Z1 = X @ wb  (K-step 32: half the barriers of R13)
// ---------------------------------------------------------------------------
__global__ void __launch_bounds__(256) k_zgemm(const float* __restrict__ wa,
                                               const float* __restrict__ wb) {
    __shared__ float Xs [32][64];
    __shared__ float Was[32][64];
    __shared__ float Wbs[32][64];
    int tid = threadIdx.x;
    int n0 = blockIdx.x * 64;
    int m0 = blockIdx.y * 64;
    int ty = tid >> 4, tx = tid & 15;
    float a0[4][4] = {}, a1[4][4] = {};

    for (int k0 = 0; k0 < DD; k0 += 32) {
        #pragma unroll
        for (int q = 0; q < 2; q++) {          // X tile (transposed store)
            int f = tid + 256 * q;
            int m  = f >> 3;
            int kq = (f & 7) * 4;
            float4 v = *(const float4*)&g_X[(size_t)(m0 + m) * DD + k0 + kq];
            Xs[kq+0][m] = v.x; Xs[kq+1][m] = v.y; Xs[kq+2][m] = v.z; Xs[kq+3][m] = v.w;
        }
        #pragma unroll
        for (int q = 0; q < 2; q++) {          // W tiles
            int f = tid + 256 * q;
            int k  = f >> 4;
            int nq = (f & 15) * 4;
            *(float4*)&Was[k][nq] = *(const float4*)&wa[(size_t)(k0 + k) * DD + n0 + nq];
            *(float4*)&Wbs[k][nq] = *(const float4*)&wb[(size_t)(k0 + k) * DD + n0 + nq];
        }
        __syncthreads();
        #pragma unroll
        for (int k = 0; k < 32; k++) {
            float xr[4], war[4], wbr[4];
            #pragma unroll
            for (int i = 0; i < 4; i++) xr[i] = Xs[k][ty*4 + i];
            #pragma unroll
            for (int j = 0; j < 4; j++) { war[j] = Was[k][tx*4 + j]; wbr[j] = Wbs[k][tx*4 + j]; }
            #pragma unroll
            for (int i = 0; i < 4; i++)
                #pragma unroll
                for (int j = 0; j < 4; j++) {
                    a0[i][j] = fmaf(xr[i], war[j], a0[i][j]);
                    a1[i][j] = fmaf(xr[i], wbr[j], a1[i][j]);
                }
        }
        __syncthreads();
    }
    #pragma unroll
    for (int i = 0; i < 4; i++) {
        int row = m0 + ty*4 + i;
        #pragma unroll
        for (int j = 0; j < 4; j++) {
            int col = n0 + tx*4 + j;
            g_Z0[(size_t)row * DD + col] = a0[i][j];
            g_Z1[(size_t)row * DD + col] = a1[i][j];
        }
    }
}

// ---------------------------------------------------------------------------
// 4) Scan v6 (R13: 119us): 16-step blocks, bulk-staged z0/x, z1 pipelined.
// ---------------------------------------------------------------------------
#define SC_STEPS 16
#define SC_HALF  (SC_STEPS*DD*4)
#define SC_BUF   (2*SC_HALF)
#define SC_STAGE0 9216
#define SC_SMEM  (SC_STAGE0 + 2*SC_BUF)
#define PART_IDX(ph, s, w, c)  (((ph)*SC_STEPS + (s))*68 + (w)*4 + (c))

__global__ void __launch_bounds__(512) k_scan(const float* __restrict__ fw_init,
                                              const float* __restrict__ eta_p) {
    extern __shared__ __align__(1024) char smem[];
    uint32_t sb = smem_u32(smem);
    float* part = (float*)(smem + 64);

    int tid  = threadIdx.x;
    int wid  = tid >> 5;
    int lane = tid & 31;
    int r4   = lane >> 2;
    int col  = lane & 3;
    int j0   = blockIdx.x * 4;
    int j    = j0 + col;
    int row0 = wid * 32 + r4 * 4;
    float eta = *eta_p;

    if (tid == 0) { MBAR_INIT(sb, 1); MBAR_INIT(sb + 8, 1); }
    __syncthreads();

    auto issue = [&](int b) {
        uint32_t mb  = sb + (b & 1) * 8;
        uint32_t dst = sb + SC_STAGE0 + (b & 1) * SC_BUF;
        MBAR_EXPECT_TX(mb, SC_BUF);
        bulk_cp(dst,           g_Z0 + (size_t)b * SC_STEPS * DD, SC_HALF, mb);
        bulk_cp(dst + SC_HALF, g_X  + (size_t)b * SC_STEPS * DD, SC_HALF, mb);
    };
    if (tid == 0) { issue(0); issue(1); }

    float fw[4];
    #pragma unroll
    for (int g = 0; g < 4; g++)
        fw[g] = fw_init[(size_t)(row0 + g) * DD + j];

    float z1cur[SC_STEPS];
    #pragma unroll
    for (int s = 0; s < SC_STEPS; s++)
        z1cur[s] = __ldg(&g_Z1[(size_t)s * DD + j]);

    const int NB = TT / SC_STEPS;
    for (int b = 0; b < NB; b++) {
        int tb = b * SC_STEPS;
        float z1nxt[SC_STEPS];
        if (b + 1 < NB) {
            #pragma unroll
            for (int s = 0; s < SC_STEPS; s++)
                z1nxt[s] = __ldg(&g_Z1[(size_t)(tb + SC_STEPS + s) * DD + j]);
        }

        mbar_wait(sb + (b & 1) * 8, (b >> 1) & 1);
        uint32_t base = sb + SC_STAGE0 + (b & 1) * SC_BUF;

        float yb[SC_STEPS];
        #pragma unroll
        for (int s = 0; s < SC_STEPS; s++) {
            float4 z0v, xv;
            asm volatile("ld.shared.v4.f32 {%0,%1,%2,%3}, [%4];"
                         : "=f"(z0v.x), "=f"(z0v.y), "=f"(z0v.z), "=f"(z0v.w)
                         : "r"(base + (uint32_t)(s * DD + row0) * 4));
            asm volatile("ld.shared.v4.f32 {%0,%1,%2,%3}, [%4];"
                         : "=f"(xv.x), "=f"(xv.y), "=f"(xv.z), "=f"(xv.w)
                         : "r"(base + SC_HALF + (uint32_t)(s * DD + row0) * 4));
            float p = eta * z1cur[s];
            float t0 = tanh_fast(fmaf(z0v.x, p, fw[0]));
            float t1 = tanh_fast(fmaf(z0v.y, p, fw[1]));
            float t2 = tanh_fast(fmaf(z0v.z, p, fw[2]));
            float t3 = tanh_fast(fmaf(z0v.w, p, fw[3]));
            fw[0] = t0; fw[1] = t1; fw[2] = t2; fw[3] = t3;
            yb[s] = fmaf(xv.x, t0, fmaf(xv.y, t1, fmaf(xv.z, t2, xv.w * t3)));
        }
        #pragma unroll
        for (int off = 16; off >= 4; off >>= 1)
            #pragma unroll
            for (int s = 0; s < SC_STEPS; s++)
                yb[s] += __shfl_xor_sync(0xffffffffu, yb[s], off);
        int ph = b & 1;
        if (lane < 4) {
            #pragma unroll
            for (int s = 0; s < SC_STEPS; s++)
                part[PART_IDX(ph, s, wid, lane)] = yb[s];
        }
        __syncthreads();
        if (tid == 0 && b + 2 < NB) issue(b + 2);
        if (tid < 64) {
            int s = tid >> 2, c = tid & 3;
            float y = 0.f;
            #pragma unroll
            for (int w = 0; w < 16; w++)
                y += part[PART_IDX(ph, s, w, c)];
            g_Y[(size_t)(tb + s) * DD + j0 + c] = y;
        }
        #pragma unroll
        for (int s = 0; s < SC_STEPS; s++)
            z1cur[s] = z1nxt[s];
    }
}

// ---------------------------------------------------------------------------
// 5) MLP + mix; epilogue emits chunk-major swizzled bf16 hi/lo of "mixed"
// ---------------------------------------------------------------------------
__global__ void k_mlp(const float* __restrict__ aw, const float* __restrict__ ab,
                      const float* __restrict__ bw, const float* __restrict__ bb) {
    __shared__ float ys[DD];
    __shared__ float hs[HH];
    int t = blockIdx.x, tid = threadIdx.x;
    for (int d = tid; d < DD; d += 256) ys[d] = g_Y[(size_t)t * DD + d];
    __syncthreads();
    int w = tid >> 5, lane = tid & 31;
    for (int u = w; u < HH; u += 8) {
        float acc = 0.f;
        #pragma unroll
        for (int k = 0; k < 16; k++) {
            int d = lane + 32*k;
            acc = fmaf(ys[d], aw[(size_t)d * HH + u], acc);
        }
        #pragma unroll
        for (int off = 16; off; off >>= 1)
            acc += __shfl_xor_sync(0xffffffffu, acc, off);
        if (lane == 0) {
            float hv = acc + ab[u];
            const float SC = 1.0507009873554805f, AL = 1.6732632423543772f;
            hs[u] = hv > 0.f ? SC * hv : SC * AL * expm1f(hv);
        }
    }
    __syncthreads();
    char* ah = (char*)g_Ahic;
    char* al = (char*)g_Aloc;
    for (int j = tid; j < DD; j += 256) {
        float o = bb[j];
        #pragma unroll
        for (int k = 0; k < HH; k++)
            o = fmaf(hs[k], bw[(size_t)k * DD + j], o);
        float mx = 0.5f * o + 0.5f * g_X[(size_t)t * DD + j];
        __nv_bfloat16 hi = __float2bfloat16_rn(mx);
        __nv_bfloat16 lo = __float2bfloat16_rn(mx - __bfloat162float(hi));
        size_t g = (((size_t)(j >> 6) * TT + t) * 64 + (j & 63)) * 2;
        size_t sw = g ^ ((g >> 3) & 0x70);
        *(__nv_bfloat16*)(ah + sw) = hi;
        *(__nv_bfloat16*)(al + sw) = lo;
    }
}

// ---------------------------------------------------------------------------
// 6) Head GEMM + fused softmax tile-stats epilogue.
//    After logits: per-(row, 128-col tile) max and sum-exp computed in the
//    epilogue (quad shfl + smem two-stage, reusing staging smem) ->
//    g_pm/g_ps. Removes k_softmax's 131MB logit re-read.
// ---------------------------------------------------------------------------
#define TILE_B   16384
#define CH_B     (4*TILE_B)
#define HEAD_SMEM (1024 + 3*CH_B)

__global__ void __launch_bounds__(512, 1) k_head(const float* __restrict__ bias,
                                                 float* __restrict__ out) {
    extern __shared__ __align__(1024) char smem[];
    uint32_t sb = smem_u32(smem);
    int tid  = threadIdx.x;
    int wid  = tid >> 5;
    int lane = tid & 31;
    int grp  = lane >> 2;
    int t4   = lane & 3;
    int m0 = blockIdx.x * 128;
    int n0 = blockIdx.y * 128;
    int wm = wid & 3;
    int wn = wid >> 2;

    if (tid == 0) { MBAR_INIT(sb, 1); MBAR_INIT(sb + 8, 1); MBAR_INIT(sb + 16, 1); }
    __syncthreads();

    const char* gAh = (const char*)g_Ahic;
    const char* gAl = (const char*)g_Aloc;
    const char* gBh = (const char*)g_Bhic;
    const char* gBl = (const char*)g_Bloc;

    auto issue = [&](int c) {
        int buf = c % 3;
        uint32_t mb  = sb + buf * 8;
        uint32_t dst = sb + 1024 + buf * CH_B;
        MBAR_EXPECT_TX(mb, CH_B);
        size_t aoff = ((size_t)c * TT + m0) * 128;
        size_t boff = ((size_t)c * VV + n0) * 128;
        bulk_cp(dst,            gAh + aoff, TILE_B, mb);
        bulk_cp(dst +   TILE_B, gAl + aoff, TILE_B, mb);
        bulk_cp(dst + 2*TILE_B, gBh + boff, TILE_B, mb);
        bulk_cp(dst + 3*TILE_B, gBl + boff, TILE_B, mb);
    };
    if (tid == 0) { issue(0); issue(1); issue(2); }

    float acc[2][4][4] = {};

    uint32_t aRow  = (uint32_t)(wm*32 + (lane & 15));
    uint32_t aByte = aRow * 128;
    uint32_t aXor  = (aRow & 7) << 4;
    uint32_t aKb   = (uint32_t)((lane >> 4) * 16);
    uint32_t bRow  = (uint32_t)(wn*32 + (lane & 7) + ((lane >> 4) & 1) * 8);
    uint32_t bByte = bRow * 128;
    uint32_t bXor  = (bRow & 7) << 4;
    uint32_t bKb   = (uint32_t)(((lane >> 3) & 1) * 16);

    for (int c = 0; c < 8; c++) {
        mbar_wait(sb + (c % 3) * 8, (c / 3) & 1);
        uint32_t base = sb + 1024 + (c % 3) * CH_B;
        uint32_t pAh = base;
        uint32_t pAl = base + TILE_B;
        uint32_t pBh = base + 2*TILE_B;
        uint32_t pBl = base + 3*TILE_B;

        #pragma unroll
        for (int ks = 0; ks < 4; ks++) {
            uint32_t ka = ((uint32_t)(ks*32) + aKb) ^ aXor;
            uint32_t kb = ((uint32_t)(ks*32) + bKb) ^ bXor;
            unsigned ah[2][4], al[2][4], bh[4][2], bl[4][2];
            #pragma unroll
            for (int mi = 0; mi < 2; mi++) {
                ldsm4(ah[mi], pAh + aByte + mi*2048 + ka);
                ldsm4(al[mi], pAl + aByte + mi*2048 + ka);
            }
            #pragma unroll
            for (int p = 0; p < 2; p++) {
                unsigned tmp[4];
                ldsm4(tmp, pBh + bByte + p*2048 + kb);
                bh[p*2][0] = tmp[0]; bh[p*2][1] = tmp[1];
                bh[p*2+1][0] = tmp[2]; bh[p*2+1][1] = tmp[3];
                ldsm4(tmp, pBl + bByte + p*2048 + kb);
                bl[p*2][0] = tmp[0]; bl[p*2][1] = tmp[1];
                bl[p*2+1][0] = tmp[2]; bl[p*2+1][1] = tmp[3];
            }
            #pragma unroll
            for (int mi = 0; mi < 2; mi++)
                #pragma unroll
                for (int ni = 0; ni < 4; ni++) {
                    mma16816(acc[mi][ni], ah[mi], bh[ni]);
                    mma16816(acc[mi][ni], ah[mi], bl[ni]);
                    mma16816(acc[mi][ni], al[mi], bh[ni]);
                }
        }
        __syncthreads();
        if (tid == 0 && c + 3 < 8) issue(c + 3);
    }

    // ---- epilogue: bias into acc, store logits ----
    #pragma unroll
    for (int mi = 0; mi < 2; mi++) {
        #pragma unroll
        for (int ni = 0; ni < 4; ni++) {
            int col = n0 + wn * 32 + ni * 8 + t4 * 2;
            float2 bv = *(const float2*)&bias[col];
            acc[mi][ni][0] += bv.x; acc[mi][ni][1] += bv.y;
            acc[mi][ni][2] += bv.x; acc[mi][ni][3] += bv.y;
        }
    }
    #pragma unroll
    for (int mi = 0; mi < 2; mi++) {
        int r0 = m0 + wm * 32 + mi * 16 + grp;
        #pragma unroll
        for (int ni = 0; ni < 4; ni++) {
            int col = n0 + wn * 32 + ni * 8 + t4 * 2;
            *(float2*)&out[(size_t)r0       * VV + col] = *(float2*)&acc[mi][ni][0];
            *(float2*)&out[(size_t)(r0 + 8) * VV + col] = *(float2*)&acc[mi][ni][2];
        }
    }

    // ---- fused softmax tile stats (staging smem is free now) ----
    float* red = (float*)(smem + 1024);       // [128 rows][4 wn]
    float* gm  = red + 512;                   // [128]
    float* rs  = gm + 128;                    // [128][4]
    __syncthreads();                          // all bulk reads of smem done

    // per-thread per-row max over its 8 cols; rows: (mi, h) -> wm*32+mi*16+h*8+grp
    float rmax[2][2];
    #pragma unroll
    for (int mi = 0; mi < 2; mi++) {
        float m0v = -INFINITY, m1v = -INFINITY;
        #pragma unroll
        for (int ni = 0; ni < 4; ni++) {
            m0v = fmaxf(m0v, fmaxf(acc[mi][ni][0], acc[mi][ni][1]));
            m1v = fmaxf(m1v, fmaxf(acc[mi][ni][2], acc[mi][ni][3]));
        }
        rmax[mi][0] = m0v; rmax[mi][1] = m1v;
    }
    #pragma unroll
    for (int off = 1; off <= 2; off <<= 1)
        #pragma unroll
        for (int mi = 0; mi < 2; mi++)
            #pragma unroll
            for (int h = 0; h < 2; h++)
                rmax[mi][h] = fmaxf(rmax[mi][h], __shfl_xor_sync(0xffffffffu, rmax[mi][h], off));
    if (t4 == 0) {
        #pragma unroll
        for (int mi = 0; mi < 2; mi++)
            #pragma unroll
            for (int h = 0; h < 2; h++)
                red[(wm*32 + mi*16 + h*8 + grp) * 4 + wn] = rmax[mi][h];
    }
    __syncthreads();
    if (tid < 128)
        gm[tid] = fmaxf(fmaxf(red[tid*4], red[tid*4+1]), fmaxf(red[tid*4+2], red[tid*4+3]));
    __syncthreads();

    float rsum[2][2];
    #pragma unroll
    for (int mi = 0; mi < 2; mi++) {
        float g0 = gm[wm*32 + mi*16 + grp];
        float g1 = gm[wm*32 + mi*16 + 8 + grp];
        float s0 = 0.f, s1 = 0.f;
        #pragma unroll
        for (int ni = 0; ni < 4; ni++) {
            s0 += __expf(acc[mi][ni][0] - g0) + __expf(acc[mi][ni][1] - g0);
            s1 += __expf(acc[mi][ni][2] - g1) + __expf(acc[mi][ni][3] - g1);
        }
        rsum[mi][0] = s0; rsum[mi][1] = s1;
    }
    #pragma unroll
    for (int off = 1; off <= 2; off <<= 1)
        #pragma unroll
        for (int mi = 0; mi < 2; mi++)
            #pragma unroll
            for (int h = 0; h < 2; h++)
                rsum[mi][h] += __shfl_xor_sync(0xffffffffu, rsum[mi][h], off);
    if (t4 == 0) {
        #pragma unroll
        for (int mi = 0; mi < 2; mi++)
            #pragma unroll
            for (int h = 0; h < 2; h++)
                rs[(wm*32 + mi*16 + h*8 + grp) * 4 + wn] = rsum[mi][h];
    }
    __syncthreads();
    if (tid < 128) {
        float s = rs[tid*4] + rs[tid*4+1] + rs[tid*4+2] + rs[tid*4+3];
        size_t o = (size_t)(m0 + tid) * NTILES + blockIdx.y;
        g_pm[o] = gm[tid];
        g_ps[o] = s;
    }
}

// ---------------------------------------------------------------------------
// 7) finalize: merge 250 tile stats per row -> rowloss; 8) mean
// ---------------------------------------------------------------------------
__global__ void __launch_bounds__(128) k_finalize(const float* __restrict__ logits,
                                                  const int* __restrict__ targets) {
    __shared__ float sm[128], ss[128];
    int t = blockIdx.x, tid = threadIdx.x;
    float m = -INFINITY, s = 0.f;
    for (int i = tid; i < NTILES; i += 128) {
        float pm = g_pm[(size_t)t * NTILES + i];
        float ps = g_ps[(size_t)t * NTILES + i];
        if (pm > m) { s = s * __expf(m - pm) + ps; m = pm; }
        else        { s += ps * __expf(pm - m); }
    }
    sm[tid] = m; ss[tid] = s; __syncthreads();
    for (int st = 64; st; st >>= 1) {
        if (tid < st) {
            float m2 = fmaxf(sm[tid], sm[tid + st]);
            ss[tid] = ss[tid] * __expf(sm[tid] - m2) + ss[tid + st] * __expf(sm[tid + st] - m2);
            sm[tid] = m2;
        }
        __syncthreads();
    }
    if (tid == 0)
        g_rowloss[t] = logits[(size_t)t * VV + targets[t]] - sm[0] - logf(ss[0]);
}

__global__ void k_loss(float* __restrict__ out) {
    __shared__ float red[256];
    int tid = threadIdx.x;
    float s = 0.f;
    for (int t = tid; t < TT; t += 256) s += g_rowloss[t];
    red[tid] = s; __syncthreads();
    for (int st = 128; st; st >>= 1) { if (tid < st) red[tid] += red[tid+st]; __syncthreads(); }
    if (tid == 0) out[0] = -red[0] / (float)TT;
}

// ---------------------------------------------------------------------------
extern "C" void kernel_launch(void* const* d_in, const int* in_sizes, int n_in,
                              void* d_out, int out_size) {
    const int*   tokens  = (const int*)  d_in[0];
    const int*   targets = (const int*)  d_in[1];
    const float* embed   = (const float*)d_in[2];
    const float* fw_init = (const float*)d_in[3];
    const float* eta     = (const float*)d_in[4];
    const float* wa      = (const float*)d_in[5];
    const float* wb      = (const float*)d_in[6];
    const float* mlp_aw  = (const float*)d_in[7];
    const float* mlp_ab  = (const float*)d_in[8];
    const float* mlp_bw  = (const float*)d_in[9];
    const float* mlp_bb  = (const float*)d_in[10];
    const float* head_w  = (const float*)d_in[11];
    const float* head_b  = (const float*)d_in[12];
    float* out = (float*)d_out;

    static int smem_set = 0;
    if (!smem_set) {
        cudaFuncSetAttribute(k_head, cudaFuncAttributeMaxDynamicSharedMemorySize, HEAD_SMEM);
        cudaFuncSetAttribute(k_scan, cudaFuncAttributeMaxDynamicSharedMemorySize, SC_SMEM);
        smem_set = 1;
    }

    k_gather<<<(TT*DD + 255) / 256, 256>>>(tokens, embed);
    k_convB<<<dim3(VV/64, DD/64), 256>>>(head_w);
    k_zgemm<<<dim3(DD/64, TT/64), 256>>>(wa, wb);
    k_scan<<<DD/4, 512, SC_SMEM>>>(fw_init, eta);   // ncu slot 4
    k_mlp<<<TT, 256>>>(mlp_aw, mlp_ab, mlp_bw, mlp_bb);
    k_head<<<dim3(TT/128, VV/128), 512, HEAD_SMEM>>>(head_b, out);
    k_finalize<<<TT, 128>>>(out, targets);
    if (out_size >= TT*VV + 1)
        k_loss<<<1, 256>>>(out + (size_t)TT*VV);
}

// round 16
// speedup vs baseline: 6.1109x; 1.0975x over previous
#include <cuda_runtime.h>
#include <cuda_fp16.h>
#include <cuda_bf16.h>
#include <math.h>
#include <stdint.h>

#define DD 512
#define HH 20
#define VV 32000
#define TT 1024
#define NTILES (VV/128)

// Scratch (allocation-free rule: __device__ globals)
__device__ float g_X [TT*DD];
__device__ float g_Z0[TT*DD];
__device__ float g_Z1[TT*DD];
__device__ float g_Y [TT*DD];
__device__ float g_rowloss[TT];
__device__ float g_pm[TT*NTILES];
__device__ float g_ps[TT*NTILES];
__device__ unsigned g_bar;          // grid barrier (monotonic, mod-128)
// Chunk-major, pre-swizzled fp16 operands for the head GEMM.
// Element (row, k): g = ((kc*ROWS + row)*64 + kk)*2, stored at g ^ ((g>>3)&0x70).
__device__ __half g_Ah [TT*DD];                 // mixed, single fp16
__device__ __half g_Bhi[(size_t)VV*DD];         // head_w^T hi
__device__ __half g_Blo[(size_t)VV*DD];         // head_w^T lo

// ---------------------------------------------------------------------------
// PTX helpers
// ---------------------------------------------------------------------------
__device__ __forceinline__ uint32_t smem_u32(const void* p) {
    uint32_t a;
    asm("{ .reg .u64 t; cvta.to.shared.u64 t, %1; cvt.u32.u64 %0, t; }" : "=r"(a) : "l"(p));
    return a;
}
#define MBAR_INIT(a, c) asm volatile("mbarrier.init.shared.b64 [%0], %1;" :: "r"(a), "r"(c) : "memory")
#define MBAR_EXPECT_TX(a, b) \
    asm volatile("mbarrier.arrive.expect_tx.shared.b64 _, [%0], %1;" :: "r"(a), "r"(b) : "memory")
__device__ __forceinline__ void mbar_wait(uint32_t mbar, uint32_t parity) {
    uint32_t done;
    asm volatile("{ .reg .pred p; mbarrier.try_wait.parity.acquire.cta.shared::cta.b64 p, [%1], %2; selp.b32 %0,1,0,p; }"
                 : "=r"(done) : "r"(mbar), "r"(parity) : "memory");
    if (!done) {
        asm volatile("{ .reg .pred P1;\nWL_%=:\n"
                     "mbarrier.try_wait.parity.acquire.cta.shared::cta.b64 P1, [%0], %1, 0x989680;\n"
                     "@P1 bra.uni WD_%=;\n bra.uni WL_%=;\nWD_%=:\n}"
                     :: "r"(mbar), "r"(parity) : "memory");
    }
}
__device__ __forceinline__ void bulk_cp(uint32_t dst, const void* gsrc,
                                        uint32_t bytes, uint32_t mbar) {
    asm volatile("cp.async.bulk.shared::cluster.global.mbarrier::complete_tx::bytes [%0], [%1], %2, [%3];"
                 :: "r"(dst), "l"(__cvta_generic_to_global(gsrc)), "r"(bytes), "r"(mbar) : "memory");
}
__device__ __forceinline__ void ldsm4(unsigned r[4], uint32_t addr) {
    asm volatile("ldmatrix.sync.aligned.m8n8.x4.shared.b16 {%0,%1,%2,%3}, [%4];"
                 : "=r"(r[0]), "=r"(r[1]), "=r"(r[2]), "=r"(r[3]) : "r"(addr));
}
__device__ __forceinline__ void mma_h(float c[4], const unsigned a[4], const unsigned b[2]) {
    asm volatile(
        "mma.sync.aligned.m16n8k16.row.col.f32.f16.f16.f32 "
        "{%0,%1,%2,%3}, {%4,%5,%6,%7}, {%8,%9}, {%0,%1,%2,%3};\n"
        : "+f"(c[0]), "+f"(c[1]), "+f"(c[2]), "+f"(c[3])
        : "r"(a[0]), "r"(a[1]), "r"(a[2]), "r"(a[3]), "r"(b[0]), "r"(b[1]));
}
__device__ __forceinline__ float tanh_fast(float v) {
    float r;
    asm("tanh.approx.f32 %0, %1;" : "=f"(r) : "f"(v));
    return r;
}

// ---------------------------------------------------------------------------
// 1) k_prep: blocks [0,4000): head_w transpose + fp16 hi/lo split (chunk-major
//    swizzled); blocks [4000,6048): X = embed[tokens]
// ---------------------------------------------------------------------------
__global__ void __launch_bounds__(256) k_prep(const int* __restrict__ tokens,
                                              const float* __restrict__ embed,
                                              const float* __restrict__ W) {
    __shared__ float tile[64][65];
    int bid = blockIdx.x;
    int tid = threadIdx.x;
    if (bid < 4000) {
        int n0 = (bid % 500) * 64;
        int k0 = (bid / 500) * 64;
        #pragma unroll
        for (int i = 0; i < 16; i++) {
            int f = tid + 256 * i;
            int k = f >> 6, n = f & 63;
            tile[k][n] = W[(size_t)(k0 + k) * VV + n0 + n];
        }
        __syncthreads();
        size_t kc = (size_t)(k0 >> 6);
        char* bh = (char*)g_Bhi;
        char* bl = (char*)g_Blo;
        #pragma unroll
        for (int i = 0; i < 16; i++) {
            int f = tid + 256 * i;
            int n = f >> 6, kk = f & 63;
            float v = tile[kk][n];
            __half hi = __float2half(v);
            __half lo = __float2half(v - __half2float(hi));
            size_t g = ((kc * VV + (n0 + n)) * 64 + kk) * 2;
            size_t sw = g ^ ((g >> 3) & 0x70);
            *(__half*)(bh + sw) = hi;
            *(__half*)(bl + sw) = lo;
        }
    } else {
        int idx = (bid - 4000) * 256 + tid;
        if (idx < TT * DD) {
            int t = idx >> 9, d = idx & 511;
            g_X[idx] = embed[(size_t)tokens[t] * DD + d];
        }
    }
}

// ---------------------------------------------------------------------------
// 2) Z0 = X @ wa, Z1 = X @ wb  (K-step 32)
// ---------------------------------------------------------------------------
__global__ void __launch_bounds__(256) k_zgemm(const float* __restrict__ wa,
                                               const float* __restrict__ wb) {
    __shared__ float Xs [32][64];
    __shared__ float Was[32][64];
    __shared__ float Wbs[32][64];
    int tid = threadIdx.x;
    int n0 = blockIdx.x * 64;
    int m0 = blockIdx.y * 64;
    int ty = tid >> 4, tx = tid & 15;
    float a0[4][4] = {}, a1[4][4] = {};

    for (int k0 = 0; k0 < DD; k0 += 32) {
        #pragma unroll
        for (int q = 0; q < 2; q++) {
            int f = tid + 256 * q;
            int m  = f >> 3;
            int kq = (f & 7) * 4;
            float4 v = *(const float4*)&g_X[(size_t)(m0 + m) * DD + k0 + kq];
            Xs[kq+0][m] = v.x; Xs[kq+1][m] = v.y; Xs[kq+2][m] = v.z; Xs[kq+3][m] = v.w;
        }
        #pragma unroll
        for (int q = 0; q < 2; q++) {
            int f = tid + 256 * q;
            int k  = f >> 4;
            int nq = (f & 15) * 4;
            *(float4*)&Was[k][nq] = *(const float4*)&wa[(size_t)(k0 + k) * DD + n0 + nq];
            *(float4*)&Wbs[k][nq] = *(const float4*)&wb[(size_t)(k0 + k) * DD + n0 + nq];
        }
        __syncthreads();
        #pragma unroll
        for (int k = 0; k < 32; k++) {
            float xr[4], war[4], wbr[4];
            #pragma unroll
            for (int i = 0; i < 4; i++) xr[i] = Xs[k][ty*4 + i];
            #pragma unroll
            for (int j = 0; j < 4; j++) { war[j] = Was[k][tx*4 + j]; wbr[j] = Wbs[k][tx*4 + j]; }
            #pragma unroll
            for (int i = 0; i < 4; i++)
                #pragma unroll
                for (int j = 0; j < 4; j++) {
                    a0[i][j] = fmaf(xr[i], war[j], a0[i][j]);
                    a1[i][j] = fmaf(xr[i], wbr[j], a1[i][j]);
                }
        }
        __syncthreads();
    }
    #pragma unroll
    for (int i = 0; i < 4; i++) {
        int row = m0 + ty*4 + i;
        #pragma unroll
        for (int j = 0; j < 4; j++) {
            int col = n0 + tx*4 + j;
            g_Z0[(size_t)row * DD + col] = a0[i][j];
            g_Z1[(size_t)row * DD + col] = a1[i][j];
        }
    }
}

// ---------------------------------------------------------------------------
// 3) Fused scan (v6) + grid barrier + MLP. 128 CTAs x 512 threads
//    (always <= 1 CTA/SM -> all co-resident; R7-proven barrier pattern).
//    Phase B emits single-fp16 A in chunk-major swizzled layout.
// ---------------------------------------------------------------------------
#define SC_STEPS 16
#define SC_HALF  (SC_STEPS*DD*4)
#define SC_BUF   (2*SC_HALF)
#define SC_STAGE0 9216
#define SC_SMEM  (SC_STAGE0 + 2*SC_BUF)
#define PART_IDX(ph, s, w, c)  (((ph)*SC_STEPS + (s))*68 + (w)*4 + (c))

__global__ void __launch_bounds__(512) k_scanmlp(
        const float* __restrict__ fw_init, const float* __restrict__ eta_p,
        const float* __restrict__ aw, const float* __restrict__ ab,
        const float* __restrict__ bw, const float* __restrict__ bb) {
    extern __shared__ __align__(1024) char smem[];
    uint32_t sb = smem_u32(smem);
    float* part = (float*)(smem + 64);

    int tid  = threadIdx.x;
    int wid  = tid >> 5;
    int lane = tid & 31;
    int bid  = blockIdx.x;

    // ================= Phase A: scan =================
    {
        int r4   = lane >> 2;
        int col  = lane & 3;
        int j0   = bid * 4;
        int j    = j0 + col;
        int row0 = wid * 32 + r4 * 4;
        float eta = *eta_p;

        if (tid == 0) { MBAR_INIT(sb, 1); MBAR_INIT(sb + 8, 1); }
        __syncthreads();

        auto issue = [&](int b) {
            uint32_t mb  = sb + (b & 1) * 8;
            uint32_t dst = sb + SC_STAGE0 + (b & 1) * SC_BUF;
            MBAR_EXPECT_TX(mb, SC_BUF);
            bulk_cp(dst,           g_Z0 + (size_t)b * SC_STEPS * DD, SC_HALF, mb);
            bulk_cp(dst + SC_HALF, g_X  + (size_t)b * SC_STEPS * DD, SC_HALF, mb);
        };
        if (tid == 0) { issue(0); issue(1); }

        float fw[4];
        #pragma unroll
        for (int g = 0; g < 4; g++)
            fw[g] = fw_init[(size_t)(row0 + g) * DD + j];

        float z1cur[SC_STEPS];
        #pragma unroll
        for (int s = 0; s < SC_STEPS; s++)
            z1cur[s] = __ldg(&g_Z1[(size_t)s * DD + j]);

        const int NB = TT / SC_STEPS;
        for (int b = 0; b < NB; b++) {
            int tb = b * SC_STEPS;
            float z1nxt[SC_STEPS];
            if (b + 1 < NB) {
                #pragma unroll
                for (int s = 0; s < SC_STEPS; s++)
                    z1nxt[s] = __ldg(&g_Z1[(size_t)(tb + SC_STEPS + s) * DD + j]);
            }

            mbar_wait(sb + (b & 1) * 8, (b >> 1) & 1);
            uint32_t base = sb + SC_STAGE0 + (b & 1) * SC_BUF;

            float yb[SC_STEPS];
            #pragma unroll
            for (int s = 0; s < SC_STEPS; s++) {
                float4 z0v, xv;
                asm volatile("ld.shared.v4.f32 {%0,%1,%2,%3}, [%4];"
                             : "=f"(z0v.x), "=f"(z0v.y), "=f"(z0v.z), "=f"(z0v.w)
                             : "r"(base + (uint32_t)(s * DD + row0) * 4));
                asm volatile("ld.shared.v4.f32 {%0,%1,%2,%3}, [%4];"
                             : "=f"(xv.x), "=f"(xv.y), "=f"(xv.z), "=f"(xv.w)
                             : "r"(base + SC_HALF + (uint32_t)(s * DD + row0) * 4));
                float p = eta * z1cur[s];
                float t0 = tanh_fast(fmaf(z0v.x, p, fw[0]));
                float t1 = tanh_fast(fmaf(z0v.y, p, fw[1]));
                float t2 = tanh_fast(fmaf(z0v.z, p, fw[2]));
                float t3 = tanh_fast(fmaf(z0v.w, p, fw[3]));
                fw[0] = t0; fw[1] = t1; fw[2] = t2; fw[3] = t3;
                yb[s] = fmaf(xv.x, t0, fmaf(xv.y, t1, fmaf(xv.z, t2, xv.w * t3)));
            }
            #pragma unroll
            for (int off = 16; off >= 4; off >>= 1)
                #pragma unroll
                for (int s = 0; s < SC_STEPS; s++)
                    yb[s] += __shfl_xor_sync(0xffffffffu, yb[s], off);
            int ph = b & 1;
            if (lane < 4) {
                #pragma unroll
                for (int s = 0; s < SC_STEPS; s++)
                    part[PART_IDX(ph, s, wid, lane)] = yb[s];
            }
            __syncthreads();
            if (tid == 0 && b + 2 < NB) issue(b + 2);
            if (tid < 64) {
                int s = tid >> 2, c = tid & 3;
                float y = 0.f;
                #pragma unroll
                for (int w = 0; w < 16; w++)
                    y += part[PART_IDX(ph, s, w, c)];
                g_Y[(size_t)(tb + s) * DD + j0 + c] = y;
            }
            #pragma unroll
            for (int s = 0; s < SC_STEPS; s++)
                z1cur[s] = z1nxt[s];
        }
    }

    // ============ Grid barrier (all 128 CTAs resident) ============
    __threadfence();
    __syncthreads();
    if (tid == 0) {
        atomicAdd(&g_bar, 1u);
        volatile unsigned* vb = &g_bar;
        while (*vb & 127u) { }
    }
    __syncthreads();
    __threadfence();

    // ================= Phase B: MLP + mix for 8 tokens =================
    {
        float* ys = (float*)(smem + 1024);
        float* hs = ys + DD;
        char* ahp = (char*)g_Ah;
        for (int it = 0; it < 8; it++) {
            int t = bid * 8 + it;
            ys[tid] = g_Y[(size_t)t * DD + tid];
            __syncthreads();
            for (int u = wid; u < HH; u += 16) {
                float acc = 0.f;
                #pragma unroll
                for (int k = 0; k < 16; k++) {
                    int d = lane + 32*k;
                    acc = fmaf(ys[d], aw[(size_t)d * HH + u], acc);
                }
                #pragma unroll
                for (int off = 16; off; off >>= 1)
                    acc += __shfl_xor_sync(0xffffffffu, acc, off);
                if (lane == 0) {
                    float hv = acc + ab[u];
                    const float SC = 1.0507009873554805f, AL = 1.6732632423543772f;
                    hs[u] = hv > 0.f ? SC * hv : SC * AL * expm1f(hv);
                }
            }
            __syncthreads();
            {
                int j = tid;
                float o = bb[j];
                #pragma unroll
                for (int k = 0; k < HH; k++)
                    o = fmaf(hs[k], bw[(size_t)k * DD + j], o);
                float mx = 0.5f * o + 0.5f * g_X[(size_t)t * DD + j];
                size_t g = (((size_t)(j >> 6) * TT + t) * 64 + (j & 63)) * 2;
                size_t sw = g ^ ((g >> 3) & 0x70);
                *(__half*)(ahp + sw) = __float2half(mx);
            }
            __syncthreads();
        }
    }
}

// ---------------------------------------------------------------------------
// 4) Head GEMM (fp16 2-MMA: A single, B hi/lo) + fused softmax tile stats.
//    4-stage bulk-TMA chunk pipeline (3 tiles/chunk = 48KB).
// ---------------------------------------------------------------------------
#define TILE_B   16384
#define CH_B     (3*TILE_B)          // A, Bhi, Blo
#define HEAD_SMEM (1024 + 4*CH_B)    // 197632

__global__ void __launch_bounds__(512, 1) k_head(const float* __restrict__ bias,
                                                 float* __restrict__ out) {
    extern __shared__ __align__(1024) char smem[];
    uint32_t sb = smem_u32(smem);
    int tid  = threadIdx.x;
    int wid  = tid >> 5;
    int lane = tid & 31;
    int grp  = lane >> 2;
    int t4   = lane & 3;
    int m0 = blockIdx.x * 128;
    int n0 = blockIdx.y * 128;
    int wm = wid & 3;
    int wn = wid >> 2;

    if (tid == 0) {
        MBAR_INIT(sb, 1); MBAR_INIT(sb + 8, 1);
        MBAR_INIT(sb + 16, 1); MBAR_INIT(sb + 24, 1);
    }
    __syncthreads();

    const char* gA  = (const char*)g_Ah;
    const char* gBh = (const char*)g_Bhi;
    const char* gBl = (const char*)g_Blo;

    auto issue = [&](int c) {
        int buf = c & 3;
        uint32_t mb  = sb + buf * 8;
        uint32_t dst = sb + 1024 + buf * CH_B;
        MBAR_EXPECT_TX(mb, CH_B);
        size_t aoff = ((size_t)c * TT + m0) * 128;
        size_t boff = ((size_t)c * VV + n0) * 128;
        bulk_cp(dst,            gA  + aoff, TILE_B, mb);
        bulk_cp(dst +   TILE_B, gBh + boff, TILE_B, mb);
        bulk_cp(dst + 2*TILE_B, gBl + boff, TILE_B, mb);
    };
    if (tid == 0) { issue(0); issue(1); issue(2); issue(3); }

    float acc[2][4][4] = {};

    uint32_t aRow  = (uint32_t)(wm*32 + (lane & 15));
    uint32_t aByte = aRow * 128;
    uint32_t aXor  = (aRow & 7) << 4;
    uint32_t aKb   = (uint32_t)((lane >> 4) * 16);
    uint32_t bRow  = (uint32_t)(wn*32 + (lane & 7) + ((lane >> 4) & 1) * 8);
    uint32_t bByte = bRow * 128;
    uint32_t bXor  = (bRow & 7) << 4;
    uint32_t bKb   = (uint32_t)(((lane >> 3) & 1) * 16);

    for (int c = 0; c < 8; c++) {
        mbar_wait(sb + (c & 3) * 8, (c >> 2) & 1);
        uint32_t base = sb + 1024 + (c & 3) * CH_B;
        uint32_t pA  = base;
        uint32_t pBh = base + TILE_B;
        uint32_t pBl = base + 2*TILE_B;

        #pragma unroll
        for (int ks = 0; ks < 4; ks++) {
            uint32_t ka = ((uint32_t)(ks*32) + aKb) ^ aXor;
            uint32_t kb = ((uint32_t)(ks*32) + bKb) ^ bXor;
            unsigned ah[2][4], bh[4][2], bl[4][2];
            #pragma unroll
            for (int mi = 0; mi < 2; mi++)
                ldsm4(ah[mi], pA + aByte + mi*2048 + ka);
            #pragma unroll
            for (int p = 0; p < 2; p++) {
                unsigned tmp[4];
                ldsm4(tmp, pBh + bByte + p*2048 + kb);
                bh[p*2][0] = tmp[0]; bh[p*2][1] = tmp[1];
                bh[p*2+1][0] = tmp[2]; bh[p*2+1][1] = tmp[3];
                ldsm4(tmp, pBl + bByte + p*2048 + kb);
                bl[p*2][0] = tmp[0]; bl[p*2][1] = tmp[1];
                bl[p*2+1][0] = tmp[2]; bl[p*2+1][1] = tmp[3];
            }
            #pragma unroll
            for (int mi = 0; mi < 2; mi++)
                #pragma unroll
                for (int ni = 0; ni < 4; ni++) {
                    mma_h(acc[mi][ni], ah[mi], bh[ni]);
                    mma_h(acc[mi][ni], ah[mi], bl[ni]);
                }
        }
        __syncthreads();
        if (tid == 0 && c + 4 < 8) issue(c + 4);
    }

    // ---- epilogue: bias, store logits ----
    #pragma unroll
    for (int mi = 0; mi < 2; mi++) {
        #pragma unroll
        for (int ni = 0; ni < 4; ni++) {
            int col = n0 + wn * 32 + ni * 8 + t4 * 2;
            float2 bv = *(const float2*)&bias[col];
            acc[mi][ni][0] += bv.x; acc[mi][ni][1] += bv.y;
            acc[mi][ni][2] += bv.x; acc[mi][ni][3] += bv.y;
        }
    }
    #pragma unroll
    for (int mi = 0; mi < 2; mi++) {
        int r0 = m0 + wm * 32 + mi * 16 + grp;
        #pragma unroll
        for (int ni = 0; ni < 4; ni++) {
            int col = n0 + wn * 32 + ni * 8 + t4 * 2;
            *(float2*)&out[(size_t)r0       * VV + col] = *(float2*)&acc[mi][ni][0];
            *(float2*)&out[(size_t)(r0 + 8) * VV + col] = *(float2*)&acc[mi][ni][2];
        }
    }

    // ---- fused softmax tile stats ----
    float* red = (float*)(smem + 1024);
    float* gm  = red + 512;
    float* rs  = gm + 128;
    __syncthreads();

    float rmax[2][2];
    #pragma unroll
    for (int mi = 0; mi < 2; mi++) {
        float m0v = -INFINITY, m1v = -INFINITY;
        #pragma unroll
        for (int ni = 0; ni < 4; ni++) {
            m0v = fmaxf(m0v, fmaxf(acc[mi][ni][0], acc[mi][ni][1]));
            m1v = fmaxf(m1v, fmaxf(acc[mi][ni][2], acc[mi][ni][3]));
        }
        rmax[mi][0] = m0v; rmax[mi][1] = m1v;
    }
    #pragma unroll
    for (int off = 1; off <= 2; off <<= 1)
        #pragma unroll
        for (int mi = 0; mi < 2; mi++)
            #pragma unroll
            for (int h = 0; h < 2; h++)
                rmax[mi][h] = fmaxf(rmax[mi][h], __shfl_xor_sync(0xffffffffu, rmax[mi][h], off));
    if (t4 == 0) {
        #pragma unroll
        for (int mi = 0; mi < 2; mi++)
            #pragma unroll
            for (int h = 0; h < 2; h++)
                red[(wm*32 + mi*16 + h*8 + grp) * 4 + wn] = rmax[mi][h];
    }
    __syncthreads();
    if (tid < 128)
        gm[tid] = fmaxf(fmaxf(red[tid*4], red[tid*4+1]), fmaxf(red[tid*4+2], red[tid*4+3]));
    __syncthreads();

    float rsum[2][2];
    #pragma unroll
    for (int mi = 0; mi < 2; mi++) {
        float g0 = gm[wm*32 + mi*16 + grp];
        float g1 = gm[wm*32 + mi*16 + 8 + grp];
        float s0 = 0.f, s1 = 0.f;
        #pragma unroll
        for (int ni = 0; ni < 4; ni++) {
            s0 += __expf(acc[mi][ni][0] - g0) + __expf(acc[mi][ni][1] - g0);
            s1 += __expf(acc[mi][ni][2] - g1) + __expf(acc[mi][ni][3] - g1);
        }
        rsum[mi][0] = s0; rsum[mi][1] = s1;
    }
    #pragma unroll
    for (int off = 1; off <= 2; off <<= 1)
        #pragma unroll
        for (int mi = 0; mi < 2; mi++)
            #pragma unroll
            for (int h = 0; h < 2; h++)
                rsum[mi][h] += __shfl_xor_sync(0xffffffffu, rsum[mi][h], off);
    if (t4 == 0) {
        #pragma unroll
        for (int mi = 0; mi < 2; mi++)
            #pragma unroll
            for (int h = 0; h < 2; h++)
                rs[(wm*32 + mi*16 + h*8 + grp) * 4 + wn] = rsum[mi][h];
    }
    __syncthreads();
    if (tid < 128) {
        float s = rs[tid*4] + rs[tid*4+1] + rs[tid*4+2] + rs[tid*4+3];
        size_t o = (size_t)(m0 + tid) * NTILES + blockIdx.y;
        g_pm[o] = gm[tid];
        g_ps[o] = s;
    }
}

// ---------------------------------------------------------------------------
// 5) finalize: merge 250 tile stats per row -> rowloss; 6) mean
// ---------------------------------------------------------------------------
__global__ void __launch_bounds__(128) k_finalize(const float* __restrict__ logits,
                                                  const int* __restrict__ targets) {
    __shared__ float sm[128], ss[128];
    int t = blockIdx.x, tid = threadIdx.x;
    float m = -INFINITY, s = 0.f;
    for (int i = tid; i < NTILES; i += 128) {
        float pm = g_pm[(size_t)t * NTILES + i];
        float ps = g_ps[(size_t)t * NTILES + i];
        if (pm > m) { s = s * __expf(m - pm) + ps; m = pm; }
        else        { s += ps * __expf(pm - m); }
    }
    sm[tid] = m; ss[tid] = s; __syncthreads();
    for (int st = 64; st; st >>= 1) {
        if (tid < st) {
            float m2 = fmaxf(sm[tid], sm[tid + st]);
            ss[tid] = ss[tid] * __expf(sm[tid] - m2) + ss[tid + st] * __expf(sm[tid + st] - m2);
            sm[tid] = m2;
        }
        __syncthreads();
    }
    if (tid == 0)
        g_rowloss[t] = logits[(size_t)t * VV + targets[t]] - sm[0] - logf(ss[0]);
}

__global__ void k_loss(float* __restrict__ out) {
    __shared__ float red[256];
    int tid = threadIdx.x;
    float s = 0.f;
    for (int t = tid; t < TT; t += 256) s += g_rowloss[t];
    red[tid] = s; __syncthreads();
    for (int st = 128; st; st >>= 1) { if (tid < st) red[tid] += red[tid+st]; __syncthreads(); }
    if (tid == 0) out[0] = -red[0] / (float)TT;
}

// ---------------------------------------------------------------------------
extern "C" void kernel_launch(void* const* d_in, const int* in_sizes, int n_in,
                              void* d_out, int out_size) {
    const int*   tokens  = (const int*)  d_in[0];
    const int*   targets = (const int*)  d_in[1];
    const float* embed   = (const float*)d_in[2];
    const float* fw_init = (const float*)d_in[3];
    const float* eta     = (const float*)d_in[4];
    const float* wa      = (const float*)d_in[5];
    const float* wb      = (const float*)d_in[6];
    const float* mlp_aw  = (const float*)d_in[7];
    const float* mlp_ab  = (const float*)d_in[8];
    const float* mlp_bw  = (const float*)d_in[9];
    const float* mlp_bb  = (const float*)d_in[10];
    const float* head_w  = (const float*)d_in[11];
    const float* head_b  = (const float*)d_in[12];
    float* out = (float*)d_out;

    static int smem_set = 0;
    if (!smem_set) {
        cudaFuncSetAttribute(k_head, cudaFuncAttributeMaxDynamicSharedMemorySize, HEAD_SMEM);
        cudaFuncSetAttribute(k_scanmlp, cudaFuncAttributeMaxDynamicSharedMemorySize, SC_SMEM);
        smem_set = 1;
    }

    k_prep<<<4000 + (TT*DD + 255) / 256, 256>>>(tokens, embed, head_w);
    k_zgemm<<<dim3(DD/64, TT/64), 256>>>(wa, wb);
    k_scanmlp<<<DD/4, 512, SC_SMEM>>>(fw_init, eta, mlp_aw, mlp_ab, mlp_bw, mlp_bb);
    k_head<<<dim3(TT/128, VV/128), 512, HEAD_SMEM>>>(head_b, out);   // ncu slot 4
    k_finalize<<<TT, 128>>>(out, targets);
    if (out_size >= TT*VV + 1)
        k_loss<<<1, 256>>>(out + (size_t)TT*VV);
}

// round 17
// speedup vs baseline: 6.6591x; 1.0897x over previous
#include <cuda_runtime.h>
#include <cuda_fp16.h>
#include <math.h>
#include <stdint.h>

#define DD 512
#define HH 20
#define VV 32000
#define TT 1024
#define NTILES (VV/64)    // 500 n-tiles (64-wide) in the head grid

// Scratch (allocation-free rule: __device__ globals)
__device__ float g_X [TT*DD];
__device__ float g_Z0[TT*DD];
__device__ float g_Z1[TT*DD];
__device__ float g_Y [TT*DD];
__device__ float g_rowloss[TT];
__device__ float g_pm[TT*NTILES];
__device__ float g_ps[TT*NTILES];
__device__ unsigned g_bar;          // grid barrier (monotonic, mod-128)
// Chunk-major, pre-swizzled fp16 operands for the head GEMM.
// Element (row, k): g = ((kc*ROWS + row)*64 + kk)*2, stored at g ^ ((g>>3)&0x70).
__device__ __half g_Ah [TT*DD];                 // mixed, single fp16
__device__ __half g_Bhi[(size_t)VV*DD];         // head_w^T hi
__device__ __half g_Blo[(size_t)VV*DD];         // head_w^T lo

// ---------------------------------------------------------------------------
// PTX helpers
// ---------------------------------------------------------------------------
__device__ __forceinline__ uint32_t smem_u32(const void* p) {
    uint32_t a;
    asm("{ .reg .u64 t; cvta.to.shared.u64 t, %1; cvt.u32.u64 %0, t; }" : "=r"(a) : "l"(p));
    return a;
}
#define MBAR_INIT(a, c) asm volatile("mbarrier.init.shared.b64 [%0], %1;" :: "r"(a), "r"(c) : "memory")
#define MBAR_EXPECT_TX(a, b) \
    asm volatile("mbarrier.arrive.expect_tx.shared.b64 _, [%0], %1;" :: "r"(a), "r"(b) : "memory")
__device__ __forceinline__ void mbar_wait(uint32_t mbar, uint32_t parity) {
    uint32_t done;
    asm volatile("{ .reg .pred p; mbarrier.try_wait.parity.acquire.cta.shared::cta.b64 p, [%1], %2; selp.b32 %0,1,0,p; }"
                 : "=r"(done) : "r"(mbar), "r"(parity) : "memory");
    if (!done) {
        asm volatile("{ .reg .pred P1;\nWL_%=:\n"
                     "mbarrier.try_wait.parity.acquire.cta.shared::cta.b64 P1, [%0], %1, 0x989680;\n"
                     "@P1 bra.uni WD_%=;\n bra.uni WL_%=;\nWD_%=:\n}"
                     :: "r"(mbar), "r"(parity) : "memory");
    }
}
__device__ __forceinline__ void bulk_cp(uint32_t dst, const void* gsrc,
                                        uint32_t bytes, uint32_t mbar) {
    asm volatile("cp.async.bulk.shared::cluster.global.mbarrier::complete_tx::bytes [%0], [%1], %2, [%3];"
                 :: "r"(dst), "l"(__cvta_generic_to_global(gsrc)), "r"(bytes), "r"(mbar) : "memory");
}
__device__ __forceinline__ void ldsm4(unsigned r[4], uint32_t addr) {
    asm volatile("ldmatrix.sync.aligned.m8n8.x4.shared.b16 {%0,%1,%2,%3}, [%4];"
                 : "=r"(r[0]), "=r"(r[1]), "=r"(r[2]), "=r"(r[3]) : "r"(addr));
}
__device__ __forceinline__ void mma_h(float c[4], const unsigned a[4], const unsigned b[2]) {
    asm volatile(
        "mma.sync.aligned.m16n8k16.row.col.f32.f16.f16.f32 "
        "{%0,%1,%2,%3}, {%4,%5,%6,%7}, {%8,%9}, {%0,%1,%2,%3};\n"
        : "+f"(c[0]), "+f"(c[1]), "+f"(c[2]), "+f"(c[3])
        : "r"(a[0]), "r"(a[1]), "r"(a[2]), "r"(a[3]), "r"(b[0]), "r"(b[1]));
}
__device__ __forceinline__ float tanh_fast(float v) {
    float r;
    asm("tanh.approx.f32 %0, %1;" : "=f"(r) : "f"(v));
    return r;
}

// ---------------------------------------------------------------------------
// 1) X = embed[tokens]
// ---------------------------------------------------------------------------
__global__ void k_gather(const int* __restrict__ tokens,
                         const float* __restrict__ embed) {
    int idx = blockIdx.x * blockDim.x + threadIdx.x;
    if (idx < TT * DD) {
        int t = idx >> 9, d = idx & 511;
        g_X[idx] = embed[(size_t)tokens[t] * DD + d];
    }
}

// ---------------------------------------------------------------------------
// 2) head_w -> chunk-major swizzled fp16 hi/lo (runs on forked stream)
// ---------------------------------------------------------------------------
__global__ void __launch_bounds__(256) k_convB(const float* __restrict__ W) {
    __shared__ float tile[64][65];
    int n0 = blockIdx.x * 64;
    int k0 = blockIdx.y * 64;
    int tid = threadIdx.x;
    #pragma unroll
    for (int i = 0; i < 16; i++) {
        int f = tid + 256 * i;
        int k = f >> 6, n = f & 63;
        tile[k][n] = W[(size_t)(k0 + k) * VV + n0 + n];
    }
    __syncthreads();
    size_t kc = (size_t)(k0 >> 6);
    char* bh = (char*)g_Bhi;
    char* bl = (char*)g_Blo;
    #pragma unroll
    for (int i = 0; i < 16; i++) {
        int f = tid + 256 * i;
        int n = f >> 6, kk = f & 63;
        float v = tile[kk][n];
        __half hi = __float2half(v);
        __half lo = __float2half(v - __half2float(hi));
        size_t g = ((kc * VV + (n0 + n)) * 64 + kk) * 2;
        size_t sw = g ^ ((g >> 3) & 0x70);
        *(__half*)(bh + sw) = hi;
        *(__half*)(bl + sw) = lo;
    }
}

// ---------------------------------------------------------------------------
// 3) Z0 = X @ wa, Z1 = X @ wb  (K-step 32)
// ---------------------------------------------------------------------------
__global__ void __launch_bounds__(256) k_zgemm(const float* __restrict__ wa,
                                               const float* __restrict__ wb) {
    __shared__ float Xs [32][64];
    __shared__ float Was[32][64];
    __shared__ float Wbs[32][64];
    int tid = threadIdx.x;
    int n0 = blockIdx.x * 64;
    int m0 = blockIdx.y * 64;
    int ty = tid >> 4, tx = tid & 15;
    float a0[4][4] = {}, a1[4][4] = {};

    for (int k0 = 0; k0 < DD; k0 += 32) {
        #pragma unroll
        for (int q = 0; q < 2; q++) {
            int f = tid + 256 * q;
            int m  = f >> 3;
            int kq = (f & 7) * 4;
            float4 v = *(const float4*)&g_X[(size_t)(m0 + m) * DD + k0 + kq];
            Xs[kq+0][m] = v.x; Xs[kq+1][m] = v.y; Xs[kq+2][m] = v.z; Xs[kq+3][m] = v.w;
        }
        #pragma unroll
        for (int q = 0; q < 2; q++) {
            int f = tid + 256 * q;
            int k  = f >> 4;
            int nq = (f & 15) * 4;
            *(float4*)&Was[k][nq] = *(const float4*)&wa[(size_t)(k0 + k) * DD + n0 + nq];
            *(float4*)&Wbs[k][nq] = *(const float4*)&wb[(size_t)(k0 + k) * DD + n0 + nq];
        }
        __syncthreads();
        #pragma unroll
        for (int k = 0; k < 32; k++) {
            float xr[4], war[4], wbr[4];
            #pragma unroll
            for (int i = 0; i < 4; i++) xr[i] = Xs[k][ty*4 + i];
            #pragma unroll
            for (int j = 0; j < 4; j++) { war[j] = Was[k][tx*4 + j]; wbr[j] = Wbs[k][tx*4 + j]; }
            #pragma unroll
            for (int i = 0; i < 4; i++)
                #pragma unroll
                for (int j = 0; j < 4; j++) {
                    a0[i][j] = fmaf(xr[i], war[j], a0[i][j]);
                    a1[i][j] = fmaf(xr[i], wbr[j], a1[i][j]);
                }
        }
        __syncthreads();
    }
    #pragma unroll
    for (int i = 0; i < 4; i++) {
        int row = m0 + ty*4 + i;
        #pragma unroll
        for (int j = 0; j < 4; j++) {
            int col = n0 + tx*4 + j;
            g_Z0[(size_t)row * DD + col] = a0[i][j];
            g_Z1[(size_t)row * DD + col] = a1[i][j];
        }
    }
}

// ---------------------------------------------------------------------------
// 4) Fused scan (v6) + grid barrier + MLP. 128 CTAs x 512 threads.
// ---------------------------------------------------------------------------
#define SC_STEPS 16
#define SC_HALF  (SC_STEPS*DD*4)
#define SC_BUF   (2*SC_HALF)
#define SC_STAGE0 9216
#define SC_SMEM  (SC_STAGE0 + 2*SC_BUF)
#define PART_IDX(ph, s, w, c)  (((ph)*SC_STEPS + (s))*68 + (w)*4 + (c))

__global__ void __launch_bounds__(512) k_scanmlp(
        const float* __restrict__ fw_init, const float* __restrict__ eta_p,
        const float* __restrict__ aw, const float* __restrict__ ab,
        const float* __restrict__ bw, const float* __restrict__ bb) {
    extern __shared__ __align__(1024) char smem[];
    uint32_t sb = smem_u32(smem);
    float* part = (float*)(smem + 64);

    int tid  = threadIdx.x;
    int wid  = tid >> 5;
    int lane = tid & 31;
    int bid  = blockIdx.x;

    // ================= Phase A: scan =================
    {
        int r4   = lane >> 2;
        int col  = lane & 3;
        int j0   = bid * 4;
        int j    = j0 + col;
        int row0 = wid * 32 + r4 * 4;
        float eta = *eta_p;

        if (tid == 0) { MBAR_INIT(sb, 1); MBAR_INIT(sb + 8, 1); }
        __syncthreads();

        auto issue = [&](int b) {
            uint32_t mb  = sb + (b & 1) * 8;
            uint32_t dst = sb + SC_STAGE0 + (b & 1) * SC_BUF;
            MBAR_EXPECT_TX(mb, SC_BUF);
            bulk_cp(dst,           g_Z0 + (size_t)b * SC_STEPS * DD, SC_HALF, mb);
            bulk_cp(dst + SC_HALF, g_X  + (size_t)b * SC_STEPS * DD, SC_HALF, mb);
        };
        if (tid == 0) { issue(0); issue(1); }

        float fw[4];
        #pragma unroll
        for (int g = 0; g < 4; g++)
            fw[g] = fw_init[(size_t)(row0 + g) * DD + j];

        float z1cur[SC_STEPS];
        #pragma unroll
        for (int s = 0; s < SC_STEPS; s++)
            z1cur[s] = __ldg(&g_Z1[(size_t)s * DD + j]);

        const int NB = TT / SC_STEPS;
        for (int b = 0; b < NB; b++) {
            int tb = b * SC_STEPS;
            float z1nxt[SC_STEPS];
            if (b + 1 < NB) {
                #pragma unroll
                for (int s = 0; s < SC_STEPS; s++)
                    z1nxt[s] = __ldg(&g_Z1[(size_t)(tb + SC_STEPS + s) * DD + j]);
            }

            mbar_wait(sb + (b & 1) * 8, (b >> 1) & 1);
            uint32_t base = sb + SC_STAGE0 + (b & 1) * SC_BUF;

            float yb[SC_STEPS];
            #pragma unroll
            for (int s = 0; s < SC_STEPS; s++) {
                float4 z0v, xv;
                asm volatile("ld.shared.v4.f32 {%0,%1,%2,%3}, [%4];"
                             : "=f"(z0v.x), "=f"(z0v.y), "=f"(z0v.z), "=f"(z0v.w)
                             : "r"(base + (uint32_t)(s * DD + row0) * 4));
                asm volatile("ld.shared.v4.f32 {%0,%1,%2,%3}, [%4];"
                             : "=f"(xv.x), "=f"(xv.y), "=f"(xv.z), "=f"(xv.w)
                             : "r"(base + SC_HALF + (uint32_t)(s * DD + row0) * 4));
                float p = eta * z1cur[s];
                float t0 = tanh_fast(fmaf(z0v.x, p, fw[0]));
                float t1 = tanh_fast(fmaf(z0v.y, p, fw[1]));
                float t2 = tanh_fast(fmaf(z0v.z, p, fw[2]));
                float t3 = tanh_fast(fmaf(z0v.w, p, fw[3]));
                fw[0] = t0; fw[1] = t1; fw[2] = t2; fw[3] = t3;
                yb[s] = fmaf(xv.x, t0, fmaf(xv.y, t1, fmaf(xv.z, t2, xv.w * t3)));
            }
            #pragma unroll
            for (int off = 16; off >= 4; off >>= 1)
                #pragma unroll
                for (int s = 0; s < SC_STEPS; s++)
                    yb[s] += __shfl_xor_sync(0xffffffffu, yb[s], off);
            int ph = b & 1;
            if (lane < 4) {
                #pragma unroll
                for (int s = 0; s < SC_STEPS; s++)
                    part[PART_IDX(ph, s, wid, lane)] = yb[s];
            }
            __syncthreads();
            if (tid == 0 && b + 2 < NB) issue(b + 2);
            if (tid < 64) {
                int s = tid >> 2, c = tid & 3;
                float y = 0.f;
                #pragma unroll
                for (int w = 0; w < 16; w++)
                    y += part[PART_IDX(ph, s, w, c)];
                g_Y[(size_t)(tb + s) * DD + j0 + c] = y;
            }
            #pragma unroll
            for (int s = 0; s < SC_STEPS; s++)
                z1cur[s] = z1nxt[s];
        }
    }

    // ============ Grid barrier (all 128 CTAs resident) ============
    __threadfence();
    __syncthreads();
    if (tid == 0) {
        atomicAdd(&g_bar, 1u);
        volatile unsigned* vb = &g_bar;
        while (*vb & 127u) { }
    }
    __syncthreads();
    __threadfence();

    // ================= Phase B: MLP + mix for 8 tokens =================
    {
        float* ys = (float*)(smem + 1024);
        float* hs = ys + DD;
        char* ahp = (char*)g_Ah;
        for (int it = 0; it < 8; it++) {
            int t = bid * 8 + it;
            ys[tid] = g_Y[(size_t)t * DD + tid];
            __syncthreads();
            for (int u = wid; u < HH; u += 16) {
                float acc = 0.f;
                #pragma unroll
                for (int k = 0; k < 16; k++) {
                    int d = lane + 32*k;
                    acc = fmaf(ys[d], aw[(size_t)d * HH + u], acc);
                }
                #pragma unroll
                for (int off = 16; off; off >>= 1)
                    acc += __shfl_xor_sync(0xffffffffu, acc, off);
                if (lane == 0) {
                    float hv = acc + ab[u];
                    const float SC = 1.0507009873554805f, AL = 1.6732632423543772f;
                    hs[u] = hv > 0.f ? SC * hv : SC * AL * expm1f(hv);
                }
            }
            __syncthreads();
            {
                int j = tid;
                float o = bb[j];
                #pragma unroll
                for (int k = 0; k < HH; k++)
                    o = fmaf(hs[k], bw[(size_t)k * DD + j], o);
                float mx = 0.5f * o + 0.5f * g_X[(size_t)t * DD + j];
                size_t g = (((size_t)(j >> 6) * TT + t) * 64 + (j & 63)) * 2;
                size_t sw = g ^ ((g >> 3) & 0x70);
                *(__half*)(ahp + sw) = __float2half(mx);
            }
            __syncthreads();
        }
    }
}

// ---------------------------------------------------------------------------
// 5) Head GEMM (fp16 2-MMA) + fused softmax tile stats.
//    Tile 128m x 64n, 256 threads (8 warps: 4m x 2n, warp 32x32),
//    3-stage pipeline, 2 CTAs/SM for stall overlap.
// ---------------------------------------------------------------------------
#define TILE_A   16384               // 128 rows x 128 B
#define TILE_Bb  8192                // 64 rows x 128 B
#define CH_B     (TILE_A + 2*TILE_Bb)   // 32KB per chunk
#define HEAD_SMEM (1024 + 3*CH_B)    // 99328; x2 CTAs = 198656 <= 228KB

__global__ void __launch_bounds__(256, 2) k_head(const float* __restrict__ bias,
                                                 float* __restrict__ out) {
    extern __shared__ __align__(1024) char smem[];
    uint32_t sb = smem_u32(smem);
    int tid  = threadIdx.x;
    int wid  = tid >> 5;
    int lane = tid & 31;
    int grp  = lane >> 2;
    int t4   = lane & 3;
    int m0 = blockIdx.x * 128;
    int n0 = blockIdx.y * 64;
    int wm = wid & 3;            // 4 M-subtiles of 32
    int wn = wid >> 2;           // 2 N-subtiles of 32

    if (tid == 0) { MBAR_INIT(sb, 1); MBAR_INIT(sb + 8, 1); MBAR_INIT(sb + 16, 1); }
    __syncthreads();

    const char* gA  = (const char*)g_Ah;
    const char* gBh = (const char*)g_Bhi;
    const char* gBl = (const char*)g_Blo;

    auto issue = [&](int c) {
        int buf = c % 3;
        uint32_t mb  = sb + buf * 8;
        uint32_t dst = sb + 1024 + buf * CH_B;
        MBAR_EXPECT_TX(mb, CH_B);
        size_t aoff = ((size_t)c * TT + m0) * 128;
        size_t boff = ((size_t)c * VV + n0) * 128;
        bulk_cp(dst,            gA  + aoff, TILE_A, mb);
        bulk_cp(dst + TILE_A,             gBh + boff, TILE_Bb, mb);
        bulk_cp(dst + TILE_A + TILE_Bb,   gBl + boff, TILE_Bb, mb);
    };
    if (tid == 0) { issue(0); issue(1); issue(2); }

    float acc[2][4][4] = {};

    uint32_t aRow  = (uint32_t)(wm*32 + (lane & 15));
    uint32_t aByte = aRow * 128;
    uint32_t aXor  = (aRow & 7) << 4;
    uint32_t aKb   = (uint32_t)((lane >> 4) * 16);
    uint32_t bRow  = (uint32_t)(wn*32 + (lane & 7) + ((lane >> 4) & 1) * 8);
    uint32_t bByte = bRow * 128;
    uint32_t bXor  = (bRow & 7) << 4;
    uint32_t bKb   = (uint32_t)(((lane >> 3) & 1) * 16);

    for (int c = 0; c < 8; c++) {
        mbar_wait(sb + (c % 3) * 8, (c / 3) & 1);
        uint32_t base = sb + 1024 + (c % 3) * CH_B;
        uint32_t pA  = base;
        uint32_t pBh = base + TILE_A;
        uint32_t pBl = base + TILE_A + TILE_Bb;

        #pragma unroll
        for (int ks = 0; ks < 4; ks++) {
            uint32_t ka = ((uint32_t)(ks*32) + aKb) ^ aXor;
            uint32_t kb = ((uint32_t)(ks*32) + bKb) ^ bXor;
            unsigned ah[2][4], bh[4][2], bl[4][2];
            #pragma unroll
            for (int mi = 0; mi < 2; mi++)
                ldsm4(ah[mi], pA + aByte + mi*2048 + ka);
            #pragma unroll
            for (int p = 0; p < 2; p++) {
                unsigned tmp[4];
                ldsm4(tmp, pBh + bByte + p*2048 + kb);
                bh[p*2][0] = tmp[0]; bh[p*2][1] = tmp[1];
                bh[p*2+1][0] = tmp[2]; bh[p*2+1][1] = tmp[3];
                ldsm4(tmp, pBl + bByte + p*2048 + kb);
                bl[p*2][0] = tmp[0]; bl[p*2][1] = tmp[1];
                bl[p*2+1][0] = tmp[2]; bl[p*2+1][1] = tmp[3];
            }
            #pragma unroll
            for (int mi = 0; mi < 2; mi++)
                #pragma unroll
                for (int ni = 0; ni < 4; ni++) {
                    mma_h(acc[mi][ni], ah[mi], bh[ni]);
                    mma_h(acc[mi][ni], ah[mi], bl[ni]);
                }
        }
        __syncthreads();
        if (tid == 0 && c + 3 < 8) issue(c + 3);
    }

    // ---- epilogue: bias, store logits ----
    #pragma unroll
    for (int mi = 0; mi < 2; mi++) {
        #pragma unroll
        for (int ni = 0; ni < 4; ni++) {
            int col = n0 + wn * 32 + ni * 8 + t4 * 2;
            float2 bv = *(const float2*)&bias[col];
            acc[mi][ni][0] += bv.x; acc[mi][ni][1] += bv.y;
            acc[mi][ni][2] += bv.x; acc[mi][ni][3] += bv.y;
        }
    }
    #pragma unroll
    for (int mi = 0; mi < 2; mi++) {
        int r0 = m0 + wm * 32 + mi * 16 + grp;
        #pragma unroll
        for (int ni = 0; ni < 4; ni++) {
            int col = n0 + wn * 32 + ni * 8 + t4 * 2;
            *(float2*)&out[(size_t)r0       * VV + col] = *(float2*)&acc[mi][ni][0];
            *(float2*)&out[(size_t)(r0 + 8) * VV + col] = *(float2*)&acc[mi][ni][2];
        }
    }

    // ---- fused softmax tile stats (64-col tile; 2 wn slots/row) ----
    float* red = (float*)(smem + 1024);   // [128][2]
    float* gm  = red + 256;               // [128]
    float* rs  = gm + 128;                // [128][2]
    __syncthreads();

    float rmax[2][2];
    #pragma unroll
    for (int mi = 0; mi < 2; mi++) {
        float m0v = -INFINITY, m1v = -INFINITY;
        #pragma unroll
        for (int ni = 0; ni < 4; ni++) {
            m0v = fmaxf(m0v, fmaxf(acc[mi][ni][0], acc[mi][ni][1]));
            m1v = fmaxf(m1v, fmaxf(acc[mi][ni][2], acc[mi][ni][3]));
        }
        rmax[mi][0] = m0v; rmax[mi][1] = m1v;
    }
    #pragma unroll
    for (int off = 1; off <= 2; off <<= 1)
        #pragma unroll
        for (int mi = 0; mi < 2; mi++)
            #pragma unroll
            for (int h = 0; h < 2; h++)
                rmax[mi][h] = fmaxf(rmax[mi][h], __shfl_xor_sync(0xffffffffu, rmax[mi][h], off));
    if (t4 == 0) {
        #pragma unroll
        for (int mi = 0; mi < 2; mi++)
            #pragma unroll
            for (int h = 0; h < 2; h++)
                red[(wm*32 + mi*16 + h*8 + grp) * 2 + wn] = rmax[mi][h];
    }
    __syncthreads();
    if (tid < 128)
        gm[tid] = fmaxf(red[tid*2], red[tid*2+1]);
    __syncthreads();

    float rsum[2][2];
    #pragma unroll
    for (int mi = 0; mi < 2; mi++) {
        float g0 = gm[wm*32 + mi*16 + grp];
        float g1 = gm[wm*32 + mi*16 + 8 + grp];
        float s0 = 0.f, s1 = 0.f;
        #pragma unroll
        for (int ni = 0; ni < 4; ni++) {
            s0 += __expf(acc[mi][ni][0] - g0) + __expf(acc[mi][ni][1] - g0);
            s1 += __expf(acc[mi][ni][2] - g1) + __expf(acc[mi][ni][3] - g1);
        }
        rsum[mi][0] = s0; rsum[mi][1] = s1;
    }
    #pragma unroll
    for (int off = 1; off <= 2; off <<= 1)
        #pragma unroll
        for (int mi = 0; mi < 2; mi++)
            #pragma unroll
            for (int h = 0; h < 2; h++)
                rsum[mi][h] += __shfl_xor_sync(0xffffffffu, rsum[mi][h], off);
    if (t4 == 0) {
        #pragma unroll
        for (int mi = 0; mi < 2; mi++)
            #pragma unroll
            for (int h = 0; h < 2; h++)
                rs[(wm*32 + mi*16 + h*8 + grp) * 2 + wn] = rsum[mi][h];
    }
    __syncthreads();
    if (tid < 128) {
        float s = rs[tid*2] + rs[tid*2+1];
        size_t o = (size_t)(m0 + tid) * NTILES + blockIdx.y;
        g_pm[o] = gm[tid];
        g_ps[o] = s;
    }
}

// ---------------------------------------------------------------------------
// 6) finalize: merge 500 tile stats per row -> rowloss; 7) mean
// ---------------------------------------------------------------------------
__global__ void __launch_bounds__(128) k_finalize(const float* __restrict__ logits,
                                                  const int* __restrict__ targets) {
    __shared__ float sm[128], ss[128];
    int t = blockIdx.x, tid = threadIdx.x;
    float m = -INFINITY, s = 0.f;
    for (int i = tid; i < NTILES; i += 128) {
        float pm = g_pm[(size_t)t * NTILES + i];
        float ps = g_ps[(size_t)t * NTILES + i];
        if (pm > m) { s = s * __expf(m - pm) + ps; m = pm; }
        else        { s += ps * __expf(pm - m); }
    }
    sm[tid] = m; ss[tid] = s; __syncthreads();
    for (int st = 64; st; st >>= 1) {
        if (tid < st) {
            float m2 = fmaxf(sm[tid], sm[tid + st]);
            ss[tid] = ss[tid] * __expf(sm[tid] - m2) + ss[tid + st] * __expf(sm[tid + st] - m2);
            sm[tid] = m2;
        }
        __syncthreads();
    }
    if (tid == 0)
        g_rowloss[t] = logits[(size_t)t * VV + targets[t]] - sm[0] - logf(ss[0]);
}

__global__ void k_loss(float* __restrict__ out) {
    __shared__ float red[256];
    int tid = threadIdx.x;
    float s = 0.f;
    for (int t = tid; t < TT; t += 256) s += g_rowloss[t];
    red[tid] = s; __syncthreads();
    for (int st = 128; st; st >>= 1) { if (tid < st) red[tid] += red[tid+st]; __syncthreads(); }
    if (tid == 0) out[0] = -red[0] / (float)TT;
}

// ---------------------------------------------------------------------------
extern "C" void kernel_launch(void* const* d_in, const int* in_sizes, int n_in,
                              void* d_out, int out_size) {
    const int*   tokens  = (const int*)  d_in[0];
    const int*   targets = (const int*)  d_in[1];
    const float* embed   = (const float*)d_in[2];
    const float* fw_init = (const float*)d_in[3];
    const float* eta     = (const float*)d_in[4];
    const float* wa      = (const float*)d_in[5];
    const float* wb      = (const float*)d_in[6];
    const float* mlp_aw  = (const float*)d_in[7];
    const float* mlp_ab  = (const float*)d_in[8];
    const float* mlp_bw  = (const float*)d_in[9];
    const float* mlp_bb  = (const float*)d_in[10];
    const float* head_w  = (const float*)d_in[11];
    const float* head_b  = (const float*)d_in[12];
    float* out = (float*)d_out;

    static cudaStream_t s2;
    static cudaEvent_t evFork, evJoin;
    static int inited = 0;
    if (!inited) {
        cudaFuncSetAttribute(k_head, cudaFuncAttributeMaxDynamicSharedMemorySize, HEAD_SMEM);
        cudaFuncSetAttribute(k_scanmlp, cudaFuncAttributeMaxDynamicSharedMemorySize, SC_SMEM);
        cudaStreamCreateWithFlags(&s2, cudaStreamNonBlocking);
        cudaEventCreateWithFlags(&evFork, cudaEventDisableTiming);
        cudaEventCreateWithFlags(&evJoin, cudaEventDisableTiming);
        inited = 1;
    }

    // fork: convB runs on s2 concurrently with gather->zgemm->scanmlp
    cudaEventRecord(evFork, 0);
    cudaStreamWaitEvent(s2, evFork, 0);
    k_convB<<<dim3(VV/64, DD/64), 256, 0, s2>>>(head_w);
    cudaEventRecord(evJoin, s2);

    k_gather<<<(TT*DD + 255) / 256, 256>>>(tokens, embed);
    k_zgemm<<<dim3(DD/64, TT/64), 256>>>(wa, wb);
    k_scanmlp<<<DD/4, 512, SC_SMEM>>>(fw_init, eta, mlp_aw, mlp_ab, mlp_bw, mlp_bb);

    cudaStreamWaitEvent(0, evJoin, 0);    // join before head consumes g_Bhi/g_Blo
    k_head<<<dim3(TT/128, VV/64), 256, HEAD_SMEM>>>(head_b, out);
    k_finalize<<<TT, 128>>>(out, targets);
    if (out_size >= TT*VV + 1)
        k_loss<<<1, 256>>>(out + (size_t)TT*VV);
}